// round 9
// baseline (speedup 1.0000x reference)
#include <cuda_runtime.h>
#include <cuda_fp16.h>
#include <cstdint>

#define BB 8
#define NN 2048
#define DD 512
#define CC 4096
#define MM (BB*NN)   // 16384

// screen-kernel tiling (int8)
#define Bb_M 128
#define Bb_N 128
#define Bb_K 128                  // k-depth per B chunk (bytes = 128)
#define NCT (CC/Bb_N)             // 32 c-tiles
#define NKC (DD/Bb_K)             // 4 k-chunks per c-tile
#define NQ  (NCT*NKC)             // 128 chunks
#define KB_BYTES 16384            // 128 rows x 128 int8 per block
#define A_BYTES  (4*KB_BYTES)     // resident A: 128 x 512 int8 = 64KB
#define BSTAGES 4
#define SMEM_DYN (A_BYTES + BSTAGES*KB_BYTES)   // 128KB
#define NTHR 512

// ---------------- scratch ----------------
__device__ float g_implicit[CC * DD];
__device__ float g_halfnorm[CC];
__device__ int   g_idx[MM];
__device__ int   g_cand[MM * 8];
__device__ float g_commit[MM];
__device__ int8_t g_xq[MM * DD];
__device__ int8_t g_cq[CC * DD];
__device__ float g_sA[MM];
__device__ float g_sB[CC];

// =============================== helpers ===================================
__device__ __forceinline__ uint32_t smem_u32(const void* p) {
    return (uint32_t)__cvta_generic_to_shared(p);
}
__device__ __forceinline__ void cp16(uint32_t s, const void* g) {
    asm volatile("cp.async.cg.shared.global [%0], [%1], 16;" :: "r"(s), "l"(g));
}
#define CP_COMMIT() asm volatile("cp.async.commit_group;")
#define CP_WAIT2()  asm volatile("cp.async.wait_group 2;")
#define LDM4(r0,r1,r2,r3,addr) \
    asm volatile("ldmatrix.sync.aligned.m8n8.x4.shared.b16 {%0,%1,%2,%3},[%4];" \
                 : "=r"(r0),"=r"(r1),"=r"(r2),"=r"(r3) : "r"(addr))
#define IMMA16832(c,a,b) \
    asm volatile("mma.sync.aligned.m16n8k32.row.col.s32.s8.s8.s32 " \
                 "{%0,%1,%2,%3},{%4,%5,%6,%7},{%8,%9},{%0,%1,%2,%3};" \
                 : "+r"((c)[0]),"+r"((c)[1]),"+r"((c)[2]),"+r"((c)[3]) \
                 : "r"((a)[0]),"r"((a)[1]),"r"((a)[2]),"r"((a)[3]), \
                   "r"((b)[0]),"r"((b)[1]))

// sorted-8 insert (ascending, b0 = min); scalars only
__device__ __forceinline__ void ins8(float v, int ii,
    float& b0, float& b1, float& b2, float& b3,
    float& b4, float& b5, float& b6, float& b7,
    int& i0, int& i1, int& i2, int& i3,
    int& i4, int& i5, int& i6, int& i7) {
    if (v >= b7) return;
    b7 = v; i7 = ii;
    if (b7 < b6) { float t = b6; b6 = b7; b7 = t; int u = i6; i6 = i7; i7 = u; }
    if (b6 < b5) { float t = b5; b5 = b6; b6 = t; int u = i5; i5 = i6; i6 = u; }
    if (b5 < b4) { float t = b4; b4 = b5; b5 = t; int u = i4; i4 = i5; i5 = u; }
    if (b4 < b3) { float t = b3; b3 = b4; b4 = t; int u = i3; i3 = i4; i4 = u; }
    if (b3 < b2) { float t = b2; b2 = b3; b3 = t; int u = i2; i2 = i3; i3 = u; }
    if (b2 < b1) { float t = b1; b1 = b2; b2 = t; int u = i1; i1 = i2; i2 = u; }
    if (b1 < b0) { float t = b0; b0 = b1; b1 = t; int u = i0; i0 = i1; i1 = u; }
}

// ===========================================================================
// Kernel 1: implicit = codebook @ W^T  (fp32 SIMT, 2.1 GFLOP)
// ===========================================================================
__global__ __launch_bounds__(256) void k_implicit(const float* __restrict__ A,
                                                  const float* __restrict__ Wm) {
    __shared__ float As[8][128];
    __shared__ float Bs[8][128];
    const int tid = threadIdx.x;
    const int tx = tid & 15, ty = tid >> 4;
    const int m0 = blockIdx.x * 128;
    const int n0 = blockIdx.y * 128;
    const int lr = tid >> 1;
    const int lk = (tid & 1) * 4;

    float acc[2][2][4][4];
#pragma unroll
    for (int a = 0; a < 2; a++)
#pragma unroll
        for (int b = 0; b < 2; b++)
#pragma unroll
            for (int i = 0; i < 4; i++)
#pragma unroll
                for (int j = 0; j < 4; j++) acc[a][b][i][j] = 0.f;

    for (int k0 = 0; k0 < DD; k0 += 8) {
        float4 av = *(const float4*)&A[(size_t)(m0 + lr) * DD + k0 + lk];
        float4 bv = *(const float4*)&Wm[(size_t)(n0 + lr) * DD + k0 + lk];
        __syncthreads();
        As[lk + 0][lr] = av.x; As[lk + 1][lr] = av.y; As[lk + 2][lr] = av.z; As[lk + 3][lr] = av.w;
        Bs[lk + 0][lr] = bv.x; Bs[lk + 1][lr] = bv.y; Bs[lk + 2][lr] = bv.z; Bs[lk + 3][lr] = bv.w;
        __syncthreads();
#pragma unroll
        for (int kk = 0; kk < 8; kk++) {
            float4 a0 = *(const float4*)&As[kk][ty * 4];
            float4 a1 = *(const float4*)&As[kk][64 + ty * 4];
            float4 b0 = *(const float4*)&Bs[kk][tx * 4];
            float4 b1 = *(const float4*)&Bs[kk][64 + tx * 4];
            float ar[8] = {a0.x, a0.y, a0.z, a0.w, a1.x, a1.y, a1.z, a1.w};
            float br[8] = {b0.x, b0.y, b0.z, b0.w, b1.x, b1.y, b1.z, b1.w};
#pragma unroll
            for (int ih = 0; ih < 2; ih++)
#pragma unroll
                for (int i = 0; i < 4; i++)
#pragma unroll
                    for (int jh = 0; jh < 2; jh++)
#pragma unroll
                        for (int j = 0; j < 4; j++)
                            acc[ih][jh][i][j] += ar[ih * 4 + i] * br[jh * 4 + j];
        }
    }
#pragma unroll
    for (int ih = 0; ih < 2; ih++)
#pragma unroll
        for (int i = 0; i < 4; i++) {
            int rm = m0 + ih * 64 + ty * 4 + i;
#pragma unroll
            for (int jh = 0; jh < 2; jh++) {
                int cn = n0 + jh * 64 + tx * 4;
                float4 v = make_float4(acc[ih][jh][i][0], acc[ih][jh][i][1],
                                       acc[ih][jh][i][2], acc[ih][jh][i][3]);
                *(float4*)&g_implicit[(size_t)rm * DD + cn] = v;
            }
        }
}

// ===========================================================================
// Kernel 2: per-row symmetric int8 quantization (one warp per row of 512)
// ===========================================================================
__global__ __launch_bounds__(256) void k_quant(const float* __restrict__ src,
                                               int8_t* __restrict__ dst,
                                               float* __restrict__ scales) {
    const int warp = threadIdx.x >> 5, lane = threadIdx.x & 31;
    const int row = blockIdx.x * 8 + warp;
    const float4* sr = (const float4*)(src + (size_t)row * DD);

    float4 v[4];
    float am = 0.f;
#pragma unroll
    for (int t = 0; t < 4; t++) {
        v[t] = sr[lane + 32 * t];
        am = fmaxf(am, fmaxf(fmaxf(fabsf(v[t].x), fabsf(v[t].y)),
                             fmaxf(fabsf(v[t].z), fabsf(v[t].w))));
    }
#pragma unroll
    for (int o = 16; o > 0; o >>= 1) am = fmaxf(am, __shfl_xor_sync(0xffffffff, am, o));
    am = fmaxf(am, 1e-20f);
    const float inv = 127.f / am;
    if (lane == 0) scales[row] = am / 127.f;

    int* dp = (int*)(dst + (size_t)row * DD);
#pragma unroll
    for (int t = 0; t < 4; t++) {
        int q0 = max(-127, min(127, __float2int_rn(v[t].x * inv)));
        int q1 = max(-127, min(127, __float2int_rn(v[t].y * inv)));
        int q2 = max(-127, min(127, __float2int_rn(v[t].z * inv)));
        int q3 = max(-127, min(127, __float2int_rn(v[t].w * inv)));
        dp[lane + 32 * t] = (q0 & 0xff) | ((q1 & 0xff) << 8)
                          | ((q2 & 0xff) << 16) | ((q3 & 0xff) << 24);
    }
}

// ===========================================================================
// Kernel 3: halfnorm[c] = 0.5 * ||implicit[c]||^2
// ===========================================================================
__global__ __launch_bounds__(256) void k_halfnorm() {
    int warp = threadIdx.x >> 5, lane = threadIdx.x & 31;
    int row = blockIdx.x * 8 + warp;
    const float* p = g_implicit + (size_t)row * DD;
    float s = 0.f;
#pragma unroll
    for (int k = 0; k < DD / 32; k++) {
        float v = p[lane + 32 * k];
        s += v * v;
    }
#pragma unroll
    for (int o = 16; o > 0; o >>= 1) s += __shfl_xor_sync(0xffffffff, s, o);
    if (lane == 0) g_halfnorm[row] = 0.5f * s;
}

// ===========================================================================
// Kernel 4: INT8 IMMA screening GEMM + per-row top-8.  512 threads.
// A tile resident (64KB, swizzled); B streamed in k=128 chunks, 4 stages.
// swizzle: phys = row*128 + ((seg ^ (row&7))<<4), seg = 16B column segment.
// ===========================================================================
__device__ __forceinline__ void issue_b(uint32_t st, int ct, int kc, int tid) {
#pragma unroll
    for (int j = 0; j < 2; j++) {
        int idx = j * NTHR + tid;          // 0..1023
        int row = idx >> 3, seg = idx & 7;
        const int8_t* g = g_cq + (size_t)(ct * Bb_N + row) * DD + kc * Bb_K + seg * 16;
        cp16(st + row * 128 + (((seg ^ (row & 7))) << 4), g);
    }
}

__global__ __launch_bounds__(NTHR, 1) void k_screen_mma() {
    extern __shared__ char dsm[];
    __shared__ float sv[4][128][8];
    __shared__ int   si[4][128][8];

    const uint32_t sa = smem_u32(dsm);            // A resident, 64KB
    const uint32_t sbB = sa + A_BYTES;            // B stages
    const int tid = threadIdx.x;
    const int lane = tid & 31;
    const int wid = tid >> 5;
    const int warp_m = wid >> 2;      // 0..3  (32 rows each)
    const int warp_n = wid & 3;       // 0..3  (32 cols each)
    const int m0 = blockIdx.x * Bb_M;
    const int gID = lane >> 2;        // 0..7
    const int tg  = lane & 3;         // 0..3

    const uint32_t aRow = (uint32_t)(warp_m * 32 + (lane & 15)) * 128;
    const uint32_t bRow = (uint32_t)(warp_n * 32 + ((lane >> 4) & 1) * 8 + (lane & 7)) * 128;
    const int lxor = lane & 7;

    // running per-row top-8 (owned by tid<128, row = m0+tid)
    float rb0 = 3.4e38f, rb1 = 3.4e38f, rb2 = 3.4e38f, rb3 = 3.4e38f;
    float rb4 = 3.4e38f, rb5 = 3.4e38f, rb6 = 3.4e38f, rb7 = 3.4e38f;
    int   ri0 = 0, ri1 = 0, ri2 = 0, ri3 = 0, ri4 = 0, ri5 = 0, ri6 = 0, ri7 = 0;

    int acc[2][4][4];

    // ---- prologue: resident A (4096 segs) + B stages 0..2 ----
#pragma unroll
    for (int t = 0; t < 8; t++) {
        int idx = t * NTHR + tid;          // 0..4095
        int row = idx >> 5, s = idx & 31;
        int kb = s >> 3, seg = s & 7;
        const int8_t* g = g_xq + (size_t)(m0 + row) * DD + kb * 128 + seg * 16;
        cp16(sa + kb * KB_BYTES + row * 128 + ((seg ^ (row & 7)) << 4), g);
    }
    issue_b(sbB + 0 * KB_BYTES, 0, 0, tid); CP_COMMIT();
    issue_b(sbB + 1 * KB_BYTES, 0, 1, tid); CP_COMMIT();
    issue_b(sbB + 2 * KB_BYTES, 0, 2, tid); CP_COMMIT();

    for (int q = 0; q < NQ; q++) {
        const int ct = q >> 2;
        const int kc = q & 3;

        CP_WAIT2();          // chunk q (and A, at q=0) resident
        __syncthreads();

        const int qn = q + 3;
        if (qn < NQ)
            issue_b(sbB + (qn & 3) * KB_BYTES, qn >> 2, qn & 3, tid);
        CP_COMMIT();

        if (kc == 0) {
#pragma unroll
            for (int mt = 0; mt < 2; mt++)
#pragma unroll
                for (int nt = 0; nt < 4; nt++)
#pragma unroll
                    for (int e = 0; e < 4; e++) acc[mt][nt][e] = 0;
        }

        const uint32_t aBase = sa + kc * KB_BYTES;
        const uint32_t bBase = sbB + (q & 3) * KB_BYTES;
#pragma unroll
        for (int ks = 0; ks < 4; ks++) {       // 4 x k32 steps within k=128
            const uint32_t aSw = (uint32_t)(((ks * 2 + (lane >> 4)) ^ lxor) << 4);
            const uint32_t bSw = (uint32_t)(((ks * 2 + ((lane >> 3) & 1)) ^ lxor) << 4);
            uint32_t aF[2][4], bF[4][2];
#pragma unroll
            for (int mt = 0; mt < 2; mt++)
                LDM4(aF[mt][0], aF[mt][1], aF[mt][2], aF[mt][3],
                     aBase + aRow + mt * (16 * 128) + aSw);
#pragma unroll
            for (int p = 0; p < 2; p++) {
                uint32_t r0, r1, r2, r3;
                LDM4(r0, r1, r2, r3, bBase + bRow + p * (16 * 128) + bSw);
                bF[2 * p][0] = r0; bF[2 * p][1] = r1;
                bF[2 * p + 1][0] = r2; bF[2 * p + 1][1] = r3;
            }
#pragma unroll
            for (int mt = 0; mt < 2; mt++)
#pragma unroll
                for (int nt = 0; nt < 4; nt++) IMMA16832(acc[mt][nt], aF[mt], bF[nt]);
        }

        if (kc == 3) {
            // -------- top-8 epilogue for this c-tile --------
#pragma unroll
            for (int mt = 0; mt < 2; mt++) {
#pragma unroll
                for (int half = 0; half < 2; half++) {
                    const int r = warp_m * 32 + mt * 16 + gID + 8 * half;
                    const float sar = __ldg(&g_sA[m0 + r]);
                    float b0 = 3.4e38f, b1 = 3.4e38f, b2 = 3.4e38f, b3 = 3.4e38f;
                    float b4 = 3.4e38f, b5 = 3.4e38f, b6 = 3.4e38f, b7 = 3.4e38f;
                    int   i0 = 0, i1 = 0, i2 = 0, i3 = 0, i4 = 0, i5 = 0, i6 = 0, i7 = 0;
#pragma unroll
                    for (int nt = 0; nt < 4; nt++) {
#pragma unroll
                        for (int j = 0; j < 2; j++) {
                            int c = ct * Bb_N + warp_n * 32 + nt * 8 + tg * 2 + j;
                            float dot = sar * __ldg(&g_sB[c])
                                      * (float)acc[mt][nt][2 * half + j];
                            float s = __ldg(&g_halfnorm[c]) - dot;
                            ins8(s, c, b0, b1, b2, b3, b4, b5, b6, b7,
                                 i0, i1, i2, i3, i4, i5, i6, i7);
                        }
                    }
#pragma unroll
                    for (int off = 1; off <= 2; off <<= 1) {
                        float ob[8]; int oi[8];
                        ob[0] = __shfl_xor_sync(0xffffffff, b0, off);
                        ob[1] = __shfl_xor_sync(0xffffffff, b1, off);
                        ob[2] = __shfl_xor_sync(0xffffffff, b2, off);
                        ob[3] = __shfl_xor_sync(0xffffffff, b3, off);
                        ob[4] = __shfl_xor_sync(0xffffffff, b4, off);
                        ob[5] = __shfl_xor_sync(0xffffffff, b5, off);
                        ob[6] = __shfl_xor_sync(0xffffffff, b6, off);
                        ob[7] = __shfl_xor_sync(0xffffffff, b7, off);
                        oi[0] = __shfl_xor_sync(0xffffffff, i0, off);
                        oi[1] = __shfl_xor_sync(0xffffffff, i1, off);
                        oi[2] = __shfl_xor_sync(0xffffffff, i2, off);
                        oi[3] = __shfl_xor_sync(0xffffffff, i3, off);
                        oi[4] = __shfl_xor_sync(0xffffffff, i4, off);
                        oi[5] = __shfl_xor_sync(0xffffffff, i5, off);
                        oi[6] = __shfl_xor_sync(0xffffffff, i6, off);
                        oi[7] = __shfl_xor_sync(0xffffffff, i7, off);
#pragma unroll
                        for (int e = 0; e < 8; e++)
                            ins8(ob[e], oi[e], b0, b1, b2, b3, b4, b5, b6, b7,
                                 i0, i1, i2, i3, i4, i5, i6, i7);
                    }
                    if (tg == 0) {
                        sv[warp_n][r][0] = b0; sv[warp_n][r][1] = b1;
                        sv[warp_n][r][2] = b2; sv[warp_n][r][3] = b3;
                        sv[warp_n][r][4] = b4; sv[warp_n][r][5] = b5;
                        sv[warp_n][r][6] = b6; sv[warp_n][r][7] = b7;
                        si[warp_n][r][0] = i0; si[warp_n][r][1] = i1;
                        si[warp_n][r][2] = i2; si[warp_n][r][3] = i3;
                        si[warp_n][r][4] = i4; si[warp_n][r][5] = i5;
                        si[warp_n][r][6] = i6; si[warp_n][r][7] = i7;
                    }
                }
            }
            __syncthreads();
            if (tid < 128) {
#pragma unroll
                for (int wn = 0; wn < 4; wn++)
#pragma unroll
                    for (int s = 0; s < 8; s++)
                        ins8(sv[wn][tid][s], si[wn][tid][s],
                             rb0, rb1, rb2, rb3, rb4, rb5, rb6, rb7,
                             ri0, ri1, ri2, ri3, ri4, ri5, ri6, ri7);
            }
            __syncthreads();
        }
    }

    if (tid < 128) {
        int gm = m0 + tid;
        g_cand[gm * 8 + 0] = ri0; g_cand[gm * 8 + 1] = ri1;
        g_cand[gm * 8 + 2] = ri2; g_cand[gm * 8 + 3] = ri3;
        g_cand[gm * 8 + 4] = ri4; g_cand[gm * 8 + 5] = ri5;
        g_cand[gm * 8 + 6] = ri6; g_cand[gm * 8 + 7] = ri7;
    }
}

// ===========================================================================
// Kernel 5: exact fp32 rescore of the 8 candidates. One warp per row.
// ===========================================================================
__global__ __launch_bounds__(256) void k_rescore(const float* __restrict__ X,
                                                 float* __restrict__ out_idx_f) {
    const int warp = threadIdx.x >> 5, lane = threadIdx.x & 31;
    const int m = blockIdx.x * 8 + warp;
    const float* xr = X + (size_t)m * DD;

    float4 xv[4];
#pragma unroll
    for (int t = 0; t < 4; t++) xv[t] = ((const float4*)xr)[lane + 32 * t];

    float bestv = 3.4e38f;
    int   besti = 0x7fffffff;
#pragma unroll
    for (int k = 0; k < 8; k++) {
        int ci = g_cand[m * 8 + k];
        const float4* cr = (const float4*)(g_implicit + (size_t)ci * DD);
        float dot = 0.f;
#pragma unroll
        for (int t = 0; t < 4; t++) {
            float4 cv = cr[lane + 32 * t];
            dot += xv[t].x * cv.x + xv[t].y * cv.y + xv[t].z * cv.z + xv[t].w * cv.w;
        }
#pragma unroll
        for (int o = 16; o > 0; o >>= 1) dot += __shfl_xor_sync(0xffffffff, dot, o);
        float s = g_halfnorm[ci] - dot;
        if (s < bestv || (s == bestv && ci < besti)) { bestv = s; besti = ci; }
    }
    if (lane == 0) {
        g_idx[m] = besti;
        out_idx_f[m] = (float)besti;
    }
}

// ===========================================================================
// Kernel 6: rotation trick + per-row commit sum. One block per x-row.
// ===========================================================================
__global__ __launch_bounds__(128) void k_rot(const float* __restrict__ X,
                                             float* __restrict__ outq) {
    __shared__ float red[4][4];
    const int m = blockIdx.x;
    const int t = threadIdx.x;
    const float* xr = X + (size_t)m * DD;
    const float* qr = g_implicit + (size_t)g_idx[m] * DD;

    float4 xv = ((const float4*)xr)[t];
    float4 qv = ((const float4*)qr)[t];

    float sx  = xv.x * xv.x + xv.y * xv.y + xv.z * xv.z + xv.w * xv.w;
    float sq  = qv.x * qv.x + qv.y * qv.y + qv.z * qv.z + qv.w * qv.w;
    float sxq = xv.x * qv.x + xv.y * qv.y + xv.z * qv.z + xv.w * qv.w;
    float d0 = xv.x - qv.x + 1e-6f, d1 = xv.y - qv.y + 1e-6f;
    float d2 = xv.z - qv.z + 1e-6f, d3 = xv.w - qv.w + 1e-6f;
    float sc = d0 * d0 + d1 * d1 + d2 * d2 + d3 * d3;

#pragma unroll
    for (int o = 16; o > 0; o >>= 1) {
        sx  += __shfl_xor_sync(0xffffffff, sx, o);
        sq  += __shfl_xor_sync(0xffffffff, sq, o);
        sxq += __shfl_xor_sync(0xffffffff, sxq, o);
        sc  += __shfl_xor_sync(0xffffffff, sc, o);
    }
    int warp = t >> 5, lane = t & 31;
    if (lane == 0) { red[warp][0] = sx; red[warp][1] = sq; red[warp][2] = sxq; red[warp][3] = sc; }
    __syncthreads();
    sx  = red[0][0] + red[1][0] + red[2][0] + red[3][0];
    sq  = red[0][1] + red[1][1] + red[2][1] + red[3][1];
    sxq = red[0][2] + red[1][2] + red[2][2] + red[3][2];
    sc  = red[0][3] + red[1][3] + red[2][3] + red[3][3];

    if (t == 0) g_commit[m] = sc;

    float norm_x = sqrtf(sx), norm_q = sqrtf(sq);
    float nx = fmaxf(norm_x, 1e-6f);
    float nq = fmaxf(norm_q, 1e-6f);
    float uq2 = sx / (nx * nx) + sq / (nq * nq) + 2.f * sxq / (nx * nq);
    float nuq = sqrtf(fmaxf(uq2, 0.f));
    float wden = fmaxf(nuq, 1e-12f);
    float e_w = (sx / nx + sxq / nq) / wden;
    float e_u = sx / nx;
    float c1 = 2.f * e_w / wden;
    float c2 = 2.f * e_u;
    float scale = norm_q / nx;
    float coef_x = (1.f - c1 / nx) * scale;
    float coef_q = ((c2 - c1) / nq) * scale;

    float4 ov;
    ov.x = coef_x * xv.x + coef_q * qv.x;
    ov.y = coef_x * xv.y + coef_q * qv.y;
    ov.z = coef_x * xv.z + coef_q * qv.z;
    ov.w = coef_x * xv.w + coef_q * qv.w;
    ((float4*)(outq + (size_t)m * DD))[t] = ov;
}

// ===========================================================================
// Kernel 7: deterministic loss reduction
// ===========================================================================
__global__ __launch_bounds__(256) void k_loss(float* __restrict__ out_loss) {
    __shared__ float s[256];
    float v = 0.f;
    for (int i = threadIdx.x; i < MM; i += 256) v += g_commit[i];
    s[threadIdx.x] = v;
    __syncthreads();
    for (int o = 128; o > 0; o >>= 1) {
        if (threadIdx.x < o) s[threadIdx.x] += s[threadIdx.x + o];
        __syncthreads();
    }
    if (threadIdx.x == 0) out_loss[0] = s[0] / (float)MM;
}

// ===========================================================================
extern "C" void kernel_launch(void* const* d_in, const int* in_sizes, int n_in,
                              void* d_out, int out_size) {
    const float* x  = (const float*)d_in[0];
    const float* cb = (const float*)d_in[1];
    const float* Wm = (const float*)d_in[2];
    float* out = (float*)d_out;

    int idx_off  = out_size - MM - 1;
    int loss_off = out_size - 1;

    static bool attr_done = false;
    if (!attr_done) {
        cudaFuncSetAttribute(k_screen_mma, cudaFuncAttributeMaxDynamicSharedMemorySize, SMEM_DYN);
        attr_done = true;
    }

    int8_t *xq, *cq; float *sA, *sB, *imp;
    cudaGetSymbolAddress((void**)&xq, g_xq);
    cudaGetSymbolAddress((void**)&cq, g_cq);
    cudaGetSymbolAddress((void**)&sA, g_sA);
    cudaGetSymbolAddress((void**)&sB, g_sB);
    cudaGetSymbolAddress((void**)&imp, g_implicit);

    k_implicit<<<dim3(CC / 128, DD / 128), 256>>>(cb, Wm);
    k_quant<<<MM / 8, 256>>>(x, xq, sA);
    k_quant<<<CC / 8, 256>>>(imp, cq, sB);
    k_halfnorm<<<CC / 8, 256>>>();
    k_screen_mma<<<MM / Bb_M, NTHR, SMEM_DYN>>>();
    k_rescore<<<MM / 8, 256>>>(x, out + idx_off);
    k_rot<<<MM, 128>>>(x, out);
    k_loss<<<1, 256>>>(out + loss_off);
}

// round 10
// speedup vs baseline: 2.0072x; 2.0072x over previous
#include <cuda_runtime.h>
#include <cuda_fp16.h>
#include <cstdint>

#define BB 8
#define NN 2048
#define DD 512
#define CC 4096
#define MM (BB*NN)   // 16384

// screen-kernel tiling
#define Bb_M 128
#define Bb_N 128
#define Bb_K 128                  // k-depth per B chunk (2 x 64-k blocks)
#define NCT (CC/Bb_N)             // 32 c-tiles
#define NKC (DD/Bb_K)             // 4 k-chunks per c-tile
#define NQ  (NCT*NKC)             // 128 chunks
#define KB_BYTES 16384            // one 64-k block: 128 rows x 64 halfs (128B)
#define BSTAGE_BYTES (2*KB_BYTES) // 32KB B stage (k=128)
#define A_BYTES  (8*KB_BYTES)     // resident A: 128 x 512 fp16 = 128KB
#define SMEM_DYN (A_BYTES + 2*BSTAGE_BYTES)   // 192KB
#define NTHR 512

// ---------------- scratch ----------------
__device__ float g_implicit[CC * DD];
__device__ float g_halfnorm[CC];
__device__ int   g_idx[MM];
__device__ int   g_cand[MM * 4];
__device__ float g_commit[MM];
__device__ __half g_xh[MM * DD];
__device__ __half g_ch[CC * DD];

// =============================== helpers ===================================
__device__ __forceinline__ uint32_t smem_u32(const void* p) {
    return (uint32_t)__cvta_generic_to_shared(p);
}
__device__ __forceinline__ void cp16(uint32_t s, const void* g) {
    asm volatile("cp.async.cg.shared.global [%0], [%1], 16;" :: "r"(s), "l"(g));
}
#define CP_COMMIT() asm volatile("cp.async.commit_group;")
#define CP_WAIT1()  asm volatile("cp.async.wait_group 1;")
#define LDM4(r0,r1,r2,r3,addr) \
    asm volatile("ldmatrix.sync.aligned.m8n8.x4.shared.b16 {%0,%1,%2,%3},[%4];" \
                 : "=r"(r0),"=r"(r1),"=r"(r2),"=r"(r3) : "r"(addr))
#define MMA16816(c,a,b) \
    asm volatile("mma.sync.aligned.m16n8k16.row.col.f32.f16.f16.f32 " \
                 "{%0,%1,%2,%3},{%4,%5,%6,%7},{%8,%9},{%0,%1,%2,%3};" \
                 : "+f"((c)[0]),"+f"((c)[1]),"+f"((c)[2]),"+f"((c)[3]) \
                 : "r"((a)[0]),"r"((a)[1]),"r"((a)[2]),"r"((a)[3]), \
                   "r"((b)[0]),"r"((b)[1]))

// sorted-4 insert (ascending, b0 = min); static indexing only
__device__ __forceinline__ void ins4(float v, int ii,
    float& b0, float& b1, float& b2, float& b3,
    int& i0, int& i1, int& i2, int& i3) {
    if (v < b3) {
        b3 = v; i3 = ii;
        if (b3 < b2) { float t = b2; b2 = b3; b3 = t; int u = i2; i2 = i3; i3 = u; }
        if (b2 < b1) { float t = b1; b1 = b2; b2 = t; int u = i1; i1 = i2; i2 = u; }
        if (b1 < b0) { float t = b0; b0 = b1; b1 = t; int u = i0; i0 = i1; i1 = u; }
    }
}

// ===========================================================================
// Kernel 1: implicit = codebook @ W^T  (fp32 SIMT, 2.1 GFLOP)
// ===========================================================================
__global__ __launch_bounds__(256) void k_implicit(const float* __restrict__ A,
                                                  const float* __restrict__ Wm) {
    __shared__ float As[8][128];
    __shared__ float Bs[8][128];
    const int tid = threadIdx.x;
    const int tx = tid & 15, ty = tid >> 4;
    const int m0 = blockIdx.x * 128;
    const int n0 = blockIdx.y * 128;
    const int lr = tid >> 1;
    const int lk = (tid & 1) * 4;

    float acc[2][2][4][4];
#pragma unroll
    for (int a = 0; a < 2; a++)
#pragma unroll
        for (int b = 0; b < 2; b++)
#pragma unroll
            for (int i = 0; i < 4; i++)
#pragma unroll
                for (int j = 0; j < 4; j++) acc[a][b][i][j] = 0.f;

    for (int k0 = 0; k0 < DD; k0 += 8) {
        float4 av = *(const float4*)&A[(size_t)(m0 + lr) * DD + k0 + lk];
        float4 bv = *(const float4*)&Wm[(size_t)(n0 + lr) * DD + k0 + lk];
        __syncthreads();
        As[lk + 0][lr] = av.x; As[lk + 1][lr] = av.y; As[lk + 2][lr] = av.z; As[lk + 3][lr] = av.w;
        Bs[lk + 0][lr] = bv.x; Bs[lk + 1][lr] = bv.y; Bs[lk + 2][lr] = bv.z; Bs[lk + 3][lr] = bv.w;
        __syncthreads();
#pragma unroll
        for (int kk = 0; kk < 8; kk++) {
            float4 a0 = *(const float4*)&As[kk][ty * 4];
            float4 a1 = *(const float4*)&As[kk][64 + ty * 4];
            float4 b0 = *(const float4*)&Bs[kk][tx * 4];
            float4 b1 = *(const float4*)&Bs[kk][64 + tx * 4];
            float ar[8] = {a0.x, a0.y, a0.z, a0.w, a1.x, a1.y, a1.z, a1.w};
            float br[8] = {b0.x, b0.y, b0.z, b0.w, b1.x, b1.y, b1.z, b1.w};
#pragma unroll
            for (int ih = 0; ih < 2; ih++)
#pragma unroll
                for (int i = 0; i < 4; i++)
#pragma unroll
                    for (int jh = 0; jh < 2; jh++)
#pragma unroll
                        for (int j = 0; j < 4; j++)
                            acc[ih][jh][i][j] += ar[ih * 4 + i] * br[jh * 4 + j];
        }
    }
#pragma unroll
    for (int ih = 0; ih < 2; ih++)
#pragma unroll
        for (int i = 0; i < 4; i++) {
            int rm = m0 + ih * 64 + ty * 4 + i;
#pragma unroll
            for (int jh = 0; jh < 2; jh++) {
                int cn = n0 + jh * 64 + tx * 4;
                float4 v = make_float4(acc[ih][jh][i][0], acc[ih][jh][i][1],
                                       acc[ih][jh][i][2], acc[ih][jh][i][3]);
                *(float4*)&g_implicit[(size_t)rm * DD + cn] = v;
            }
        }
}

// ===========================================================================
// Kernel 2: fp32 -> fp16 (screening copy)
// ===========================================================================
__global__ __launch_bounds__(256) void k_tohalf(const float* __restrict__ src,
                                                __half* __restrict__ dst, int n) {
    int i = 4 * (blockIdx.x * 256 + threadIdx.x);
    if (i >= n) return;
    float4 v = *(const float4*)(src + i);
    __half L[4] = {__float2half_rn(v.x), __float2half_rn(v.y),
                   __float2half_rn(v.z), __float2half_rn(v.w)};
    *(uint2*)(dst + i) = *(uint2*)L;
}

// ===========================================================================
// Kernel 3: halfnorm[c] = 0.5 * ||implicit[c]||^2
// ===========================================================================
__global__ __launch_bounds__(256) void k_halfnorm() {
    int warp = threadIdx.x >> 5, lane = threadIdx.x & 31;
    int row = blockIdx.x * 8 + warp;
    const float* p = g_implicit + (size_t)row * DD;
    float s = 0.f;
#pragma unroll
    for (int k = 0; k < DD / 32; k++) {
        float v = p[lane + 32 * k];
        s += v * v;
    }
#pragma unroll
    for (int o = 16; o > 0; o >>= 1) s += __shfl_xor_sync(0xffffffff, s, o);
    if (lane == 0) g_halfnorm[row] = 0.5f * s;
}

// ===========================================================================
// Kernel 4: HMMA screening GEMM + per-row top-4.  512 threads (4x4 warps).
// A resident (128KB, swizzled 64-k blocks); B streamed in k=128 chunks
// (2 x 64-k blocks per stage), double-buffered.
// swizzle within a block: phys = row*128 + ((seg ^ (row&7))<<4).
// ===========================================================================
__device__ __forceinline__ void issue_b(uint32_t st, int ct, int kc, int tid) {
#pragma unroll
    for (int j = 0; j < 4; j++) {
        int idx = j * NTHR + tid;          // 0..2047
        int kb2 = idx >> 10;               // 0..1
        int r = (idx & 1023) >> 3;
        int seg = idx & 7;
        const __half* g = g_ch + (size_t)(ct * Bb_N + r) * DD
                        + kc * Bb_K + kb2 * 64 + seg * 8;
        cp16(st + kb2 * KB_BYTES + r * 128 + (((seg ^ (r & 7))) << 4), g);
    }
}

__global__ __launch_bounds__(NTHR, 1) void k_screen_mma() {
    extern __shared__ char dsm[];
    __shared__ float sv[4][128][4];
    __shared__ int   si[4][128][4];

    const uint32_t sa = smem_u32(dsm);            // A resident, 128KB
    const uint32_t sbB = sa + A_BYTES;            // B stages (2 x 32KB)
    const int tid = threadIdx.x;
    const int lane = tid & 31;
    const int wid = tid >> 5;
    const int warp_m = wid >> 2;      // 0..3  (32 rows each)
    const int warp_n = wid & 3;       // 0..3  (32 cols each)
    const int m0 = blockIdx.x * Bb_M;
    const int gID = lane >> 2;        // 0..7
    const int tg  = lane & 3;         // 0..3

    const uint32_t aRow = (uint32_t)(warp_m * 32 + (lane & 15)) * 128;
    const uint32_t bRow = (uint32_t)(warp_n * 32 + ((lane >> 4) & 1) * 8 + (lane & 7)) * 128;
    const int lxor = lane & 7;

    // running per-row top-4 (owned by tid<128, row = m0+tid)
    float rb0 = 3.4e38f, rb1 = 3.4e38f, rb2 = 3.4e38f, rb3 = 3.4e38f;
    int   ri0 = 0, ri1 = 0, ri2 = 0, ri3 = 0;

    float acc[2][4][4];

    // ---- prologue: resident A (8192 segs) inside group 0, + B chunks 0,1 ----
#pragma unroll
    for (int t = 0; t < 16; t++) {
        int idx = t * NTHR + tid;          // 0..8191
        int row = idx >> 6, s = idx & 63;
        int kb = s >> 3, seg = s & 7;
        const __half* g = g_xh + (size_t)(m0 + row) * DD + kb * 64 + seg * 8;
        cp16(sa + kb * KB_BYTES + row * 128 + ((seg ^ (row & 7)) << 4), g);
    }
    issue_b(sbB + 0 * BSTAGE_BYTES, 0, 0, tid); CP_COMMIT();   // G0 (A + chunk0)
    issue_b(sbB + 1 * BSTAGE_BYTES, 0, 1, tid); CP_COMMIT();   // G1 (chunk1)

    for (int q = 0; q < NQ; q++) {
        const int ct = q >> 2;
        const int kc = q & 3;

        CP_WAIT1();          // group q (chunk q) complete; q+1 may be in flight
        __syncthreads();

        if (kc == 0) {
#pragma unroll
            for (int mt = 0; mt < 2; mt++)
#pragma unroll
                for (int nt = 0; nt < 4; nt++)
#pragma unroll
                    for (int e = 0; e < 4; e++) acc[mt][nt][e] = 0.f;
        }

        const uint32_t bStage = sbB + (q & 1) * BSTAGE_BYTES;
#pragma unroll
        for (int kb2 = 0; kb2 < 2; kb2++) {
            const uint32_t aBase = sa + (kc * 2 + kb2) * KB_BYTES;
            const uint32_t bBase = bStage + kb2 * KB_BYTES;
#pragma unroll
            for (int ks = 0; ks < 4; ks++) {
                const uint32_t aSw = (uint32_t)(((ks * 2 + (lane >> 4)) ^ lxor) << 4);
                const uint32_t bSw = (uint32_t)(((ks * 2 + ((lane >> 3) & 1)) ^ lxor) << 4);
                uint32_t aF[2][4], bF[4][2];
#pragma unroll
                for (int mt = 0; mt < 2; mt++)
                    LDM4(aF[mt][0], aF[mt][1], aF[mt][2], aF[mt][3],
                         aBase + aRow + mt * (16 * 128) + aSw);
#pragma unroll
                for (int p = 0; p < 2; p++) {
                    uint32_t r0, r1, r2, r3;
                    LDM4(r0, r1, r2, r3, bBase + bRow + p * (16 * 128) + bSw);
                    bF[2 * p][0] = r0; bF[2 * p][1] = r1;
                    bF[2 * p + 1][0] = r2; bF[2 * p + 1][1] = r3;
                }
#pragma unroll
                for (int mt = 0; mt < 2; mt++)
#pragma unroll
                    for (int nt = 0; nt < 4; nt++) MMA16816(acc[mt][nt], aF[mt], bF[nt]);
            }
        }

        if (kc == 3) {
            // -------- top-4 epilogue for this c-tile --------
#pragma unroll
            for (int mt = 0; mt < 2; mt++) {
#pragma unroll
                for (int half = 0; half < 2; half++) {
                    float b0 = 3.4e38f, b1 = 3.4e38f, b2 = 3.4e38f, b3 = 3.4e38f;
                    int   i0 = 0, i1 = 0, i2 = 0, i3 = 0;
#pragma unroll
                    for (int nt = 0; nt < 4; nt++) {
#pragma unroll
                        for (int j = 0; j < 2; j++) {
                            int c = ct * Bb_N + warp_n * 32 + nt * 8 + tg * 2 + j;
                            float s = __ldg(&g_halfnorm[c]) - acc[mt][nt][2 * half + j];
                            ins4(s, c, b0, b1, b2, b3, i0, i1, i2, i3);
                        }
                    }
#pragma unroll
                    for (int off = 1; off <= 2; off <<= 1) {
                        float ob0 = __shfl_xor_sync(0xffffffff, b0, off);
                        float ob1 = __shfl_xor_sync(0xffffffff, b1, off);
                        float ob2 = __shfl_xor_sync(0xffffffff, b2, off);
                        float ob3 = __shfl_xor_sync(0xffffffff, b3, off);
                        int oi0 = __shfl_xor_sync(0xffffffff, i0, off);
                        int oi1 = __shfl_xor_sync(0xffffffff, i1, off);
                        int oi2 = __shfl_xor_sync(0xffffffff, i2, off);
                        int oi3 = __shfl_xor_sync(0xffffffff, i3, off);
                        ins4(ob0, oi0, b0, b1, b2, b3, i0, i1, i2, i3);
                        ins4(ob1, oi1, b0, b1, b2, b3, i0, i1, i2, i3);
                        ins4(ob2, oi2, b0, b1, b2, b3, i0, i1, i2, i3);
                        ins4(ob3, oi3, b0, b1, b2, b3, i0, i1, i2, i3);
                    }
                    if (tg == 0) {
                        int r = warp_m * 32 + mt * 16 + gID + 8 * half;
                        sv[warp_n][r][0] = b0; sv[warp_n][r][1] = b1;
                        sv[warp_n][r][2] = b2; sv[warp_n][r][3] = b3;
                        si[warp_n][r][0] = i0; si[warp_n][r][1] = i1;
                        si[warp_n][r][2] = i2; si[warp_n][r][3] = i3;
                    }
                }
            }
            __syncthreads();
            if (tid < 128) {
#pragma unroll
                for (int wn = 0; wn < 4; wn++)
#pragma unroll
                    for (int s = 0; s < 4; s++)
                        ins4(sv[wn][tid][s], si[wn][tid][s],
                             rb0, rb1, rb2, rb3, ri0, ri1, ri2, ri3);
            }
        }

        __syncthreads();     // all warps done reading buffer (q&1)
        const int qn = q + 2;
        if (qn < NQ)
            issue_b(sbB + (qn & 1) * BSTAGE_BYTES, qn >> 2, qn & 3, tid);
        CP_COMMIT();         // group q+2 (possibly empty)
    }

    if (tid < 128) {
        int gm = m0 + tid;
        g_cand[gm * 4 + 0] = ri0;
        g_cand[gm * 4 + 1] = ri1;
        g_cand[gm * 4 + 2] = ri2;
        g_cand[gm * 4 + 3] = ri3;
    }
}

// ===========================================================================
// Kernel 5: exact fp32 rescore of the 4 candidates. One warp per row.
// ===========================================================================
__global__ __launch_bounds__(256) void k_rescore(const float* __restrict__ X,
                                                 float* __restrict__ out_idx_f) {
    const int warp = threadIdx.x >> 5, lane = threadIdx.x & 31;
    const int m = blockIdx.x * 8 + warp;
    const float* xr = X + (size_t)m * DD;

    float4 xv[4];
#pragma unroll
    for (int t = 0; t < 4; t++) xv[t] = ((const float4*)xr)[lane + 32 * t];

    float bestv = 3.4e38f;
    int   besti = 0x7fffffff;
#pragma unroll
    for (int k = 0; k < 4; k++) {
        int ci = g_cand[m * 4 + k];
        const float4* cr = (const float4*)(g_implicit + (size_t)ci * DD);
        float dot = 0.f;
#pragma unroll
        for (int t = 0; t < 4; t++) {
            float4 cv = cr[lane + 32 * t];
            dot += xv[t].x * cv.x + xv[t].y * cv.y + xv[t].z * cv.z + xv[t].w * cv.w;
        }
#pragma unroll
        for (int o = 16; o > 0; o >>= 1) dot += __shfl_xor_sync(0xffffffff, dot, o);
        float s = g_halfnorm[ci] - dot;
        if (s < bestv || (s == bestv && ci < besti)) { bestv = s; besti = ci; }
    }
    if (lane == 0) {
        g_idx[m] = besti;
        out_idx_f[m] = (float)besti;
    }
}

// ===========================================================================
// Kernel 6: rotation trick + per-row commit sum. One block per x-row.
// ===========================================================================
__global__ __launch_bounds__(128) void k_rot(const float* __restrict__ X,
                                             float* __restrict__ outq) {
    __shared__ float red[4][4];
    const int m = blockIdx.x;
    const int t = threadIdx.x;
    const float* xr = X + (size_t)m * DD;
    const float* qr = g_implicit + (size_t)g_idx[m] * DD;

    float4 xv = ((const float4*)xr)[t];
    float4 qv = ((const float4*)qr)[t];

    float sx  = xv.x * xv.x + xv.y * xv.y + xv.z * xv.z + xv.w * xv.w;
    float sq  = qv.x * qv.x + qv.y * qv.y + qv.z * qv.z + qv.w * qv.w;
    float sxq = xv.x * qv.x + xv.y * qv.y + xv.z * qv.z + xv.w * qv.w;
    float d0 = xv.x - qv.x + 1e-6f, d1 = xv.y - qv.y + 1e-6f;
    float d2 = xv.z - qv.z + 1e-6f, d3 = xv.w - qv.w + 1e-6f;
    float sc = d0 * d0 + d1 * d1 + d2 * d2 + d3 * d3;

#pragma unroll
    for (int o = 16; o > 0; o >>= 1) {
        sx  += __shfl_xor_sync(0xffffffff, sx, o);
        sq  += __shfl_xor_sync(0xffffffff, sq, o);
        sxq += __shfl_xor_sync(0xffffffff, sxq, o);
        sc  += __shfl_xor_sync(0xffffffff, sc, o);
    }
    int warp = t >> 5, lane = t & 31;
    if (lane == 0) { red[warp][0] = sx; red[warp][1] = sq; red[warp][2] = sxq; red[warp][3] = sc; }
    __syncthreads();
    sx  = red[0][0] + red[1][0] + red[2][0] + red[3][0];
    sq  = red[0][1] + red[1][1] + red[2][1] + red[3][1];
    sxq = red[0][2] + red[1][2] + red[2][2] + red[3][2];
    sc  = red[0][3] + red[1][3] + red[2][3] + red[3][3];

    if (t == 0) g_commit[m] = sc;

    float norm_x = sqrtf(sx), norm_q = sqrtf(sq);
    float nx = fmaxf(norm_x, 1e-6f);
    float nq = fmaxf(norm_q, 1e-6f);
    float uq2 = sx / (nx * nx) + sq / (nq * nq) + 2.f * sxq / (nx * nq);
    float nuq = sqrtf(fmaxf(uq2, 0.f));
    float wden = fmaxf(nuq, 1e-12f);
    float e_w = (sx / nx + sxq / nq) / wden;
    float e_u = sx / nx;
    float c1 = 2.f * e_w / wden;
    float c2 = 2.f * e_u;
    float scale = norm_q / nx;
    float coef_x = (1.f - c1 / nx) * scale;
    float coef_q = ((c2 - c1) / nq) * scale;

    float4 ov;
    ov.x = coef_x * xv.x + coef_q * qv.x;
    ov.y = coef_x * xv.y + coef_q * qv.y;
    ov.z = coef_x * xv.z + coef_q * qv.z;
    ov.w = coef_x * xv.w + coef_q * qv.w;
    ((float4*)(outq + (size_t)m * DD))[t] = ov;
}

// ===========================================================================
// Kernel 7: deterministic loss reduction
// ===========================================================================
__global__ __launch_bounds__(256) void k_loss(float* __restrict__ out_loss) {
    __shared__ float s[256];
    float v = 0.f;
    for (int i = threadIdx.x; i < MM; i += 256) v += g_commit[i];
    s[threadIdx.x] = v;
    __syncthreads();
    for (int o = 128; o > 0; o >>= 1) {
        if (threadIdx.x < o) s[threadIdx.x] += s[threadIdx.x + o];
        __syncthreads();
    }
    if (threadIdx.x == 0) out_loss[0] = s[0] / (float)MM;
}

// ===========================================================================
extern "C" void kernel_launch(void* const* d_in, const int* in_sizes, int n_in,
                              void* d_out, int out_size) {
    const float* x  = (const float*)d_in[0];
    const float* cb = (const float*)d_in[1];
    const float* Wm = (const float*)d_in[2];
    float* out = (float*)d_out;

    int idx_off  = out_size - MM - 1;
    int loss_off = out_size - 1;

    static bool attr_done = false;
    if (!attr_done) {
        cudaFuncSetAttribute(k_screen_mma, cudaFuncAttributeMaxDynamicSharedMemorySize, SMEM_DYN);
        attr_done = true;
    }

    __half *xh, *ch; float* imp;
    cudaGetSymbolAddress((void**)&xh, g_xh);
    cudaGetSymbolAddress((void**)&ch, g_ch);
    cudaGetSymbolAddress((void**)&imp, g_implicit);

    k_implicit<<<dim3(CC / 128, DD / 128), 256>>>(cb, Wm);
    k_tohalf<<<(MM * DD / 4 + 255) / 256, 256>>>(x, xh, MM * DD);
    k_tohalf<<<(CC * DD / 4 + 255) / 256, 256>>>(imp, ch, CC * DD);
    k_halfnorm<<<CC / 8, 256>>>();
    k_screen_mma<<<MM / Bb_M, NTHR, SMEM_DYN>>>();
    k_rescore<<<MM / 8, 256>>>(x, out + idx_off);
    k_rot<<<MM, 128>>>(x, out);
    k_loss<<<1, 256>>>(out + loss_off);
}

// round 11
// speedup vs baseline: 2.2925x; 1.1422x over previous
#include <cuda_runtime.h>
#include <cuda_fp16.h>
#include <cstdint>

#define BB 8
#define NN 2048
#define DD 512
#define CC 4096
#define MM (BB*NN)   // 16384

// screen-kernel tiling
#define Bb_M 128
#define Bb_N 128
#define Bb_K 128                  // k-depth per B chunk (2 x 64-k blocks)
#define NCT (CC/Bb_N)             // 32 c-tiles
#define NKC (DD/Bb_K)             // 4 k-chunks per c-tile
#define NQ  (NCT*NKC)             // 128 chunks
#define KB_BYTES 16384            // one 64-k block: 128 rows x 64 halfs (128B)
#define BSTAGE_BYTES (2*KB_BYTES) // 32KB B stage (k=128)
#define A_BYTES  (8*KB_BYTES)     // resident A: 128 x 512 fp16 = 128KB
#define SMEM_DYN (A_BYTES + 2*BSTAGE_BYTES)   // 192KB
#define NTHR 512

// implicit-GEMM smem: 2 stages x 4 tiles (A0,A1,B0,B1) x 16KB
#define SMEM_IMPL (2*4*KB_BYTES)  // 131072

// ---------------- scratch ----------------
__device__ float g_implicit[CC * DD];
__device__ float g_halfnorm[CC];
__device__ int   g_idx[MM];
__device__ int   g_cand[MM * 4];
__device__ float g_commit[MM];
__device__ __half g_xh[MM * DD];
__device__ __half g_ch[CC * DD];
__device__ __half g_cbl0[CC * DD];
__device__ __half g_cbl1[CC * DD];
__device__ __half g_wl0[DD * DD];
__device__ __half g_wl1[DD * DD];

// =============================== helpers ===================================
__device__ __forceinline__ uint32_t smem_u32(const void* p) {
    return (uint32_t)__cvta_generic_to_shared(p);
}
__device__ __forceinline__ void cp16(uint32_t s, const void* g) {
    asm volatile("cp.async.cg.shared.global [%0], [%1], 16;" :: "r"(s), "l"(g));
}
#define CP_COMMIT() asm volatile("cp.async.commit_group;")
#define CP_WAIT1()  asm volatile("cp.async.wait_group 1;")
#define LDM4(r0,r1,r2,r3,addr) \
    asm volatile("ldmatrix.sync.aligned.m8n8.x4.shared.b16 {%0,%1,%2,%3},[%4];" \
                 : "=r"(r0),"=r"(r1),"=r"(r2),"=r"(r3) : "r"(addr))
#define MMA16816(c,a,b) \
    asm volatile("mma.sync.aligned.m16n8k16.row.col.f32.f16.f16.f32 " \
                 "{%0,%1,%2,%3},{%4,%5,%6,%7},{%8,%9},{%0,%1,%2,%3};" \
                 : "+f"((c)[0]),"+f"((c)[1]),"+f"((c)[2]),"+f"((c)[3]) \
                 : "r"((a)[0]),"r"((a)[1]),"r"((a)[2]),"r"((a)[3]), \
                   "r"((b)[0]),"r"((b)[1]))

// sorted-4 insert (ascending, b0 = min); static indexing only
__device__ __forceinline__ void ins4(float v, int ii,
    float& b0, float& b1, float& b2, float& b3,
    int& i0, int& i1, int& i2, int& i3) {
    if (v < b3) {
        b3 = v; i3 = ii;
        if (b3 < b2) { float t = b2; b2 = b3; b3 = t; int u = i2; i2 = i3; i3 = u; }
        if (b2 < b1) { float t = b1; b1 = b2; b2 = t; int u = i1; i1 = i2; i2 = u; }
        if (b1 < b0) { float t = b0; b0 = b1; b1 = t; int u = i0; i0 = i1; i1 = u; }
    }
}

// ===========================================================================
// Kernel 1: k_prep_all — one warp per row.
//   rows [0, MM):            x row -> g_xh (fp16)
//   rows [MM, MM+CC):        codebook row -> g_cbl0/g_cbl1 (2-limb fp16)
//   rows [MM+CC, MM+CC+DD):  W row -> g_wl0/g_wl1 (2-limb fp16)
// ===========================================================================
__global__ __launch_bounds__(256) void k_prep_all(const float* __restrict__ x,
                                                  const float* __restrict__ cb,
                                                  const float* __restrict__ Wm) {
    const int warp = threadIdx.x >> 5, lane = threadIdx.x & 31;
    const int row = blockIdx.x * 8 + warp;

    if (row < MM) {
        const float4* sr = (const float4*)(x + (size_t)row * DD);
        __half* d = g_xh + (size_t)row * DD;
#pragma unroll
        for (int t = 0; t < 4; t++) {
            float4 v = sr[lane + 32 * t];
            __half L[4] = {__float2half_rn(v.x), __float2half_rn(v.y),
                           __float2half_rn(v.z), __float2half_rn(v.w)};
            *(uint2*)(d + 4 * (lane + 32 * t)) = *(uint2*)L;
        }
    } else {
        const float* src;
        __half *d0, *d1;
        if (row < MM + CC) {
            int r = row - MM;
            src = cb + (size_t)r * DD;
            d0 = g_cbl0 + (size_t)r * DD;
            d1 = g_cbl1 + (size_t)r * DD;
        } else {
            int r = row - MM - CC;
            src = Wm + (size_t)r * DD;
            d0 = g_wl0 + (size_t)r * DD;
            d1 = g_wl1 + (size_t)r * DD;
        }
        const float4* sr = (const float4*)src;
#pragma unroll
        for (int t = 0; t < 4; t++) {
            float4 v = sr[lane + 32 * t];
            float vv[4] = {v.x, v.y, v.z, v.w};
            __half L0[4], L1[4];
#pragma unroll
            for (int c = 0; c < 4; c++) {
                __half h0 = __float2half_rn(vv[c]);
                float r2 = vv[c] - __half2float(h0);
                L0[c] = h0;
                L1[c] = __float2half_rn(r2);
            }
            *(uint2*)(d0 + 4 * (lane + 32 * t)) = *(uint2*)L0;
            *(uint2*)(d1 + 4 * (lane + 32 * t)) = *(uint2*)L1;
        }
    }
}

// ===========================================================================
// Kernel 2: implicit = codebook @ W^T via fp16 2-limb 3-product HMMA.
// grid (32, 4): m0 = codebook rows, n0 = W rows.  256 thr, 8 warps (2x4).
// K chunks of 64, 2 stages x (A0,A1,B0,B1) 16KB tiles, swizzled.
// ===========================================================================
__device__ __forceinline__ void issue_impl(uint32_t st, int m0, int n0, int kc, int tid) {
#pragma unroll
    for (int t = 0; t < 16; t++) {
        const int tile = t >> 2;                       // 0..3, compile-time
        const int r = (t & 3) * 32 + (tid >> 3);       // 0..127
        const int seg = tid & 7;
        const __half* src;
        if (tile == 0)      src = g_cbl0 + (size_t)(m0 + r) * DD;
        else if (tile == 1) src = g_cbl1 + (size_t)(m0 + r) * DD;
        else if (tile == 2) src = g_wl0 + (size_t)(n0 + r) * DD;
        else                src = g_wl1 + (size_t)(n0 + r) * DD;
        cp16(st + tile * KB_BYTES + r * 128 + ((seg ^ (r & 7)) << 4),
             src + kc * 64 + seg * 8);
    }
}

__global__ __launch_bounds__(256, 1) void k_impl_mma() {
    extern __shared__ char dsm[];
    const uint32_t sb = smem_u32(dsm);
    const int tid = threadIdx.x;
    const int lane = tid & 31;
    const int wid = tid >> 5;
    const int warp_m = wid >> 2;      // 0..1  (64 rows each)
    const int warp_n = wid & 3;       // 0..3  (32 cols each)
    const int m0 = blockIdx.x * 128;
    const int n0 = blockIdx.y * 128;
    const int gID = lane >> 2;
    const int tg  = lane & 3;

    const uint32_t aRow = (uint32_t)(warp_m * 64 + (lane & 15)) * 128;
    const uint32_t bRow = (uint32_t)(warp_n * 32 + ((lane >> 4) & 1) * 8 + (lane & 7)) * 128;
    const int lxor = lane & 7;

    float acc[4][4][4];
#pragma unroll
    for (int mt = 0; mt < 4; mt++)
#pragma unroll
        for (int nt = 0; nt < 4; nt++)
#pragma unroll
            for (int e = 0; e < 4; e++) acc[mt][nt][e] = 0.f;

    issue_impl(sb + 0 * (4 * KB_BYTES), m0, n0, 0, tid); CP_COMMIT();
    issue_impl(sb + 1 * (4 * KB_BYTES), m0, n0, 1, tid); CP_COMMIT();

    for (int kc = 0; kc < 8; kc++) {
        CP_WAIT1();
        __syncthreads();

        const uint32_t st = sb + (kc & 1) * (4 * KB_BYTES);
#pragma unroll
        for (int ks = 0; ks < 4; ks++) {
            const uint32_t aSw = (uint32_t)(((ks * 2 + (lane >> 4)) ^ lxor) << 4);
            const uint32_t bSw = (uint32_t)(((ks * 2 + ((lane >> 3) & 1)) ^ lxor) << 4);
            uint32_t aF[4][4], b0F[4][2], b1F[4][2];
            // A limb0
#pragma unroll
            for (int mt = 0; mt < 4; mt++)
                LDM4(aF[mt][0], aF[mt][1], aF[mt][2], aF[mt][3],
                     st + 0 * KB_BYTES + aRow + mt * (16 * 128) + aSw);
            // B limb0
#pragma unroll
            for (int p = 0; p < 2; p++) {
                uint32_t r0, r1, r2, r3;
                LDM4(r0, r1, r2, r3, st + 2 * KB_BYTES + bRow + p * (16 * 128) + bSw);
                b0F[2 * p][0] = r0; b0F[2 * p][1] = r1;
                b0F[2 * p + 1][0] = r2; b0F[2 * p + 1][1] = r3;
            }
#pragma unroll
            for (int mt = 0; mt < 4; mt++)
#pragma unroll
                for (int nt = 0; nt < 4; nt++) MMA16816(acc[mt][nt], aF[mt], b0F[nt]);
            // B limb1
#pragma unroll
            for (int p = 0; p < 2; p++) {
                uint32_t r0, r1, r2, r3;
                LDM4(r0, r1, r2, r3, st + 3 * KB_BYTES + bRow + p * (16 * 128) + bSw);
                b1F[2 * p][0] = r0; b1F[2 * p][1] = r1;
                b1F[2 * p + 1][0] = r2; b1F[2 * p + 1][1] = r3;
            }
#pragma unroll
            for (int mt = 0; mt < 4; mt++)
#pragma unroll
                for (int nt = 0; nt < 4; nt++) MMA16816(acc[mt][nt], aF[mt], b1F[nt]);
            // A limb1 (overwrite aF)
#pragma unroll
            for (int mt = 0; mt < 4; mt++)
                LDM4(aF[mt][0], aF[mt][1], aF[mt][2], aF[mt][3],
                     st + 1 * KB_BYTES + aRow + mt * (16 * 128) + aSw);
#pragma unroll
            for (int mt = 0; mt < 4; mt++)
#pragma unroll
                for (int nt = 0; nt < 4; nt++) MMA16816(acc[mt][nt], aF[mt], b0F[nt]);
        }

        __syncthreads();
        const int kn = kc + 2;
        if (kn < 8)
            issue_impl(sb + (kn & 1) * (4 * KB_BYTES), m0, n0, kn, tid);
        CP_COMMIT();
    }

    // epilogue: write fp32 implicit
#pragma unroll
    for (int mt = 0; mt < 4; mt++) {
#pragma unroll
        for (int half = 0; half < 2; half++) {
            int row = m0 + warp_m * 64 + mt * 16 + gID + 8 * half;
#pragma unroll
            for (int nt = 0; nt < 4; nt++) {
                int col = n0 + warp_n * 32 + nt * 8 + tg * 2;
                float2 v = make_float2(acc[mt][nt][2 * half + 0],
                                       acc[mt][nt][2 * half + 1]);
                *(float2*)&g_implicit[(size_t)row * DD + col] = v;
            }
        }
    }
}

// ===========================================================================
// Kernel 3: k_prep_c — implicit row -> fp16 g_ch + halfnorm. One warp/row.
// ===========================================================================
__global__ __launch_bounds__(256) void k_prep_c() {
    const int warp = threadIdx.x >> 5, lane = threadIdx.x & 31;
    const int row = blockIdx.x * 8 + warp;
    const float4* sr = (const float4*)(g_implicit + (size_t)row * DD);
    __half* d = g_ch + (size_t)row * DD;
    float s = 0.f;
#pragma unroll
    for (int t = 0; t < 4; t++) {
        float4 v = sr[lane + 32 * t];
        s += v.x * v.x + v.y * v.y + v.z * v.z + v.w * v.w;
        __half L[4] = {__float2half_rn(v.x), __float2half_rn(v.y),
                       __float2half_rn(v.z), __float2half_rn(v.w)};
        *(uint2*)(d + 4 * (lane + 32 * t)) = *(uint2*)L;
    }
#pragma unroll
    for (int o = 16; o > 0; o >>= 1) s += __shfl_xor_sync(0xffffffff, s, o);
    if (lane == 0) g_halfnorm[row] = 0.5f * s;
}

// ===========================================================================
// Kernel 4: HMMA screening GEMM + per-row top-4.  (unchanged from R10)
// ===========================================================================
__device__ __forceinline__ void issue_b(uint32_t st, int ct, int kc, int tid) {
#pragma unroll
    for (int j = 0; j < 4; j++) {
        int idx = j * NTHR + tid;          // 0..2047
        int kb2 = idx >> 10;               // 0..1
        int r = (idx & 1023) >> 3;
        int seg = idx & 7;
        const __half* g = g_ch + (size_t)(ct * Bb_N + r) * DD
                        + kc * Bb_K + kb2 * 64 + seg * 8;
        cp16(st + kb2 * KB_BYTES + r * 128 + (((seg ^ (r & 7))) << 4), g);
    }
}

__global__ __launch_bounds__(NTHR, 1) void k_screen_mma() {
    extern __shared__ char dsm[];
    __shared__ float sv[4][128][4];
    __shared__ int   si[4][128][4];

    const uint32_t sa = smem_u32(dsm);            // A resident, 128KB
    const uint32_t sbB = sa + A_BYTES;            // B stages (2 x 32KB)
    const int tid = threadIdx.x;
    const int lane = tid & 31;
    const int wid = tid >> 5;
    const int warp_m = wid >> 2;      // 0..3  (32 rows each)
    const int warp_n = wid & 3;       // 0..3  (32 cols each)
    const int m0 = blockIdx.x * Bb_M;
    const int gID = lane >> 2;        // 0..7
    const int tg  = lane & 3;         // 0..3

    const uint32_t aRow = (uint32_t)(warp_m * 32 + (lane & 15)) * 128;
    const uint32_t bRow = (uint32_t)(warp_n * 32 + ((lane >> 4) & 1) * 8 + (lane & 7)) * 128;
    const int lxor = lane & 7;

    float rb0 = 3.4e38f, rb1 = 3.4e38f, rb2 = 3.4e38f, rb3 = 3.4e38f;
    int   ri0 = 0, ri1 = 0, ri2 = 0, ri3 = 0;

    float acc[2][4][4];

#pragma unroll
    for (int t = 0; t < 16; t++) {
        int idx = t * NTHR + tid;          // 0..8191
        int row = idx >> 6, s = idx & 63;
        int kb = s >> 3, seg = s & 7;
        const __half* g = g_xh + (size_t)(m0 + row) * DD + kb * 64 + seg * 8;
        cp16(sa + kb * KB_BYTES + row * 128 + ((seg ^ (row & 7)) << 4), g);
    }
    issue_b(sbB + 0 * BSTAGE_BYTES, 0, 0, tid); CP_COMMIT();
    issue_b(sbB + 1 * BSTAGE_BYTES, 0, 1, tid); CP_COMMIT();

    for (int q = 0; q < NQ; q++) {
        const int ct = q >> 2;
        const int kc = q & 3;

        CP_WAIT1();
        __syncthreads();

        if (kc == 0) {
#pragma unroll
            for (int mt = 0; mt < 2; mt++)
#pragma unroll
                for (int nt = 0; nt < 4; nt++)
#pragma unroll
                    for (int e = 0; e < 4; e++) acc[mt][nt][e] = 0.f;
        }

        const uint32_t bStage = sbB + (q & 1) * BSTAGE_BYTES;
#pragma unroll
        for (int kb2 = 0; kb2 < 2; kb2++) {
            const uint32_t aBase = sa + (kc * 2 + kb2) * KB_BYTES;
            const uint32_t bBase = bStage + kb2 * KB_BYTES;
#pragma unroll
            for (int ks = 0; ks < 4; ks++) {
                const uint32_t aSw = (uint32_t)(((ks * 2 + (lane >> 4)) ^ lxor) << 4);
                const uint32_t bSw = (uint32_t)(((ks * 2 + ((lane >> 3) & 1)) ^ lxor) << 4);
                uint32_t aF[2][4], bF[4][2];
#pragma unroll
                for (int mt = 0; mt < 2; mt++)
                    LDM4(aF[mt][0], aF[mt][1], aF[mt][2], aF[mt][3],
                         aBase + aRow + mt * (16 * 128) + aSw);
#pragma unroll
                for (int p = 0; p < 2; p++) {
                    uint32_t r0, r1, r2, r3;
                    LDM4(r0, r1, r2, r3, bBase + bRow + p * (16 * 128) + bSw);
                    bF[2 * p][0] = r0; bF[2 * p][1] = r1;
                    bF[2 * p + 1][0] = r2; bF[2 * p + 1][1] = r3;
                }
#pragma unroll
                for (int mt = 0; mt < 2; mt++)
#pragma unroll
                    for (int nt = 0; nt < 4; nt++) MMA16816(acc[mt][nt], aF[mt], bF[nt]);
            }
        }

        if (kc == 3) {
#pragma unroll
            for (int mt = 0; mt < 2; mt++) {
#pragma unroll
                for (int half = 0; half < 2; half++) {
                    float b0 = 3.4e38f, b1 = 3.4e38f, b2 = 3.4e38f, b3 = 3.4e38f;
                    int   i0 = 0, i1 = 0, i2 = 0, i3 = 0;
#pragma unroll
                    for (int nt = 0; nt < 4; nt++) {
#pragma unroll
                        for (int j = 0; j < 2; j++) {
                            int c = ct * Bb_N + warp_n * 32 + nt * 8 + tg * 2 + j;
                            float s = __ldg(&g_halfnorm[c]) - acc[mt][nt][2 * half + j];
                            ins4(s, c, b0, b1, b2, b3, i0, i1, i2, i3);
                        }
                    }
#pragma unroll
                    for (int off = 1; off <= 2; off <<= 1) {
                        float ob0 = __shfl_xor_sync(0xffffffff, b0, off);
                        float ob1 = __shfl_xor_sync(0xffffffff, b1, off);
                        float ob2 = __shfl_xor_sync(0xffffffff, b2, off);
                        float ob3 = __shfl_xor_sync(0xffffffff, b3, off);
                        int oi0 = __shfl_xor_sync(0xffffffff, i0, off);
                        int oi1 = __shfl_xor_sync(0xffffffff, i1, off);
                        int oi2 = __shfl_xor_sync(0xffffffff, i2, off);
                        int oi3 = __shfl_xor_sync(0xffffffff, i3, off);
                        ins4(ob0, oi0, b0, b1, b2, b3, i0, i1, i2, i3);
                        ins4(ob1, oi1, b0, b1, b2, b3, i0, i1, i2, i3);
                        ins4(ob2, oi2, b0, b1, b2, b3, i0, i1, i2, i3);
                        ins4(ob3, oi3, b0, b1, b2, b3, i0, i1, i2, i3);
                    }
                    if (tg == 0) {
                        int r = warp_m * 32 + mt * 16 + gID + 8 * half;
                        sv[warp_n][r][0] = b0; sv[warp_n][r][1] = b1;
                        sv[warp_n][r][2] = b2; sv[warp_n][r][3] = b3;
                        si[warp_n][r][0] = i0; si[warp_n][r][1] = i1;
                        si[warp_n][r][2] = i2; si[warp_n][r][3] = i3;
                    }
                }
            }
            __syncthreads();
            if (tid < 128) {
#pragma unroll
                for (int wn = 0; wn < 4; wn++)
#pragma unroll
                    for (int s = 0; s < 4; s++)
                        ins4(sv[wn][tid][s], si[wn][tid][s],
                             rb0, rb1, rb2, rb3, ri0, ri1, ri2, ri3);
            }
        }

        __syncthreads();
        const int qn = q + 2;
        if (qn < NQ)
            issue_b(sbB + (qn & 1) * BSTAGE_BYTES, qn >> 2, qn & 3, tid);
        CP_COMMIT();
    }

    if (tid < 128) {
        int gm = m0 + tid;
        g_cand[gm * 4 + 0] = ri0;
        g_cand[gm * 4 + 1] = ri1;
        g_cand[gm * 4 + 2] = ri2;
        g_cand[gm * 4 + 3] = ri3;
    }
}

// ===========================================================================
// Kernel 5: exact fp32 rescore of the 4 candidates. One warp per row.
// ===========================================================================
__global__ __launch_bounds__(256) void k_rescore(const float* __restrict__ X,
                                                 float* __restrict__ out_idx_f) {
    const int warp = threadIdx.x >> 5, lane = threadIdx.x & 31;
    const int m = blockIdx.x * 8 + warp;
    const float* xr = X + (size_t)m * DD;

    float4 xv[4];
#pragma unroll
    for (int t = 0; t < 4; t++) xv[t] = ((const float4*)xr)[lane + 32 * t];

    float bestv = 3.4e38f;
    int   besti = 0x7fffffff;
#pragma unroll
    for (int k = 0; k < 4; k++) {
        int ci = g_cand[m * 4 + k];
        const float4* cr = (const float4*)(g_implicit + (size_t)ci * DD);
        float dot = 0.f;
#pragma unroll
        for (int t = 0; t < 4; t++) {
            float4 cv = cr[lane + 32 * t];
            dot += xv[t].x * cv.x + xv[t].y * cv.y + xv[t].z * cv.z + xv[t].w * cv.w;
        }
#pragma unroll
        for (int o = 16; o > 0; o >>= 1) dot += __shfl_xor_sync(0xffffffff, dot, o);
        float s = g_halfnorm[ci] - dot;
        if (s < bestv || (s == bestv && ci < besti)) { bestv = s; besti = ci; }
    }
    if (lane == 0) {
        g_idx[m] = besti;
        out_idx_f[m] = (float)besti;
    }
}

// ===========================================================================
// Kernel 6: rotation trick + per-row commit sum. One block per x-row.
// ===========================================================================
__global__ __launch_bounds__(128) void k_rot(const float* __restrict__ X,
                                             float* __restrict__ outq) {
    __shared__ float red[4][4];
    const int m = blockIdx.x;
    const int t = threadIdx.x;
    const float* xr = X + (size_t)m * DD;
    const float* qr = g_implicit + (size_t)g_idx[m] * DD;

    float4 xv = ((const float4*)xr)[t];
    float4 qv = ((const float4*)qr)[t];

    float sx  = xv.x * xv.x + xv.y * xv.y + xv.z * xv.z + xv.w * xv.w;
    float sq  = qv.x * qv.x + qv.y * qv.y + qv.z * qv.z + qv.w * qv.w;
    float sxq = xv.x * qv.x + xv.y * qv.y + xv.z * qv.z + xv.w * qv.w;
    float d0 = xv.x - qv.x + 1e-6f, d1 = xv.y - qv.y + 1e-6f;
    float d2 = xv.z - qv.z + 1e-6f, d3 = xv.w - qv.w + 1e-6f;
    float sc = d0 * d0 + d1 * d1 + d2 * d2 + d3 * d3;

#pragma unroll
    for (int o = 16; o > 0; o >>= 1) {
        sx  += __shfl_xor_sync(0xffffffff, sx, o);
        sq  += __shfl_xor_sync(0xffffffff, sq, o);
        sxq += __shfl_xor_sync(0xffffffff, sxq, o);
        sc  += __shfl_xor_sync(0xffffffff, sc, o);
    }
    int warp = t >> 5, lane = t & 31;
    if (lane == 0) { red[warp][0] = sx; red[warp][1] = sq; red[warp][2] = sxq; red[warp][3] = sc; }
    __syncthreads();
    sx  = red[0][0] + red[1][0] + red[2][0] + red[3][0];
    sq  = red[0][1] + red[1][1] + red[2][1] + red[3][1];
    sxq = red[0][2] + red[1][2] + red[2][2] + red[3][2];
    sc  = red[0][3] + red[1][3] + red[2][3] + red[3][3];

    if (t == 0) g_commit[m] = sc;

    float norm_x = sqrtf(sx), norm_q = sqrtf(sq);
    float nx = fmaxf(norm_x, 1e-6f);
    float nq = fmaxf(norm_q, 1e-6f);
    float uq2 = sx / (nx * nx) + sq / (nq * nq) + 2.f * sxq / (nx * nq);
    float nuq = sqrtf(fmaxf(uq2, 0.f));
    float wden = fmaxf(nuq, 1e-12f);
    float e_w = (sx / nx + sxq / nq) / wden;
    float e_u = sx / nx;
    float c1 = 2.f * e_w / wden;
    float c2 = 2.f * e_u;
    float scale = norm_q / nx;
    float coef_x = (1.f - c1 / nx) * scale;
    float coef_q = ((c2 - c1) / nq) * scale;

    float4 ov;
    ov.x = coef_x * xv.x + coef_q * qv.x;
    ov.y = coef_x * xv.y + coef_q * qv.y;
    ov.z = coef_x * xv.z + coef_q * qv.z;
    ov.w = coef_x * xv.w + coef_q * qv.w;
    ((float4*)(outq + (size_t)m * DD))[t] = ov;
}

// ===========================================================================
// Kernel 7: deterministic loss reduction
// ===========================================================================
__global__ __launch_bounds__(256) void k_loss(float* __restrict__ out_loss) {
    __shared__ float s[256];
    float v = 0.f;
    for (int i = threadIdx.x; i < MM; i += 256) v += g_commit[i];
    s[threadIdx.x] = v;
    __syncthreads();
    for (int o = 128; o > 0; o >>= 1) {
        if (threadIdx.x < o) s[threadIdx.x] += s[threadIdx.x + o];
        __syncthreads();
    }
    if (threadIdx.x == 0) out_loss[0] = s[0] / (float)MM;
}

// ===========================================================================
extern "C" void kernel_launch(void* const* d_in, const int* in_sizes, int n_in,
                              void* d_out, int out_size) {
    const float* x  = (const float*)d_in[0];
    const float* cb = (const float*)d_in[1];
    const float* Wm = (const float*)d_in[2];
    float* out = (float*)d_out;

    int idx_off  = out_size - MM - 1;
    int loss_off = out_size - 1;

    static bool attr_done = false;
    if (!attr_done) {
        cudaFuncSetAttribute(k_screen_mma, cudaFuncAttributeMaxDynamicSharedMemorySize, SMEM_DYN);
        cudaFuncSetAttribute(k_impl_mma, cudaFuncAttributeMaxDynamicSharedMemorySize, SMEM_IMPL);
        attr_done = true;
    }

    k_prep_all<<<(MM + CC + DD) / 8, 256>>>(x, cb, Wm);
    k_impl_mma<<<dim3(CC / 128, DD / 128), 256, SMEM_IMPL>>>();
    k_prep_c<<<CC / 8, 256>>>();
    k_screen_mma<<<MM / Bb_M, NTHR, SMEM_DYN>>>();
    k_rescore<<<MM / 8, 256>>>(x, out + idx_off);
    k_rot<<<MM, 128>>>(x, out);
    k_loss<<<1, 256>>>(out + loss_off);
}

// round 12
// speedup vs baseline: 3.0800x; 1.3435x over previous
#include <cuda_runtime.h>
#include <cuda_fp16.h>
#include <cstdint>

#define BB 8
#define NN 2048
#define DD 512
#define CC 4096
#define MM (BB*NN)   // 16384

// screen-kernel tiling
#define Bb_M 128
#define Bb_N 128
#define Bb_K 128                  // k-depth per B chunk (2 x 64-k blocks)
#define NCT (CC/Bb_N)             // 32 c-tiles
#define NKC (DD/Bb_K)             // 4 k-chunks per c-tile
#define NQ  (NCT*NKC)             // 128 chunks
#define KB_BYTES 16384            // one 64-k block: 128 rows x 64 halfs (128B)
#define BSTAGE_BYTES (2*KB_BYTES) // 32KB B stage (k=128)
#define A_BYTES  (8*KB_BYTES)     // resident A: 128 x 512 fp16 = 128KB
#define SMEM_DYN (A_BYTES + 2*BSTAGE_BYTES)   // 192KB
#define NTHR 512

// implicit-GEMM smem: 2 stages x 4 tiles (A0,A1,B0,B1) x 16KB
#define SMEM_IMPL (2*4*KB_BYTES)  // 131072

// ---------------- scratch ----------------
__device__ float g_implicit[CC * DD];
__device__ float g_halfnorm[CC];
__device__ int   g_cand[MM * 4];
__device__ float g_commit[MM];
__device__ __half g_xh[MM * DD];
__device__ __half g_ch[CC * DD];
__device__ __half g_cbl0[CC * DD];
__device__ __half g_cbl1[CC * DD];
__device__ __half g_wl0[DD * DD];
__device__ __half g_wl1[DD * DD];

// =============================== helpers ===================================
__device__ __forceinline__ uint32_t smem_u32(const void* p) {
    return (uint32_t)__cvta_generic_to_shared(p);
}
__device__ __forceinline__ void cp16(uint32_t s, const void* g) {
    asm volatile("cp.async.cg.shared.global [%0], [%1], 16;" :: "r"(s), "l"(g));
}
#define CP_COMMIT() asm volatile("cp.async.commit_group;")
#define CP_WAIT1()  asm volatile("cp.async.wait_group 1;")
#define LDM4(r0,r1,r2,r3,addr) \
    asm volatile("ldmatrix.sync.aligned.m8n8.x4.shared.b16 {%0,%1,%2,%3},[%4];" \
                 : "=r"(r0),"=r"(r1),"=r"(r2),"=r"(r3) : "r"(addr))
#define MMA16816(c,a,b) \
    asm volatile("mma.sync.aligned.m16n8k16.row.col.f32.f16.f16.f32 " \
                 "{%0,%1,%2,%3},{%4,%5,%6,%7},{%8,%9},{%0,%1,%2,%3};" \
                 : "+f"((c)[0]),"+f"((c)[1]),"+f"((c)[2]),"+f"((c)[3]) \
                 : "r"((a)[0]),"r"((a)[1]),"r"((a)[2]),"r"((a)[3]), \
                   "r"((b)[0]),"r"((b)[1]))

// float -> order-preserving uint
__device__ __forceinline__ uint32_t fkey(float f) {
    uint32_t u = __float_as_uint(f);
    uint32_t m = (u & 0x80000000u) ? 0xFFFFFFFFu : 0x80000000u;
    return u ^ m;
}
// branchless sorted-4 insert (ascending) on packed keys: 7 min/max ops
__device__ __forceinline__ void ins4u(uint32_t v, uint32_t& b0, uint32_t& b1,
                                      uint32_t& b2, uint32_t& b3) {
    uint32_t m0 = max(b0, v); b0 = min(b0, v);
    uint32_t m1 = max(b1, m0); b1 = min(b1, m0);
    uint32_t m2 = max(b2, m1); b2 = min(b2, m1);
    b3 = min(b3, m2);
}

// ===========================================================================
// Kernel 1: k_prep_all — one warp per row.
//   rows [0, MM):            x row -> g_xh (fp16)
//   rows [MM, MM+CC):        codebook row -> g_cbl0/g_cbl1 (2-limb fp16)
//   rows [MM+CC, MM+CC+DD):  W row -> g_wl0/g_wl1 (2-limb fp16)
// ===========================================================================
__global__ __launch_bounds__(256) void k_prep_all(const float* __restrict__ x,
                                                  const float* __restrict__ cb,
                                                  const float* __restrict__ Wm) {
    const int warp = threadIdx.x >> 5, lane = threadIdx.x & 31;
    const int row = blockIdx.x * 8 + warp;

    if (row < MM) {
        const float4* sr = (const float4*)(x + (size_t)row * DD);
        __half* d = g_xh + (size_t)row * DD;
#pragma unroll
        for (int t = 0; t < 4; t++) {
            float4 v = sr[lane + 32 * t];
            __half L[4] = {__float2half_rn(v.x), __float2half_rn(v.y),
                           __float2half_rn(v.z), __float2half_rn(v.w)};
            *(uint2*)(d + 4 * (lane + 32 * t)) = *(uint2*)L;
        }
    } else {
        const float* src;
        __half *d0, *d1;
        if (row < MM + CC) {
            int r = row - MM;
            src = cb + (size_t)r * DD;
            d0 = g_cbl0 + (size_t)r * DD;
            d1 = g_cbl1 + (size_t)r * DD;
        } else {
            int r = row - MM - CC;
            src = Wm + (size_t)r * DD;
            d0 = g_wl0 + (size_t)r * DD;
            d1 = g_wl1 + (size_t)r * DD;
        }
        const float4* sr = (const float4*)src;
#pragma unroll
        for (int t = 0; t < 4; t++) {
            float4 v = sr[lane + 32 * t];
            float vv[4] = {v.x, v.y, v.z, v.w};
            __half L0[4], L1[4];
#pragma unroll
            for (int c = 0; c < 4; c++) {
                __half h0 = __float2half_rn(vv[c]);
                float r2 = vv[c] - __half2float(h0);
                L0[c] = h0;
                L1[c] = __float2half_rn(r2);
            }
            *(uint2*)(d0 + 4 * (lane + 32 * t)) = *(uint2*)L0;
            *(uint2*)(d1 + 4 * (lane + 32 * t)) = *(uint2*)L1;
        }
    }
}

// ===========================================================================
// Kernel 2: implicit = codebook @ W^T via fp16 2-limb 3-product HMMA.
// ===========================================================================
__device__ __forceinline__ void issue_impl(uint32_t st, int m0, int n0, int kc, int tid) {
#pragma unroll
    for (int t = 0; t < 16; t++) {
        const int tile = t >> 2;
        const int r = (t & 3) * 32 + (tid >> 3);
        const int seg = tid & 7;
        const __half* src;
        if (tile == 0)      src = g_cbl0 + (size_t)(m0 + r) * DD;
        else if (tile == 1) src = g_cbl1 + (size_t)(m0 + r) * DD;
        else if (tile == 2) src = g_wl0 + (size_t)(n0 + r) * DD;
        else                src = g_wl1 + (size_t)(n0 + r) * DD;
        cp16(st + tile * KB_BYTES + r * 128 + ((seg ^ (r & 7)) << 4),
             src + kc * 64 + seg * 8);
    }
}

__global__ __launch_bounds__(256, 1) void k_impl_mma() {
    extern __shared__ char dsm[];
    const uint32_t sb = smem_u32(dsm);
    const int tid = threadIdx.x;
    const int lane = tid & 31;
    const int wid = tid >> 5;
    const int warp_m = wid >> 2;
    const int warp_n = wid & 3;
    const int m0 = blockIdx.x * 128;
    const int n0 = blockIdx.y * 128;
    const int gID = lane >> 2;
    const int tg  = lane & 3;

    const uint32_t aRow = (uint32_t)(warp_m * 64 + (lane & 15)) * 128;
    const uint32_t bRow = (uint32_t)(warp_n * 32 + ((lane >> 4) & 1) * 8 + (lane & 7)) * 128;
    const int lxor = lane & 7;

    float acc[4][4][4];
#pragma unroll
    for (int mt = 0; mt < 4; mt++)
#pragma unroll
        for (int nt = 0; nt < 4; nt++)
#pragma unroll
            for (int e = 0; e < 4; e++) acc[mt][nt][e] = 0.f;

    issue_impl(sb + 0 * (4 * KB_BYTES), m0, n0, 0, tid); CP_COMMIT();
    issue_impl(sb + 1 * (4 * KB_BYTES), m0, n0, 1, tid); CP_COMMIT();

    for (int kc = 0; kc < 8; kc++) {
        CP_WAIT1();
        __syncthreads();

        const uint32_t st = sb + (kc & 1) * (4 * KB_BYTES);
#pragma unroll
        for (int ks = 0; ks < 4; ks++) {
            const uint32_t aSw = (uint32_t)(((ks * 2 + (lane >> 4)) ^ lxor) << 4);
            const uint32_t bSw = (uint32_t)(((ks * 2 + ((lane >> 3) & 1)) ^ lxor) << 4);
            uint32_t aF[4][4], b0F[4][2], b1F[4][2];
#pragma unroll
            for (int mt = 0; mt < 4; mt++)
                LDM4(aF[mt][0], aF[mt][1], aF[mt][2], aF[mt][3],
                     st + 0 * KB_BYTES + aRow + mt * (16 * 128) + aSw);
#pragma unroll
            for (int p = 0; p < 2; p++) {
                uint32_t r0, r1, r2, r3;
                LDM4(r0, r1, r2, r3, st + 2 * KB_BYTES + bRow + p * (16 * 128) + bSw);
                b0F[2 * p][0] = r0; b0F[2 * p][1] = r1;
                b0F[2 * p + 1][0] = r2; b0F[2 * p + 1][1] = r3;
            }
#pragma unroll
            for (int mt = 0; mt < 4; mt++)
#pragma unroll
                for (int nt = 0; nt < 4; nt++) MMA16816(acc[mt][nt], aF[mt], b0F[nt]);
#pragma unroll
            for (int p = 0; p < 2; p++) {
                uint32_t r0, r1, r2, r3;
                LDM4(r0, r1, r2, r3, st + 3 * KB_BYTES + bRow + p * (16 * 128) + bSw);
                b1F[2 * p][0] = r0; b1F[2 * p][1] = r1;
                b1F[2 * p + 1][0] = r2; b1F[2 * p + 1][1] = r3;
            }
#pragma unroll
            for (int mt = 0; mt < 4; mt++)
#pragma unroll
                for (int nt = 0; nt < 4; nt++) MMA16816(acc[mt][nt], aF[mt], b1F[nt]);
#pragma unroll
            for (int mt = 0; mt < 4; mt++)
                LDM4(aF[mt][0], aF[mt][1], aF[mt][2], aF[mt][3],
                     st + 1 * KB_BYTES + aRow + mt * (16 * 128) + aSw);
#pragma unroll
            for (int mt = 0; mt < 4; mt++)
#pragma unroll
                for (int nt = 0; nt < 4; nt++) MMA16816(acc[mt][nt], aF[mt], b0F[nt]);
        }

        __syncthreads();
        const int kn = kc + 2;
        if (kn < 8)
            issue_impl(sb + (kn & 1) * (4 * KB_BYTES), m0, n0, kn, tid);
        CP_COMMIT();
    }

#pragma unroll
    for (int mt = 0; mt < 4; mt++) {
#pragma unroll
        for (int half = 0; half < 2; half++) {
            int row = m0 + warp_m * 64 + mt * 16 + gID + 8 * half;
#pragma unroll
            for (int nt = 0; nt < 4; nt++) {
                int col = n0 + warp_n * 32 + nt * 8 + tg * 2;
                float2 v = make_float2(acc[mt][nt][2 * half + 0],
                                       acc[mt][nt][2 * half + 1]);
                *(float2*)&g_implicit[(size_t)row * DD + col] = v;
            }
        }
    }
}

// ===========================================================================
// Kernel 3: k_prep_c — implicit row -> fp16 g_ch + halfnorm. One warp/row.
// ===========================================================================
__global__ __launch_bounds__(256) void k_prep_c() {
    const int warp = threadIdx.x >> 5, lane = threadIdx.x & 31;
    const int row = blockIdx.x * 8 + warp;
    const float4* sr = (const float4*)(g_implicit + (size_t)row * DD);
    __half* d = g_ch + (size_t)row * DD;
    float s = 0.f;
#pragma unroll
    for (int t = 0; t < 4; t++) {
        float4 v = sr[lane + 32 * t];
        s += v.x * v.x + v.y * v.y + v.z * v.z + v.w * v.w;
        __half L[4] = {__float2half_rn(v.x), __float2half_rn(v.y),
                       __float2half_rn(v.z), __float2half_rn(v.w)};
        *(uint2*)(d + 4 * (lane + 32 * t)) = *(uint2*)L;
    }
#pragma unroll
    for (int o = 16; o > 0; o >>= 1) s += __shfl_xor_sync(0xffffffff, s, o);
    if (lane == 0) g_halfnorm[row] = 0.5f * s;
}

// ===========================================================================
// Kernel 4: HMMA screening GEMM + per-row top-4 via packed sortable keys.
// ===========================================================================
__device__ __forceinline__ void issue_b(uint32_t st, int ct, int kc, int tid) {
#pragma unroll
    for (int j = 0; j < 4; j++) {
        int idx = j * NTHR + tid;
        int kb2 = idx >> 10;
        int r = (idx & 1023) >> 3;
        int seg = idx & 7;
        const __half* g = g_ch + (size_t)(ct * Bb_N + r) * DD
                        + kc * Bb_K + kb2 * 64 + seg * 8;
        cp16(st + kb2 * KB_BYTES + r * 128 + (((seg ^ (r & 7))) << 4), g);
    }
}

__global__ __launch_bounds__(NTHR, 1) void k_screen_mma() {
    extern __shared__ char dsm[];
    __shared__ uint32_t sv[4][128][4];

    const uint32_t sa = smem_u32(dsm);
    const uint32_t sbB = sa + A_BYTES;
    const int tid = threadIdx.x;
    const int lane = tid & 31;
    const int wid = tid >> 5;
    const int warp_m = wid >> 2;
    const int warp_n = wid & 3;
    const int m0 = blockIdx.x * Bb_M;
    const int gID = lane >> 2;
    const int tg  = lane & 3;

    const uint32_t aRow = (uint32_t)(warp_m * 32 + (lane & 15)) * 128;
    const uint32_t bRow = (uint32_t)(warp_n * 32 + ((lane >> 4) & 1) * 8 + (lane & 7)) * 128;
    const int lxor = lane & 7;

    // running per-row top-4 packed keys (owned by tid<128)
    uint32_t rb0 = 0xFFFFFFFFu, rb1 = 0xFFFFFFFFu, rb2 = 0xFFFFFFFFu, rb3 = 0xFFFFFFFFu;

    float acc[2][4][4];

#pragma unroll
    for (int t = 0; t < 16; t++) {
        int idx = t * NTHR + tid;
        int row = idx >> 6, s = idx & 63;
        int kb = s >> 3, seg = s & 7;
        const __half* g = g_xh + (size_t)(m0 + row) * DD + kb * 64 + seg * 8;
        cp16(sa + kb * KB_BYTES + row * 128 + ((seg ^ (row & 7)) << 4), g);
    }
    issue_b(sbB + 0 * BSTAGE_BYTES, 0, 0, tid); CP_COMMIT();
    issue_b(sbB + 1 * BSTAGE_BYTES, 0, 1, tid); CP_COMMIT();

    for (int q = 0; q < NQ; q++) {
        const int ct = q >> 2;
        const int kc = q & 3;

        CP_WAIT1();
        __syncthreads();

        if (kc == 0) {
#pragma unroll
            for (int mt = 0; mt < 2; mt++)
#pragma unroll
                for (int nt = 0; nt < 4; nt++)
#pragma unroll
                    for (int e = 0; e < 4; e++) acc[mt][nt][e] = 0.f;
        }

        const uint32_t bStage = sbB + (q & 1) * BSTAGE_BYTES;
#pragma unroll
        for (int kb2 = 0; kb2 < 2; kb2++) {
            const uint32_t aBase = sa + (kc * 2 + kb2) * KB_BYTES;
            const uint32_t bBase = bStage + kb2 * KB_BYTES;
#pragma unroll
            for (int ks = 0; ks < 4; ks++) {
                const uint32_t aSw = (uint32_t)(((ks * 2 + (lane >> 4)) ^ lxor) << 4);
                const uint32_t bSw = (uint32_t)(((ks * 2 + ((lane >> 3) & 1)) ^ lxor) << 4);
                uint32_t aF[2][4], bF[4][2];
#pragma unroll
                for (int mt = 0; mt < 2; mt++)
                    LDM4(aF[mt][0], aF[mt][1], aF[mt][2], aF[mt][3],
                         aBase + aRow + mt * (16 * 128) + aSw);
#pragma unroll
                for (int p = 0; p < 2; p++) {
                    uint32_t r0, r1, r2, r3;
                    LDM4(r0, r1, r2, r3, bBase + bRow + p * (16 * 128) + bSw);
                    bF[2 * p][0] = r0; bF[2 * p][1] = r1;
                    bF[2 * p + 1][0] = r2; bF[2 * p + 1][1] = r3;
                }
#pragma unroll
                for (int mt = 0; mt < 2; mt++)
#pragma unroll
                    for (int nt = 0; nt < 4; nt++) MMA16816(acc[mt][nt], aF[mt], bF[nt]);
            }
        }

        if (kc == 3) {
            // hoisted halfnorm loads: this thread's 8 columns (same for all mt/half)
            float2 hn[4];
#pragma unroll
            for (int nt = 0; nt < 4; nt++)
                hn[nt] = *(const float2*)&g_halfnorm[ct * Bb_N + warp_n * 32 + nt * 8 + tg * 2];

#pragma unroll
            for (int mt = 0; mt < 2; mt++) {
#pragma unroll
                for (int half = 0; half < 2; half++) {
                    uint32_t b0 = 0xFFFFFFFFu, b1 = 0xFFFFFFFFu,
                             b2 = 0xFFFFFFFFu, b3 = 0xFFFFFFFFu;
#pragma unroll
                    for (int nt = 0; nt < 4; nt++) {
                        int cbase = ct * Bb_N + warp_n * 32 + nt * 8 + tg * 2;
                        float s0 = hn[nt].x - acc[mt][nt][2 * half + 0];
                        float s1 = hn[nt].y - acc[mt][nt][2 * half + 1];
                        ins4u((fkey(s0) & 0xFFFFF000u) | (uint32_t)cbase, b0, b1, b2, b3);
                        ins4u((fkey(s1) & 0xFFFFF000u) | (uint32_t)(cbase + 1), b0, b1, b2, b3);
                    }
#pragma unroll
                    for (int off = 1; off <= 2; off <<= 1) {
                        uint32_t o0 = __shfl_xor_sync(0xffffffff, b0, off);
                        uint32_t o1 = __shfl_xor_sync(0xffffffff, b1, off);
                        uint32_t o2 = __shfl_xor_sync(0xffffffff, b2, off);
                        uint32_t o3 = __shfl_xor_sync(0xffffffff, b3, off);
                        ins4u(o0, b0, b1, b2, b3);
                        ins4u(o1, b0, b1, b2, b3);
                        ins4u(o2, b0, b1, b2, b3);
                        ins4u(o3, b0, b1, b2, b3);
                    }
                    if (tg == 0) {
                        int r = warp_m * 32 + mt * 16 + gID + 8 * half;
                        sv[warp_n][r][0] = b0; sv[warp_n][r][1] = b1;
                        sv[warp_n][r][2] = b2; sv[warp_n][r][3] = b3;
                    }
                }
            }
            __syncthreads();
            if (tid < 128) {
#pragma unroll
                for (int wn = 0; wn < 4; wn++) {
                    ins4u(sv[wn][tid][0], rb0, rb1, rb2, rb3);
                    ins4u(sv[wn][tid][1], rb0, rb1, rb2, rb3);
                    ins4u(sv[wn][tid][2], rb0, rb1, rb2, rb3);
                    ins4u(sv[wn][tid][3], rb0, rb1, rb2, rb3);
                }
            }
        }

        __syncthreads();
        const int qn = q + 2;
        if (qn < NQ)
            issue_b(sbB + (qn & 1) * BSTAGE_BYTES, qn >> 2, qn & 3, tid);
        CP_COMMIT();
    }

    if (tid < 128) {
        int gm = m0 + tid;
        g_cand[gm * 4 + 0] = (int)(rb0 & 0xFFFu);
        g_cand[gm * 4 + 1] = (int)(rb1 & 0xFFFu);
        g_cand[gm * 4 + 2] = (int)(rb2 & 0xFFFu);
        g_cand[gm * 4 + 3] = (int)(rb3 & 0xFFFu);
    }
}

// ===========================================================================
// Kernel 5: fused exact rescore (4 candidates) + rotation. One block per row.
// ===========================================================================
__global__ __launch_bounds__(128) void k_rescore_rot(const float* __restrict__ X,
                                                     float* __restrict__ outq,
                                                     float* __restrict__ out_idx_f) {
    __shared__ float xs[DD];
    __shared__ float cscore[4];
    __shared__ int   cidx[4];
    __shared__ float red[4][4];

    const int m = blockIdx.x;
    const int t = threadIdx.x;
    const int warp = t >> 5, lane = t & 31;
    const float* xr = X + (size_t)m * DD;

    float4 xv = ((const float4*)xr)[t];
    ((float4*)xs)[t] = xv;
    __syncthreads();

    // phase 1: warp w rescores candidate w (exact fp32)
    {
        int ci = g_cand[m * 4 + warp];
        const float4* cr = (const float4*)(g_implicit + (size_t)ci * DD);
        float dot = 0.f;
#pragma unroll
        for (int t2 = 0; t2 < 4; t2++) {
            float4 cv = cr[lane + 32 * t2];
            float4 x4 = ((const float4*)xs)[lane + 32 * t2];
            dot += x4.x * cv.x + x4.y * cv.y + x4.z * cv.z + x4.w * cv.w;
        }
#pragma unroll
        for (int o = 16; o > 0; o >>= 1) dot += __shfl_xor_sync(0xffffffff, dot, o);
        if (lane == 0) {
            cscore[warp] = g_halfnorm[ci] - dot;
            cidx[warp] = ci;
        }
    }
    __syncthreads();

    // deterministic argmin over the 4 candidates (all threads identical)
    float bv = cscore[0]; int bi = cidx[0];
#pragma unroll
    for (int k = 1; k < 4; k++) {
        float v = cscore[k]; int ci = cidx[k];
        if (v < bv || (v == bv && ci < bi)) { bv = v; bi = ci; }
    }
    if (t == 0) out_idx_f[m] = (float)bi;

    // phase 2: rotation trick with chosen q
    const float* qr = g_implicit + (size_t)bi * DD;
    float4 qv = ((const float4*)qr)[t];

    float sx  = xv.x * xv.x + xv.y * xv.y + xv.z * xv.z + xv.w * xv.w;
    float sq  = qv.x * qv.x + qv.y * qv.y + qv.z * qv.z + qv.w * qv.w;
    float sxq = xv.x * qv.x + xv.y * qv.y + xv.z * qv.z + xv.w * qv.w;
    float d0 = xv.x - qv.x + 1e-6f, d1 = xv.y - qv.y + 1e-6f;
    float d2 = xv.z - qv.z + 1e-6f, d3 = xv.w - qv.w + 1e-6f;
    float sc = d0 * d0 + d1 * d1 + d2 * d2 + d3 * d3;

#pragma unroll
    for (int o = 16; o > 0; o >>= 1) {
        sx  += __shfl_xor_sync(0xffffffff, sx, o);
        sq  += __shfl_xor_sync(0xffffffff, sq, o);
        sxq += __shfl_xor_sync(0xffffffff, sxq, o);
        sc  += __shfl_xor_sync(0xffffffff, sc, o);
    }
    if (lane == 0) { red[warp][0] = sx; red[warp][1] = sq; red[warp][2] = sxq; red[warp][3] = sc; }
    __syncthreads();
    sx  = red[0][0] + red[1][0] + red[2][0] + red[3][0];
    sq  = red[0][1] + red[1][1] + red[2][1] + red[3][1];
    sxq = red[0][2] + red[1][2] + red[2][2] + red[3][2];
    sc  = red[0][3] + red[1][3] + red[2][3] + red[3][3];

    if (t == 0) g_commit[m] = sc;

    float norm_x = sqrtf(sx), norm_q = sqrtf(sq);
    float nx = fmaxf(norm_x, 1e-6f);
    float nq = fmaxf(norm_q, 1e-6f);
    float uq2 = sx / (nx * nx) + sq / (nq * nq) + 2.f * sxq / (nx * nq);
    float nuq = sqrtf(fmaxf(uq2, 0.f));
    float wden = fmaxf(nuq, 1e-12f);
    float e_w = (sx / nx + sxq / nq) / wden;
    float e_u = sx / nx;
    float c1 = 2.f * e_w / wden;
    float c2 = 2.f * e_u;
    float scale = norm_q / nx;
    float coef_x = (1.f - c1 / nx) * scale;
    float coef_q = ((c2 - c1) / nq) * scale;

    float4 ov;
    ov.x = coef_x * xv.x + coef_q * qv.x;
    ov.y = coef_x * xv.y + coef_q * qv.y;
    ov.z = coef_x * xv.z + coef_q * qv.z;
    ov.w = coef_x * xv.w + coef_q * qv.w;
    ((float4*)(outq + (size_t)m * DD))[t] = ov;
}

// ===========================================================================
// Kernel 6: deterministic loss reduction
// ===========================================================================
__global__ __launch_bounds__(256) void k_loss(float* __restrict__ out_loss) {
    __shared__ float s[256];
    float v = 0.f;
    for (int i = threadIdx.x; i < MM; i += 256) v += g_commit[i];
    s[threadIdx.x] = v;
    __syncthreads();
    for (int o = 128; o > 0; o >>= 1) {
        if (threadIdx.x < o) s[threadIdx.x] += s[threadIdx.x + o];
        __syncthreads();
    }
    if (threadIdx.x == 0) out_loss[0] = s[0] / (float)MM;
}

// ===========================================================================
extern "C" void kernel_launch(void* const* d_in, const int* in_sizes, int n_in,
                              void* d_out, int out_size) {
    const float* x  = (const float*)d_in[0];
    const float* cb = (const float*)d_in[1];
    const float* Wm = (const float*)d_in[2];
    float* out = (float*)d_out;

    int idx_off  = out_size - MM - 1;
    int loss_off = out_size - 1;

    static bool attr_done = false;
    if (!attr_done) {
        cudaFuncSetAttribute(k_screen_mma, cudaFuncAttributeMaxDynamicSharedMemorySize, SMEM_DYN);
        cudaFuncSetAttribute(k_impl_mma, cudaFuncAttributeMaxDynamicSharedMemorySize, SMEM_IMPL);
        attr_done = true;
    }

    k_prep_all<<<(MM + CC + DD) / 8, 256>>>(x, cb, Wm);
    k_impl_mma<<<dim3(CC / 128, DD / 128), 256, SMEM_IMPL>>>();
    k_prep_c<<<CC / 8, 256>>>();
    k_screen_mma<<<MM / Bb_M, NTHR, SMEM_DYN>>>();
    k_rescore_rot<<<MM, 128>>>(x, out, out + idx_off);
    k_loss<<<1, 256>>>(out + loss_off);
}

// round 13
// speedup vs baseline: 3.5125x; 1.1404x over previous
#include <cuda_runtime.h>
#include <cuda_fp16.h>
#include <cstdint>

#define BB 8
#define NN 2048
#define DD 512
#define CC 4096
#define MM (BB*NN)   // 16384

// screen-kernel tiling
#define Bb_M 128
#define Bb_N 128
#define Bb_K 128                  // k-depth per B chunk (2 x 64-k blocks)
#define NCT (CC/Bb_N)             // 32 c-tiles
#define NKC (DD/Bb_K)             // 4 k-chunks per c-tile
#define NQ  (NCT*NKC)             // 128 chunks
#define KB_BYTES 16384            // one 64-k block: 128 rows x 64 halfs (128B)
#define BSTAGE_BYTES (2*KB_BYTES) // 32KB B stage (k=128)
#define A_BYTES  (8*KB_BYTES)     // resident A: 128 x 512 fp16 = 128KB
#define SMEM_DYN (A_BYTES + 2*BSTAGE_BYTES)   // 192KB
#define NTHR 512

// implicit-GEMM smem: 2 stages x 4 tiles (A0,A1,B0,B1) x 16KB
#define SMEM_IMPL (2*4*KB_BYTES)  // 131072

// ---------------- scratch ----------------
__device__ float g_implicit[CC * DD];
__device__ float g_halfnorm[CC];
__device__ int   g_cand[MM * 4];
__device__ float g_commit[MM];
__device__ __half g_xh[MM * DD];
__device__ __half g_ch[CC * DD];
__device__ __half g_cbl0[CC * DD];
__device__ __half g_cbl1[CC * DD];
__device__ __half g_wl0[DD * DD];
__device__ __half g_wl1[DD * DD];

// =============================== helpers ===================================
__device__ __forceinline__ uint32_t smem_u32(const void* p) {
    return (uint32_t)__cvta_generic_to_shared(p);
}
__device__ __forceinline__ void cp16(uint32_t s, const void* g) {
    asm volatile("cp.async.cg.shared.global [%0], [%1], 16;" :: "r"(s), "l"(g));
}
#define CP_COMMIT() asm volatile("cp.async.commit_group;")
#define CP_WAIT1()  asm volatile("cp.async.wait_group 1;")
#define LDM4(r0,r1,r2,r3,addr) \
    asm volatile("ldmatrix.sync.aligned.m8n8.x4.shared.b16 {%0,%1,%2,%3},[%4];" \
                 : "=r"(r0),"=r"(r1),"=r"(r2),"=r"(r3) : "r"(addr))
#define MMA16816(c,a,b) \
    asm volatile("mma.sync.aligned.m16n8k16.row.col.f32.f16.f16.f32 " \
                 "{%0,%1,%2,%3},{%4,%5,%6,%7},{%8,%9},{%0,%1,%2,%3};" \
                 : "+f"((c)[0]),"+f"((c)[1]),"+f"((c)[2]),"+f"((c)[3]) \
                 : "r"((a)[0]),"r"((a)[1]),"r"((a)[2]),"r"((a)[3]), \
                   "r"((b)[0]),"r"((b)[1]))

// float -> order-preserving uint
__device__ __forceinline__ uint32_t fkey(float f) {
    uint32_t u = __float_as_uint(f);
    uint32_t m = (u & 0x80000000u) ? 0xFFFFFFFFu : 0x80000000u;
    return u ^ m;
}
// branchless sorted-2 insert (ascending): 3 ops
__device__ __forceinline__ void ins2u(uint32_t v, uint32_t& b0, uint32_t& b1) {
    uint32_t m0 = max(b0, v);
    b0 = min(b0, v);
    b1 = min(b1, m0);
}
// branchless sorted-4 insert (ascending): 7 ops
__device__ __forceinline__ void ins4u(uint32_t v, uint32_t& b0, uint32_t& b1,
                                      uint32_t& b2, uint32_t& b3) {
    uint32_t m0 = max(b0, v); b0 = min(b0, v);
    uint32_t m1 = max(b1, m0); b1 = min(b1, m0);
    uint32_t m2 = max(b2, m1); b2 = min(b2, m1);
    b3 = min(b3, m2);
}

// ===========================================================================
// Kernel 1: k_prep_all — one warp per row.
// ===========================================================================
__global__ __launch_bounds__(256) void k_prep_all(const float* __restrict__ x,
                                                  const float* __restrict__ cb,
                                                  const float* __restrict__ Wm) {
    const int warp = threadIdx.x >> 5, lane = threadIdx.x & 31;
    const int row = blockIdx.x * 8 + warp;

    if (row < MM) {
        const float4* sr = (const float4*)(x + (size_t)row * DD);
        __half* d = g_xh + (size_t)row * DD;
#pragma unroll
        for (int t = 0; t < 4; t++) {
            float4 v = sr[lane + 32 * t];
            __half L[4] = {__float2half_rn(v.x), __float2half_rn(v.y),
                           __float2half_rn(v.z), __float2half_rn(v.w)};
            *(uint2*)(d + 4 * (lane + 32 * t)) = *(uint2*)L;
        }
    } else {
        const float* src;
        __half *d0, *d1;
        if (row < MM + CC) {
            int r = row - MM;
            src = cb + (size_t)r * DD;
            d0 = g_cbl0 + (size_t)r * DD;
            d1 = g_cbl1 + (size_t)r * DD;
        } else {
            int r = row - MM - CC;
            src = Wm + (size_t)r * DD;
            d0 = g_wl0 + (size_t)r * DD;
            d1 = g_wl1 + (size_t)r * DD;
        }
        const float4* sr = (const float4*)src;
#pragma unroll
        for (int t = 0; t < 4; t++) {
            float4 v = sr[lane + 32 * t];
            float vv[4] = {v.x, v.y, v.z, v.w};
            __half L0[4], L1[4];
#pragma unroll
            for (int c = 0; c < 4; c++) {
                __half h0 = __float2half_rn(vv[c]);
                float r2 = vv[c] - __half2float(h0);
                L0[c] = h0;
                L1[c] = __float2half_rn(r2);
            }
            *(uint2*)(d0 + 4 * (lane + 32 * t)) = *(uint2*)L0;
            *(uint2*)(d1 + 4 * (lane + 32 * t)) = *(uint2*)L1;
        }
    }
}

// ===========================================================================
// Kernel 2: implicit = codebook @ W^T via fp16 2-limb 3-product HMMA.
// ===========================================================================
__device__ __forceinline__ void issue_impl(uint32_t st, int m0, int n0, int kc, int tid) {
#pragma unroll
    for (int t = 0; t < 16; t++) {
        const int tile = t >> 2;
        const int r = (t & 3) * 32 + (tid >> 3);
        const int seg = tid & 7;
        const __half* src;
        if (tile == 0)      src = g_cbl0 + (size_t)(m0 + r) * DD;
        else if (tile == 1) src = g_cbl1 + (size_t)(m0 + r) * DD;
        else if (tile == 2) src = g_wl0 + (size_t)(n0 + r) * DD;
        else                src = g_wl1 + (size_t)(n0 + r) * DD;
        cp16(st + tile * KB_BYTES + r * 128 + ((seg ^ (r & 7)) << 4),
             src + kc * 64 + seg * 8);
    }
}

__global__ __launch_bounds__(256, 1) void k_impl_mma() {
    extern __shared__ char dsm[];
    const uint32_t sb = smem_u32(dsm);
    const int tid = threadIdx.x;
    const int lane = tid & 31;
    const int wid = tid >> 5;
    const int warp_m = wid >> 2;
    const int warp_n = wid & 3;
    const int m0 = blockIdx.x * 128;
    const int n0 = blockIdx.y * 128;
    const int gID = lane >> 2;
    const int tg  = lane & 3;

    const uint32_t aRow = (uint32_t)(warp_m * 64 + (lane & 15)) * 128;
    const uint32_t bRow = (uint32_t)(warp_n * 32 + ((lane >> 4) & 1) * 8 + (lane & 7)) * 128;
    const int lxor = lane & 7;

    float acc[4][4][4];
#pragma unroll
    for (int mt = 0; mt < 4; mt++)
#pragma unroll
        for (int nt = 0; nt < 4; nt++)
#pragma unroll
            for (int e = 0; e < 4; e++) acc[mt][nt][e] = 0.f;

    issue_impl(sb + 0 * (4 * KB_BYTES), m0, n0, 0, tid); CP_COMMIT();
    issue_impl(sb + 1 * (4 * KB_BYTES), m0, n0, 1, tid); CP_COMMIT();

    for (int kc = 0; kc < 8; kc++) {
        CP_WAIT1();
        __syncthreads();

        const uint32_t st = sb + (kc & 1) * (4 * KB_BYTES);
#pragma unroll
        for (int ks = 0; ks < 4; ks++) {
            const uint32_t aSw = (uint32_t)(((ks * 2 + (lane >> 4)) ^ lxor) << 4);
            const uint32_t bSw = (uint32_t)(((ks * 2 + ((lane >> 3) & 1)) ^ lxor) << 4);
            uint32_t aF[4][4], b0F[4][2], b1F[4][2];
#pragma unroll
            for (int mt = 0; mt < 4; mt++)
                LDM4(aF[mt][0], aF[mt][1], aF[mt][2], aF[mt][3],
                     st + 0 * KB_BYTES + aRow + mt * (16 * 128) + aSw);
#pragma unroll
            for (int p = 0; p < 2; p++) {
                uint32_t r0, r1, r2, r3;
                LDM4(r0, r1, r2, r3, st + 2 * KB_BYTES + bRow + p * (16 * 128) + bSw);
                b0F[2 * p][0] = r0; b0F[2 * p][1] = r1;
                b0F[2 * p + 1][0] = r2; b0F[2 * p + 1][1] = r3;
            }
#pragma unroll
            for (int mt = 0; mt < 4; mt++)
#pragma unroll
                for (int nt = 0; nt < 4; nt++) MMA16816(acc[mt][nt], aF[mt], b0F[nt]);
#pragma unroll
            for (int p = 0; p < 2; p++) {
                uint32_t r0, r1, r2, r3;
                LDM4(r0, r1, r2, r3, st + 3 * KB_BYTES + bRow + p * (16 * 128) + bSw);
                b1F[2 * p][0] = r0; b1F[2 * p][1] = r1;
                b1F[2 * p + 1][0] = r2; b1F[2 * p + 1][1] = r3;
            }
#pragma unroll
            for (int mt = 0; mt < 4; mt++)
#pragma unroll
                for (int nt = 0; nt < 4; nt++) MMA16816(acc[mt][nt], aF[mt], b1F[nt]);
#pragma unroll
            for (int mt = 0; mt < 4; mt++)
                LDM4(aF[mt][0], aF[mt][1], aF[mt][2], aF[mt][3],
                     st + 1 * KB_BYTES + aRow + mt * (16 * 128) + aSw);
#pragma unroll
            for (int mt = 0; mt < 4; mt++)
#pragma unroll
                for (int nt = 0; nt < 4; nt++) MMA16816(acc[mt][nt], aF[mt], b0F[nt]);
        }

        __syncthreads();
        const int kn = kc + 2;
        if (kn < 8)
            issue_impl(sb + (kn & 1) * (4 * KB_BYTES), m0, n0, kn, tid);
        CP_COMMIT();
    }

#pragma unroll
    for (int mt = 0; mt < 4; mt++) {
#pragma unroll
        for (int half = 0; half < 2; half++) {
            int row = m0 + warp_m * 64 + mt * 16 + gID + 8 * half;
#pragma unroll
            for (int nt = 0; nt < 4; nt++) {
                int col = n0 + warp_n * 32 + nt * 8 + tg * 2;
                float2 v = make_float2(acc[mt][nt][2 * half + 0],
                                       acc[mt][nt][2 * half + 1]);
                *(float2*)&g_implicit[(size_t)row * DD + col] = v;
            }
        }
    }
}

// ===========================================================================
// Kernel 3: k_prep_c — implicit row -> fp16 g_ch + halfnorm. One warp/row.
// ===========================================================================
__global__ __launch_bounds__(256) void k_prep_c() {
    const int warp = threadIdx.x >> 5, lane = threadIdx.x & 31;
    const int row = blockIdx.x * 8 + warp;
    const float4* sr = (const float4*)(g_implicit + (size_t)row * DD);
    __half* d = g_ch + (size_t)row * DD;
    float s = 0.f;
#pragma unroll
    for (int t = 0; t < 4; t++) {
        float4 v = sr[lane + 32 * t];
        s += v.x * v.x + v.y * v.y + v.z * v.z + v.w * v.w;
        __half L[4] = {__float2half_rn(v.x), __float2half_rn(v.y),
                       __float2half_rn(v.z), __float2half_rn(v.w)};
        *(uint2*)(d + 4 * (lane + 32 * t)) = *(uint2*)L;
    }
#pragma unroll
    for (int o = 16; o > 0; o >>= 1) s += __shfl_xor_sync(0xffffffff, s, o);
    if (lane == 0) g_halfnorm[row] = 0.5f * s;
}

// ===========================================================================
// Kernel 4: HMMA screening GEMM. Per-thread RUNNING top-2 per row-slot
// (packed keys); single merge at kernel end. No per-tile reductions.
// ===========================================================================
__device__ __forceinline__ void issue_b(uint32_t st, int ct, int kc, int tid) {
#pragma unroll
    for (int j = 0; j < 4; j++) {
        int idx = j * NTHR + tid;
        int kb2 = idx >> 10;
        int r = (idx & 1023) >> 3;
        int seg = idx & 7;
        const __half* g = g_ch + (size_t)(ct * Bb_N + r) * DD
                        + kc * Bb_K + kb2 * 64 + seg * 8;
        cp16(st + kb2 * KB_BYTES + r * 128 + (((seg ^ (r & 7))) << 4), g);
    }
}

__global__ __launch_bounds__(NTHR, 1) void k_screen_mma() {
    extern __shared__ char dsm[];
    __shared__ uint32_t sv[4][128][4];

    const uint32_t sa = smem_u32(dsm);
    const uint32_t sbB = sa + A_BYTES;
    const int tid = threadIdx.x;
    const int lane = tid & 31;
    const int wid = tid >> 5;
    const int warp_m = wid >> 2;
    const int warp_n = wid & 3;
    const int m0 = blockIdx.x * Bb_M;
    const int gID = lane >> 2;
    const int tg  = lane & 3;

    const uint32_t aRow = (uint32_t)(warp_m * 32 + (lane & 15)) * 128;
    const uint32_t bRow = (uint32_t)(warp_n * 32 + ((lane >> 4) & 1) * 8 + (lane & 7)) * 128;
    const int lxor = lane & 7;

    // per-thread running top-2 per row-slot [mt][half]
    uint32_t t2[2][2][2];
#pragma unroll
    for (int mt = 0; mt < 2; mt++)
#pragma unroll
        for (int h = 0; h < 2; h++) { t2[mt][h][0] = 0xFFFFFFFFu; t2[mt][h][1] = 0xFFFFFFFFu; }

    float acc[2][4][4];

#pragma unroll
    for (int t = 0; t < 16; t++) {
        int idx = t * NTHR + tid;
        int row = idx >> 6, s = idx & 63;
        int kb = s >> 3, seg = s & 7;
        const __half* g = g_xh + (size_t)(m0 + row) * DD + kb * 64 + seg * 8;
        cp16(sa + kb * KB_BYTES + row * 128 + ((seg ^ (row & 7)) << 4), g);
    }
    issue_b(sbB + 0 * BSTAGE_BYTES, 0, 0, tid); CP_COMMIT();
    issue_b(sbB + 1 * BSTAGE_BYTES, 0, 1, tid); CP_COMMIT();

    for (int q = 0; q < NQ; q++) {
        const int ct = q >> 2;
        const int kc = q & 3;

        CP_WAIT1();
        __syncthreads();

        if (kc == 0) {
#pragma unroll
            for (int mt = 0; mt < 2; mt++)
#pragma unroll
                for (int nt = 0; nt < 4; nt++)
#pragma unroll
                    for (int e = 0; e < 4; e++) acc[mt][nt][e] = 0.f;
        }

        const uint32_t bStage = sbB + (q & 1) * BSTAGE_BYTES;
#pragma unroll
        for (int kb2 = 0; kb2 < 2; kb2++) {
            const uint32_t aBase = sa + (kc * 2 + kb2) * KB_BYTES;
            const uint32_t bBase = bStage + kb2 * KB_BYTES;
#pragma unroll
            for (int ks = 0; ks < 4; ks++) {
                const uint32_t aSw = (uint32_t)(((ks * 2 + (lane >> 4)) ^ lxor) << 4);
                const uint32_t bSw = (uint32_t)(((ks * 2 + ((lane >> 3) & 1)) ^ lxor) << 4);
                uint32_t aF[2][4], bF[4][2];
#pragma unroll
                for (int mt = 0; mt < 2; mt++)
                    LDM4(aF[mt][0], aF[mt][1], aF[mt][2], aF[mt][3],
                         aBase + aRow + mt * (16 * 128) + aSw);
#pragma unroll
                for (int p = 0; p < 2; p++) {
                    uint32_t r0, r1, r2, r3;
                    LDM4(r0, r1, r2, r3, bBase + bRow + p * (16 * 128) + bSw);
                    bF[2 * p][0] = r0; bF[2 * p][1] = r1;
                    bF[2 * p + 1][0] = r2; bF[2 * p + 1][1] = r3;
                }
#pragma unroll
                for (int mt = 0; mt < 2; mt++)
#pragma unroll
                    for (int nt = 0; nt < 4; nt++) MMA16816(acc[mt][nt], aF[mt], bF[nt]);
            }
        }

        if (kc == 3) {
            float2 hn[4];
#pragma unroll
            for (int nt = 0; nt < 4; nt++)
                hn[nt] = *(const float2*)&g_halfnorm[ct * Bb_N + warp_n * 32 + nt * 8 + tg * 2];

#pragma unroll
            for (int mt = 0; mt < 2; mt++) {
#pragma unroll
                for (int half = 0; half < 2; half++) {
#pragma unroll
                    for (int nt = 0; nt < 4; nt++) {
                        int cbase = ct * Bb_N + warp_n * 32 + nt * 8 + tg * 2;
                        float s0 = hn[nt].x - acc[mt][nt][2 * half + 0];
                        float s1 = hn[nt].y - acc[mt][nt][2 * half + 1];
                        ins2u((fkey(s0) & 0xFFFFF000u) | (uint32_t)cbase,
                              t2[mt][half][0], t2[mt][half][1]);
                        ins2u((fkey(s1) & 0xFFFFF000u) | (uint32_t)(cbase + 1),
                              t2[mt][half][0], t2[mt][half][1]);
                    }
                }
            }
        }

        __syncthreads();
        const int qn = q + 2;
        if (qn < NQ)
            issue_b(sbB + (qn & 1) * BSTAGE_BYTES, qn >> 2, qn & 3, tid);
        CP_COMMIT();
    }

    // ---- one-time merge: lanes (tg) -> smem -> global top-4 per row ----
#pragma unroll
    for (int mt = 0; mt < 2; mt++) {
#pragma unroll
        for (int half = 0; half < 2; half++) {
            uint32_t b0 = t2[mt][half][0], b1 = t2[mt][half][1];
            uint32_t b2 = 0xFFFFFFFFu, b3 = 0xFFFFFFFFu;
#pragma unroll
            for (int off = 1; off <= 2; off <<= 1) {
                uint32_t o0 = __shfl_xor_sync(0xffffffff, b0, off);
                uint32_t o1 = __shfl_xor_sync(0xffffffff, b1, off);
                uint32_t o2 = __shfl_xor_sync(0xffffffff, b2, off);
                uint32_t o3 = __shfl_xor_sync(0xffffffff, b3, off);
                ins4u(o0, b0, b1, b2, b3);
                ins4u(o1, b0, b1, b2, b3);
                ins4u(o2, b0, b1, b2, b3);
                ins4u(o3, b0, b1, b2, b3);
            }
            if (tg == 0) {
                int r = warp_m * 32 + mt * 16 + gID + 8 * half;
                sv[warp_n][r][0] = b0; sv[warp_n][r][1] = b1;
                sv[warp_n][r][2] = b2; sv[warp_n][r][3] = b3;
            }
        }
    }
    __syncthreads();
    if (tid < 128) {
        uint32_t rb0 = 0xFFFFFFFFu, rb1 = 0xFFFFFFFFu, rb2 = 0xFFFFFFFFu, rb3 = 0xFFFFFFFFu;
#pragma unroll
        for (int wn = 0; wn < 4; wn++) {
            ins4u(sv[wn][tid][0], rb0, rb1, rb2, rb3);
            ins4u(sv[wn][tid][1], rb0, rb1, rb2, rb3);
            ins4u(sv[wn][tid][2], rb0, rb1, rb2, rb3);
            ins4u(sv[wn][tid][3], rb0, rb1, rb2, rb3);
        }
        int gm = m0 + tid;
        g_cand[gm * 4 + 0] = (int)(rb0 & 0xFFFu);
        g_cand[gm * 4 + 1] = (int)(rb1 & 0xFFFu);
        g_cand[gm * 4 + 2] = (int)(rb2 & 0xFFFu);
        g_cand[gm * 4 + 3] = (int)(rb3 & 0xFFFu);
    }
}

// ===========================================================================
// Kernel 5: fused exact rescore (4 candidates) + rotation. One block per row.
// ===========================================================================
__global__ __launch_bounds__(128) void k_rescore_rot(const float* __restrict__ X,
                                                     float* __restrict__ outq,
                                                     float* __restrict__ out_idx_f) {
    __shared__ float xs[DD];
    __shared__ float cscore[4];
    __shared__ int   cidx[4];
    __shared__ float red[4][4];

    const int m = blockIdx.x;
    const int t = threadIdx.x;
    const int warp = t >> 5, lane = t & 31;
    const float* xr = X + (size_t)m * DD;

    float4 xv = ((const float4*)xr)[t];
    ((float4*)xs)[t] = xv;
    __syncthreads();

    {
        int ci = g_cand[m * 4 + warp];
        const float4* cr = (const float4*)(g_implicit + (size_t)ci * DD);
        float dot = 0.f;
#pragma unroll
        for (int t2 = 0; t2 < 4; t2++) {
            float4 cv = cr[lane + 32 * t2];
            float4 x4 = ((const float4*)xs)[lane + 32 * t2];
            dot += x4.x * cv.x + x4.y * cv.y + x4.z * cv.z + x4.w * cv.w;
        }
#pragma unroll
        for (int o = 16; o > 0; o >>= 1) dot += __shfl_xor_sync(0xffffffff, dot, o);
        if (lane == 0) {
            cscore[warp] = g_halfnorm[ci] - dot;
            cidx[warp] = ci;
        }
    }
    __syncthreads();

    float bv = cscore[0]; int bi = cidx[0];
#pragma unroll
    for (int k = 1; k < 4; k++) {
        float v = cscore[k]; int ci = cidx[k];
        if (v < bv || (v == bv && ci < bi)) { bv = v; bi = ci; }
    }
    if (t == 0) out_idx_f[m] = (float)bi;

    const float* qr = g_implicit + (size_t)bi * DD;
    float4 qv = ((const float4*)qr)[t];

    float sx  = xv.x * xv.x + xv.y * xv.y + xv.z * xv.z + xv.w * xv.w;
    float sq  = qv.x * qv.x + qv.y * qv.y + qv.z * qv.z + qv.w * qv.w;
    float sxq = xv.x * qv.x + xv.y * qv.y + xv.z * qv.z + xv.w * qv.w;
    float d0 = xv.x - qv.x + 1e-6f, d1 = xv.y - qv.y + 1e-6f;
    float d2 = xv.z - qv.z + 1e-6f, d3 = xv.w - qv.w + 1e-6f;
    float sc = d0 * d0 + d1 * d1 + d2 * d2 + d3 * d3;

#pragma unroll
    for (int o = 16; o > 0; o >>= 1) {
        sx  += __shfl_xor_sync(0xffffffff, sx, o);
        sq  += __shfl_xor_sync(0xffffffff, sq, o);
        sxq += __shfl_xor_sync(0xffffffff, sxq, o);
        sc  += __shfl_xor_sync(0xffffffff, sc, o);
    }
    if (lane == 0) { red[warp][0] = sx; red[warp][1] = sq; red[warp][2] = sxq; red[warp][3] = sc; }
    __syncthreads();
    sx  = red[0][0] + red[1][0] + red[2][0] + red[3][0];
    sq  = red[0][1] + red[1][1] + red[2][1] + red[3][1];
    sxq = red[0][2] + red[1][2] + red[2][2] + red[3][2];
    sc  = red[0][3] + red[1][3] + red[2][3] + red[3][3];

    if (t == 0) g_commit[m] = sc;

    float norm_x = sqrtf(sx), norm_q = sqrtf(sq);
    float nx = fmaxf(norm_x, 1e-6f);
    float nq = fmaxf(norm_q, 1e-6f);
    float uq2 = sx / (nx * nx) + sq / (nq * nq) + 2.f * sxq / (nx * nq);
    float nuq = sqrtf(fmaxf(uq2, 0.f));
    float wden = fmaxf(nuq, 1e-12f);
    float e_w = (sx / nx + sxq / nq) / wden;
    float e_u = sx / nx;
    float c1 = 2.f * e_w / wden;
    float c2 = 2.f * e_u;
    float scale = norm_q / nx;
    float coef_x = (1.f - c1 / nx) * scale;
    float coef_q = ((c2 - c1) / nq) * scale;

    float4 ov;
    ov.x = coef_x * xv.x + coef_q * qv.x;
    ov.y = coef_x * xv.y + coef_q * qv.y;
    ov.z = coef_x * xv.z + coef_q * qv.z;
    ov.w = coef_x * xv.w + coef_q * qv.w;
    ((float4*)(outq + (size_t)m * DD))[t] = ov;
}

// ===========================================================================
// Kernel 6: deterministic loss reduction
// ===========================================================================
__global__ __launch_bounds__(256) void k_loss(float* __restrict__ out_loss) {
    __shared__ float s[256];
    float v = 0.f;
    for (int i = threadIdx.x; i < MM; i += 256) v += g_commit[i];
    s[threadIdx.x] = v;
    __syncthreads();
    for (int o = 128; o > 0; o >>= 1) {
        if (threadIdx.x < o) s[threadIdx.x] += s[threadIdx.x + o];
        __syncthreads();
    }
    if (threadIdx.x == 0) out_loss[0] = s[0] / (float)MM;
}

// ===========================================================================
extern "C" void kernel_launch(void* const* d_in, const int* in_sizes, int n_in,
                              void* d_out, int out_size) {
    const float* x  = (const float*)d_in[0];
    const float* cb = (const float*)d_in[1];
    const float* Wm = (const float*)d_in[2];
    float* out = (float*)d_out;

    int idx_off  = out_size - MM - 1;
    int loss_off = out_size - 1;

    static bool attr_done = false;
    if (!attr_done) {
        cudaFuncSetAttribute(k_screen_mma, cudaFuncAttributeMaxDynamicSharedMemorySize, SMEM_DYN);
        cudaFuncSetAttribute(k_impl_mma, cudaFuncAttributeMaxDynamicSharedMemorySize, SMEM_IMPL);
        attr_done = true;
    }

    k_prep_all<<<(MM + CC + DD) / 8, 256>>>(x, cb, Wm);
    k_impl_mma<<<dim3(CC / 128, DD / 128), 256, SMEM_IMPL>>>();
    k_prep_c<<<CC / 8, 256>>>();
    k_screen_mma<<<MM / Bb_M, NTHR, SMEM_DYN>>>();
    k_rescore_rot<<<MM, 128>>>(x, out, out + idx_off);
    k_loss<<<1, 256>>>(out + loss_off);
}

// round 14
// speedup vs baseline: 3.5146x; 1.0006x over previous
#include <cuda_runtime.h>
#include <cuda_fp16.h>
#include <cstdint>

#define BB 8
#define NN 2048
#define DD 512
#define CC 4096
#define MM (BB*NN)   // 16384

// screen-kernel tiling: 64-row CTAs, 2 CTAs/SM
#define Bb_M 64
#define Bb_N 128
#define Bb_K 64                   // k-depth per B chunk
#define NCT (CC/Bb_N)             // 32 c-tiles
#define NKC (DD/Bb_K)             // 8 k-chunks per c-tile
#define NQ  (NCT*NKC)             // 256 chunks
#define ABLK_BYTES 8192           // one 64-k A block: 64 rows x 128B
#define A_BYTES  (8*ABLK_BYTES)   // resident A: 64 x 512 fp16 = 64KB
#define BSTAGE_BYTES 16384        // B stage: 128 rows x 128B (k=64)
#define SMEM_DYN (A_BYTES + 2*BSTAGE_BYTES)   // 96KB
#define NTHR 256

// implicit-GEMM smem: 2 stages x 4 tiles x 16KB
#define KB_BYTES 16384
#define SMEM_IMPL (2*4*KB_BYTES)  // 131072

// ---------------- scratch ----------------
__device__ float g_implicit[CC * DD];
__device__ float g_halfnorm[CC];
__device__ int   g_cand[MM * 4];
__device__ float g_commit[MM];
__device__ __half g_xh[MM * DD];
__device__ __half g_ch[CC * DD];
__device__ __half g_cbl0[CC * DD];
__device__ __half g_cbl1[CC * DD];
__device__ __half g_wl0[DD * DD];
__device__ __half g_wl1[DD * DD];

// =============================== helpers ===================================
__device__ __forceinline__ uint32_t smem_u32(const void* p) {
    return (uint32_t)__cvta_generic_to_shared(p);
}
__device__ __forceinline__ void cp16(uint32_t s, const void* g) {
    asm volatile("cp.async.cg.shared.global [%0], [%1], 16;" :: "r"(s), "l"(g));
}
#define CP_COMMIT() asm volatile("cp.async.commit_group;")
#define CP_WAIT1()  asm volatile("cp.async.wait_group 1;")
#define LDM4(r0,r1,r2,r3,addr) \
    asm volatile("ldmatrix.sync.aligned.m8n8.x4.shared.b16 {%0,%1,%2,%3},[%4];" \
                 : "=r"(r0),"=r"(r1),"=r"(r2),"=r"(r3) : "r"(addr))
#define MMA16816(c,a,b) \
    asm volatile("mma.sync.aligned.m16n8k16.row.col.f32.f16.f16.f32 " \
                 "{%0,%1,%2,%3},{%4,%5,%6,%7},{%8,%9},{%0,%1,%2,%3};" \
                 : "+f"((c)[0]),"+f"((c)[1]),"+f"((c)[2]),"+f"((c)[3]) \
                 : "r"((a)[0]),"r"((a)[1]),"r"((a)[2]),"r"((a)[3]), \
                   "r"((b)[0]),"r"((b)[1]))

__device__ __forceinline__ uint32_t fkey(float f) {
    uint32_t u = __float_as_uint(f);
    uint32_t m = (u & 0x80000000u) ? 0xFFFFFFFFu : 0x80000000u;
    return u ^ m;
}
__device__ __forceinline__ void ins2u(uint32_t v, uint32_t& b0, uint32_t& b1) {
    uint32_t m0 = max(b0, v);
    b0 = min(b0, v);
    b1 = min(b1, m0);
}
__device__ __forceinline__ void ins4u(uint32_t v, uint32_t& b0, uint32_t& b1,
                                      uint32_t& b2, uint32_t& b3) {
    uint32_t m0 = max(b0, v); b0 = min(b0, v);
    uint32_t m1 = max(b1, m0); b1 = min(b1, m0);
    uint32_t m2 = max(b2, m1); b2 = min(b2, m1);
    b3 = min(b3, m2);
}

// ===========================================================================
// Kernel 1: k_prep_all — one warp per row.
// ===========================================================================
__global__ __launch_bounds__(256) void k_prep_all(const float* __restrict__ x,
                                                  const float* __restrict__ cb,
                                                  const float* __restrict__ Wm) {
    const int warp = threadIdx.x >> 5, lane = threadIdx.x & 31;
    const int row = blockIdx.x * 8 + warp;

    if (row < MM) {
        const float4* sr = (const float4*)(x + (size_t)row * DD);
        __half* d = g_xh + (size_t)row * DD;
#pragma unroll
        for (int t = 0; t < 4; t++) {
            float4 v = sr[lane + 32 * t];
            __half L[4] = {__float2half_rn(v.x), __float2half_rn(v.y),
                           __float2half_rn(v.z), __float2half_rn(v.w)};
            *(uint2*)(d + 4 * (lane + 32 * t)) = *(uint2*)L;
        }
    } else {
        const float* src;
        __half *d0, *d1;
        if (row < MM + CC) {
            int r = row - MM;
            src = cb + (size_t)r * DD;
            d0 = g_cbl0 + (size_t)r * DD;
            d1 = g_cbl1 + (size_t)r * DD;
        } else {
            int r = row - MM - CC;
            src = Wm + (size_t)r * DD;
            d0 = g_wl0 + (size_t)r * DD;
            d1 = g_wl1 + (size_t)r * DD;
        }
        const float4* sr = (const float4*)src;
#pragma unroll
        for (int t = 0; t < 4; t++) {
            float4 v = sr[lane + 32 * t];
            float vv[4] = {v.x, v.y, v.z, v.w};
            __half L0[4], L1[4];
#pragma unroll
            for (int c = 0; c < 4; c++) {
                __half h0 = __float2half_rn(vv[c]);
                float r2 = vv[c] - __half2float(h0);
                L0[c] = h0;
                L1[c] = __float2half_rn(r2);
            }
            *(uint2*)(d0 + 4 * (lane + 32 * t)) = *(uint2*)L0;
            *(uint2*)(d1 + 4 * (lane + 32 * t)) = *(uint2*)L1;
        }
    }
}

// ===========================================================================
// Kernel 2: implicit = codebook @ W^T via fp16 2-limb 3-product HMMA.
// ===========================================================================
__device__ __forceinline__ void issue_impl(uint32_t st, int m0, int n0, int kc, int tid) {
#pragma unroll
    for (int t = 0; t < 16; t++) {
        const int tile = t >> 2;
        const int r = (t & 3) * 32 + (tid >> 3);
        const int seg = tid & 7;
        const __half* src;
        if (tile == 0)      src = g_cbl0 + (size_t)(m0 + r) * DD;
        else if (tile == 1) src = g_cbl1 + (size_t)(m0 + r) * DD;
        else if (tile == 2) src = g_wl0 + (size_t)(n0 + r) * DD;
        else                src = g_wl1 + (size_t)(n0 + r) * DD;
        cp16(st + tile * KB_BYTES + r * 128 + ((seg ^ (r & 7)) << 4),
             src + kc * 64 + seg * 8);
    }
}

__global__ __launch_bounds__(256, 1) void k_impl_mma() {
    extern __shared__ char dsm[];
    const uint32_t sb = smem_u32(dsm);
    const int tid = threadIdx.x;
    const int lane = tid & 31;
    const int wid = tid >> 5;
    const int warp_m = wid >> 2;
    const int warp_n = wid & 3;
    const int m0 = blockIdx.x * 128;
    const int n0 = blockIdx.y * 128;
    const int gID = lane >> 2;
    const int tg  = lane & 3;

    const uint32_t aRow = (uint32_t)(warp_m * 64 + (lane & 15)) * 128;
    const uint32_t bRow = (uint32_t)(warp_n * 32 + ((lane >> 4) & 1) * 8 + (lane & 7)) * 128;
    const int lxor = lane & 7;

    float acc[4][4][4];
#pragma unroll
    for (int mt = 0; mt < 4; mt++)
#pragma unroll
        for (int nt = 0; nt < 4; nt++)
#pragma unroll
            for (int e = 0; e < 4; e++) acc[mt][nt][e] = 0.f;

    issue_impl(sb + 0 * (4 * KB_BYTES), m0, n0, 0, tid); CP_COMMIT();
    issue_impl(sb + 1 * (4 * KB_BYTES), m0, n0, 1, tid); CP_COMMIT();

    for (int kc = 0; kc < 8; kc++) {
        CP_WAIT1();
        __syncthreads();

        const uint32_t st = sb + (kc & 1) * (4 * KB_BYTES);
#pragma unroll
        for (int ks = 0; ks < 4; ks++) {
            const uint32_t aSw = (uint32_t)(((ks * 2 + (lane >> 4)) ^ lxor) << 4);
            const uint32_t bSw = (uint32_t)(((ks * 2 + ((lane >> 3) & 1)) ^ lxor) << 4);
            uint32_t aF[4][4], b0F[4][2], b1F[4][2];
#pragma unroll
            for (int mt = 0; mt < 4; mt++)
                LDM4(aF[mt][0], aF[mt][1], aF[mt][2], aF[mt][3],
                     st + 0 * KB_BYTES + aRow + mt * (16 * 128) + aSw);
#pragma unroll
            for (int p = 0; p < 2; p++) {
                uint32_t r0, r1, r2, r3;
                LDM4(r0, r1, r2, r3, st + 2 * KB_BYTES + bRow + p * (16 * 128) + bSw);
                b0F[2 * p][0] = r0; b0F[2 * p][1] = r1;
                b0F[2 * p + 1][0] = r2; b0F[2 * p + 1][1] = r3;
            }
#pragma unroll
            for (int mt = 0; mt < 4; mt++)
#pragma unroll
                for (int nt = 0; nt < 4; nt++) MMA16816(acc[mt][nt], aF[mt], b0F[nt]);
#pragma unroll
            for (int p = 0; p < 2; p++) {
                uint32_t r0, r1, r2, r3;
                LDM4(r0, r1, r2, r3, st + 3 * KB_BYTES + bRow + p * (16 * 128) + bSw);
                b1F[2 * p][0] = r0; b1F[2 * p][1] = r1;
                b1F[2 * p + 1][0] = r2; b1F[2 * p + 1][1] = r3;
            }
#pragma unroll
            for (int mt = 0; mt < 4; mt++)
#pragma unroll
                for (int nt = 0; nt < 4; nt++) MMA16816(acc[mt][nt], aF[mt], b1F[nt]);
#pragma unroll
            for (int mt = 0; mt < 4; mt++)
                LDM4(aF[mt][0], aF[mt][1], aF[mt][2], aF[mt][3],
                     st + 1 * KB_BYTES + aRow + mt * (16 * 128) + aSw);
#pragma unroll
            for (int mt = 0; mt < 4; mt++)
#pragma unroll
                for (int nt = 0; nt < 4; nt++) MMA16816(acc[mt][nt], aF[mt], b0F[nt]);
        }

        __syncthreads();
        const int kn = kc + 2;
        if (kn < 8)
            issue_impl(sb + (kn & 1) * (4 * KB_BYTES), m0, n0, kn, tid);
        CP_COMMIT();
    }

#pragma unroll
    for (int mt = 0; mt < 4; mt++) {
#pragma unroll
        for (int half = 0; half < 2; half++) {
            int row = m0 + warp_m * 64 + mt * 16 + gID + 8 * half;
#pragma unroll
            for (int nt = 0; nt < 4; nt++) {
                int col = n0 + warp_n * 32 + nt * 8 + tg * 2;
                float2 v = make_float2(acc[mt][nt][2 * half + 0],
                                       acc[mt][nt][2 * half + 1]);
                *(float2*)&g_implicit[(size_t)row * DD + col] = v;
            }
        }
    }
}

// ===========================================================================
// Kernel 3: k_prep_c — implicit row -> fp16 g_ch + halfnorm. One warp/row.
// ===========================================================================
__global__ __launch_bounds__(256) void k_prep_c() {
    const int warp = threadIdx.x >> 5, lane = threadIdx.x & 31;
    const int row = blockIdx.x * 8 + warp;
    const float4* sr = (const float4*)(g_implicit + (size_t)row * DD);
    __half* d = g_ch + (size_t)row * DD;
    float s = 0.f;
#pragma unroll
    for (int t = 0; t < 4; t++) {
        float4 v = sr[lane + 32 * t];
        s += v.x * v.x + v.y * v.y + v.z * v.z + v.w * v.w;
        __half L[4] = {__float2half_rn(v.x), __float2half_rn(v.y),
                       __float2half_rn(v.z), __float2half_rn(v.w)};
        *(uint2*)(d + 4 * (lane + 32 * t)) = *(uint2*)L;
    }
#pragma unroll
    for (int o = 16; o > 0; o >>= 1) s += __shfl_xor_sync(0xffffffff, s, o);
    if (lane == 0) g_halfnorm[row] = 0.5f * s;
}

// ===========================================================================
// Kernel 4: HMMA screening GEMM, Bb_M=64, 256 thr, 2 CTAs/SM.
// Per-thread running top-2; single merge at end.
// ===========================================================================
__device__ __forceinline__ void issue_b(uint32_t st, int ct, int kc, int tid) {
#pragma unroll
    for (int j = 0; j < 4; j++) {
        int idx = j * NTHR + tid;          // 0..1023
        int r = idx >> 3, seg = idx & 7;
        const __half* g = g_ch + (size_t)(ct * Bb_N + r) * DD + kc * Bb_K + seg * 8;
        cp16(st + r * 128 + (((seg ^ (r & 7))) << 4), g);
    }
}

__global__ __launch_bounds__(NTHR, 2) void k_screen_mma() {
    extern __shared__ char dsm[];
    __shared__ uint32_t sv[4][64][4];

    const uint32_t sa = smem_u32(dsm);            // A resident, 64KB
    const uint32_t sbB = sa + A_BYTES;            // B stages (2 x 16KB)
    const int tid = threadIdx.x;
    const int lane = tid & 31;
    const int wid = tid >> 5;
    const int warp_m = wid >> 2;      // 0..1  (32 rows each)
    const int warp_n = wid & 3;       // 0..3  (32 cols each)
    const int m0 = blockIdx.x * Bb_M;
    const int gID = lane >> 2;
    const int tg  = lane & 3;

    const uint32_t aRow = (uint32_t)(warp_m * 32 + (lane & 15)) * 128;
    const uint32_t bRow = (uint32_t)(warp_n * 32 + ((lane >> 4) & 1) * 8 + (lane & 7)) * 128;
    const int lxor = lane & 7;

    uint32_t t2[2][2][2];
#pragma unroll
    for (int mt = 0; mt < 2; mt++)
#pragma unroll
        for (int h = 0; h < 2; h++) { t2[mt][h][0] = 0xFFFFFFFFu; t2[mt][h][1] = 0xFFFFFFFFu; }

    float acc[2][4][4];

    // prologue: resident A (4096 segs of 16B) with chunk0's group
#pragma unroll
    for (int t = 0; t < 16; t++) {
        int idx = t * NTHR + tid;          // 0..4095
        int row = idx >> 6, s = idx & 63;
        int kb = s >> 3, seg = s & 7;
        const __half* g = g_xh + (size_t)(m0 + row) * DD + kb * 64 + seg * 8;
        cp16(sa + kb * ABLK_BYTES + row * 128 + ((seg ^ (row & 7)) << 4), g);
    }
    issue_b(sbB + 0 * BSTAGE_BYTES, 0, 0, tid); CP_COMMIT();
    issue_b(sbB + 1 * BSTAGE_BYTES, 0, 1, tid); CP_COMMIT();

    for (int q = 0; q < NQ; q++) {
        const int ct = q >> 3;
        const int kc = q & 7;

        CP_WAIT1();
        __syncthreads();

        if (kc == 0) {
#pragma unroll
            for (int mt = 0; mt < 2; mt++)
#pragma unroll
                for (int nt = 0; nt < 4; nt++)
#pragma unroll
                    for (int e = 0; e < 4; e++) acc[mt][nt][e] = 0.f;
        }

        const uint32_t aBase = sa + kc * ABLK_BYTES;
        const uint32_t bBase = sbB + (q & 1) * BSTAGE_BYTES;
#pragma unroll
        for (int ks = 0; ks < 4; ks++) {
            const uint32_t aSw = (uint32_t)(((ks * 2 + (lane >> 4)) ^ lxor) << 4);
            const uint32_t bSw = (uint32_t)(((ks * 2 + ((lane >> 3) & 1)) ^ lxor) << 4);
            uint32_t aF[2][4], bF[4][2];
#pragma unroll
            for (int mt = 0; mt < 2; mt++)
                LDM4(aF[mt][0], aF[mt][1], aF[mt][2], aF[mt][3],
                     aBase + aRow + mt * (16 * 128) + aSw);
#pragma unroll
            for (int p = 0; p < 2; p++) {
                uint32_t r0, r1, r2, r3;
                LDM4(r0, r1, r2, r3, bBase + bRow + p * (16 * 128) + bSw);
                bF[2 * p][0] = r0; bF[2 * p][1] = r1;
                bF[2 * p + 1][0] = r2; bF[2 * p + 1][1] = r3;
            }
#pragma unroll
            for (int mt = 0; mt < 2; mt++)
#pragma unroll
                for (int nt = 0; nt < 4; nt++) MMA16816(acc[mt][nt], aF[mt], bF[nt]);
        }

        if (kc == 7) {
            float2 hn[4];
#pragma unroll
            for (int nt = 0; nt < 4; nt++)
                hn[nt] = *(const float2*)&g_halfnorm[ct * Bb_N + warp_n * 32 + nt * 8 + tg * 2];

#pragma unroll
            for (int mt = 0; mt < 2; mt++) {
#pragma unroll
                for (int half = 0; half < 2; half++) {
#pragma unroll
                    for (int nt = 0; nt < 4; nt++) {
                        int cbase = ct * Bb_N + warp_n * 32 + nt * 8 + tg * 2;
                        float s0 = hn[nt].x - acc[mt][nt][2 * half + 0];
                        float s1 = hn[nt].y - acc[mt][nt][2 * half + 1];
                        ins2u((fkey(s0) & 0xFFFFF000u) | (uint32_t)cbase,
                              t2[mt][half][0], t2[mt][half][1]);
                        ins2u((fkey(s1) & 0xFFFFF000u) | (uint32_t)(cbase + 1),
                              t2[mt][half][0], t2[mt][half][1]);
                    }
                }
            }
        }

        __syncthreads();
        const int qn = q + 2;
        if (qn < NQ)
            issue_b(sbB + (qn & 1) * BSTAGE_BYTES, qn >> 3, qn & 7, tid);
        CP_COMMIT();
    }

    // ---- one-time merge ----
#pragma unroll
    for (int mt = 0; mt < 2; mt++) {
#pragma unroll
        for (int half = 0; half < 2; half++) {
            uint32_t b0 = t2[mt][half][0], b1 = t2[mt][half][1];
            uint32_t b2 = 0xFFFFFFFFu, b3 = 0xFFFFFFFFu;
#pragma unroll
            for (int off = 1; off <= 2; off <<= 1) {
                uint32_t o0 = __shfl_xor_sync(0xffffffff, b0, off);
                uint32_t o1 = __shfl_xor_sync(0xffffffff, b1, off);
                uint32_t o2 = __shfl_xor_sync(0xffffffff, b2, off);
                uint32_t o3 = __shfl_xor_sync(0xffffffff, b3, off);
                ins4u(o0, b0, b1, b2, b3);
                ins4u(o1, b0, b1, b2, b3);
                ins4u(o2, b0, b1, b2, b3);
                ins4u(o3, b0, b1, b2, b3);
            }
            if (tg == 0) {
                int r = warp_m * 32 + mt * 16 + gID + 8 * half;
                sv[warp_n][r][0] = b0; sv[warp_n][r][1] = b1;
                sv[warp_n][r][2] = b2; sv[warp_n][r][3] = b3;
            }
        }
    }
    __syncthreads();
    if (tid < 64) {
        uint32_t rb0 = 0xFFFFFFFFu, rb1 = 0xFFFFFFFFu, rb2 = 0xFFFFFFFFu, rb3 = 0xFFFFFFFFu;
#pragma unroll
        for (int wn = 0; wn < 4; wn++) {
            ins4u(sv[wn][tid][0], rb0, rb1, rb2, rb3);
            ins4u(sv[wn][tid][1], rb0, rb1, rb2, rb3);
            ins4u(sv[wn][tid][2], rb0, rb1, rb2, rb3);
            ins4u(sv[wn][tid][3], rb0, rb1, rb2, rb3);
        }
        int gm = m0 + tid;
        g_cand[gm * 4 + 0] = (int)(rb0 & 0xFFFu);
        g_cand[gm * 4 + 1] = (int)(rb1 & 0xFFFu);
        g_cand[gm * 4 + 2] = (int)(rb2 & 0xFFFu);
        g_cand[gm * 4 + 3] = (int)(rb3 & 0xFFFu);
    }
}

// ===========================================================================
// Kernel 5: fused exact rescore (4 candidates) + rotation. One block per row.
// ===========================================================================
__global__ __launch_bounds__(128) void k_rescore_rot(const float* __restrict__ X,
                                                     float* __restrict__ outq,
                                                     float* __restrict__ out_idx_f) {
    __shared__ float xs[DD];
    __shared__ float cscore[4];
    __shared__ int   cidx[4];
    __shared__ float red[4][4];

    const int m = blockIdx.x;
    const int t = threadIdx.x;
    const int warp = t >> 5, lane = t & 31;
    const float* xr = X + (size_t)m * DD;

    float4 xv = ((const float4*)xr)[t];
    ((float4*)xs)[t] = xv;
    __syncthreads();

    {
        int ci = g_cand[m * 4 + warp];
        const float4* cr = (const float4*)(g_implicit + (size_t)ci * DD);
        float dot = 0.f;
#pragma unroll
        for (int t2 = 0; t2 < 4; t2++) {
            float4 cv = cr[lane + 32 * t2];
            float4 x4 = ((const float4*)xs)[lane + 32 * t2];
            dot += x4.x * cv.x + x4.y * cv.y + x4.z * cv.z + x4.w * cv.w;
        }
#pragma unroll
        for (int o = 16; o > 0; o >>= 1) dot += __shfl_xor_sync(0xffffffff, dot, o);
        if (lane == 0) {
            cscore[warp] = g_halfnorm[ci] - dot;
            cidx[warp] = ci;
        }
    }
    __syncthreads();

    float bv = cscore[0]; int bi = cidx[0];
#pragma unroll
    for (int k = 1; k < 4; k++) {
        float v = cscore[k]; int ci = cidx[k];
        if (v < bv || (v == bv && ci < bi)) { bv = v; bi = ci; }
    }
    if (t == 0) out_idx_f[m] = (float)bi;

    const float* qr = g_implicit + (size_t)bi * DD;
    float4 qv = ((const float4*)qr)[t];

    float sx  = xv.x * xv.x + xv.y * xv.y + xv.z * xv.z + xv.w * xv.w;
    float sq  = qv.x * qv.x + qv.y * qv.y + qv.z * qv.z + qv.w * qv.w;
    float sxq = xv.x * qv.x + xv.y * qv.y + xv.z * qv.z + xv.w * qv.w;
    float d0 = xv.x - qv.x + 1e-6f, d1 = xv.y - qv.y + 1e-6f;
    float d2 = xv.z - qv.z + 1e-6f, d3 = xv.w - qv.w + 1e-6f;
    float sc = d0 * d0 + d1 * d1 + d2 * d2 + d3 * d3;

#pragma unroll
    for (int o = 16; o > 0; o >>= 1) {
        sx  += __shfl_xor_sync(0xffffffff, sx, o);
        sq  += __shfl_xor_sync(0xffffffff, sq, o);
        sxq += __shfl_xor_sync(0xffffffff, sxq, o);
        sc  += __shfl_xor_sync(0xffffffff, sc, o);
    }
    if (lane == 0) { red[warp][0] = sx; red[warp][1] = sq; red[warp][2] = sxq; red[warp][3] = sc; }
    __syncthreads();
    sx  = red[0][0] + red[1][0] + red[2][0] + red[3][0];
    sq  = red[0][1] + red[1][1] + red[2][1] + red[3][1];
    sxq = red[0][2] + red[1][2] + red[2][2] + red[3][2];
    sc  = red[0][3] + red[1][3] + red[2][3] + red[3][3];

    if (t == 0) g_commit[m] = sc;

    float norm_x = sqrtf(sx), norm_q = sqrtf(sq);
    float nx = fmaxf(norm_x, 1e-6f);
    float nq = fmaxf(norm_q, 1e-6f);
    float uq2 = sx / (nx * nx) + sq / (nq * nq) + 2.f * sxq / (nx * nq);
    float nuq = sqrtf(fmaxf(uq2, 0.f));
    float wden = fmaxf(nuq, 1e-12f);
    float e_w = (sx / nx + sxq / nq) / wden;
    float e_u = sx / nx;
    float c1 = 2.f * e_w / wden;
    float c2 = 2.f * e_u;
    float scale = norm_q / nx;
    float coef_x = (1.f - c1 / nx) * scale;
    float coef_q = ((c2 - c1) / nq) * scale;

    float4 ov;
    ov.x = coef_x * xv.x + coef_q * qv.x;
    ov.y = coef_x * xv.y + coef_q * qv.y;
    ov.z = coef_x * xv.z + coef_q * qv.z;
    ov.w = coef_x * xv.w + coef_q * qv.w;
    ((float4*)(outq + (size_t)m * DD))[t] = ov;
}

// ===========================================================================
// Kernel 6: deterministic loss reduction
// ===========================================================================
__global__ __launch_bounds__(256) void k_loss(float* __restrict__ out_loss) {
    __shared__ float s[256];
    float v = 0.f;
    for (int i = threadIdx.x; i < MM; i += 256) v += g_commit[i];
    s[threadIdx.x] = v;
    __syncthreads();
    for (int o = 128; o > 0; o >>= 1) {
        if (threadIdx.x < o) s[threadIdx.x] += s[threadIdx.x + o];
        __syncthreads();
    }
    if (threadIdx.x == 0) out_loss[0] = s[0] / (float)MM;
}

// ===========================================================================
extern "C" void kernel_launch(void* const* d_in, const int* in_sizes, int n_in,
                              void* d_out, int out_size) {
    const float* x  = (const float*)d_in[0];
    const float* cb = (const float*)d_in[1];
    const float* Wm = (const float*)d_in[2];
    float* out = (float*)d_out;

    int idx_off  = out_size - MM - 1;
    int loss_off = out_size - 1;

    static bool attr_done = false;
    if (!attr_done) {
        cudaFuncSetAttribute(k_screen_mma, cudaFuncAttributeMaxDynamicSharedMemorySize, SMEM_DYN);
        cudaFuncSetAttribute(k_impl_mma, cudaFuncAttributeMaxDynamicSharedMemorySize, SMEM_IMPL);
        attr_done = true;
    }

    k_prep_all<<<(MM + CC + DD) / 8, 256>>>(x, cb, Wm);
    k_impl_mma<<<dim3(CC / 128, DD / 128), 256, SMEM_IMPL>>>();
    k_prep_c<<<CC / 8, 256>>>();
    k_screen_mma<<<MM / Bb_M, NTHR, SMEM_DYN>>>();
    k_rescore_rot<<<MM, 128>>>(x, out, out + idx_off);
    k_loss<<<1, 256>>>(out + loss_off);
}

// round 15
// speedup vs baseline: 3.6530x; 1.0394x over previous
#include <cuda_runtime.h>
#include <cuda_fp16.h>
#include <cstdint>

#define BB 8
#define NN 2048
#define DD 512
#define CC 4096
#define MM (BB*NN)   // 16384

// screen-kernel tiling (R13 topology)
#define Bb_M 128
#define Bb_N 128
#define Bb_K 128                  // k-depth per B chunk (2 x 64-k blocks)
#define NCT (CC/Bb_N)             // 32 c-tiles
#define NKC (DD/Bb_K)             // 4 k-chunks per c-tile
#define NQ  (NCT*NKC)             // 128 chunks
#define KB_BYTES 16384            // one 64-k block: 128 rows x 128B
#define BSTAGE_BYTES (2*KB_BYTES) // 32KB B chunk (k=128)
#define A_BYTES  (8*KB_BYTES)     // resident A: 128 x 512 fp16 = 128KB
#define SMEM_DYN (A_BYTES + 2*BSTAGE_BYTES)   // 192KB
#define NTHR 512

// implicit-GEMM smem: 2 stages x 4 tiles x 16KB
#define SMEM_IMPL (2*4*KB_BYTES)  // 131072

// ---------------- scratch ----------------
__device__ float g_implicit[CC * DD];
__device__ float g_halfnorm[CC];
__device__ int   g_cand[MM * 4];
__device__ float g_commit[MM];
// pre-swizzled, chunk-contiguous fp16 images for bulk-copy
__device__ __align__(16) char g_xh_sw[(size_t)MM * DD * 2];  // [mtile][kb][row][seg^]
__device__ __align__(16) char g_ch_sw[(size_t)CC * DD * 2];  // [chunk][kb2][row][seg^]
__device__ __half g_cbl0[CC * DD];
__device__ __half g_cbl1[CC * DD];
__device__ __half g_wl0[DD * DD];
__device__ __half g_wl1[DD * DD];

// =============================== helpers ===================================
__device__ __forceinline__ uint32_t smem_u32(const void* p) {
    return (uint32_t)__cvta_generic_to_shared(p);
}
__device__ __forceinline__ void cp16(uint32_t s, const void* g) {
    asm volatile("cp.async.cg.shared.global [%0], [%1], 16;" :: "r"(s), "l"(g));
}
#define CP_COMMIT() asm volatile("cp.async.commit_group;")
#define CP_WAIT1()  asm volatile("cp.async.wait_group 1;")
#define LDM4(r0,r1,r2,r3,addr) \
    asm volatile("ldmatrix.sync.aligned.m8n8.x4.shared.b16 {%0,%1,%2,%3},[%4];" \
                 : "=r"(r0),"=r"(r1),"=r"(r2),"=r"(r3) : "r"(addr))
#define MMA16816(c,a,b) \
    asm volatile("mma.sync.aligned.m16n8k16.row.col.f32.f16.f16.f32 " \
                 "{%0,%1,%2,%3},{%4,%5,%6,%7},{%8,%9},{%0,%1,%2,%3};" \
                 : "+f"((c)[0]),"+f"((c)[1]),"+f"((c)[2]),"+f"((c)[3]) \
                 : "r"((a)[0]),"r"((a)[1]),"r"((a)[2]),"r"((a)[3]), \
                   "r"((b)[0]),"r"((b)[1]))

// mbarrier ops (sm_90-baseline; compiled fine in R3)
__device__ __forceinline__ void mbar_init(uint32_t a, uint32_t cnt) {
    asm volatile("mbarrier.init.shared.b64 [%0], %1;" :: "r"(a), "r"(cnt) : "memory");
}
__device__ __forceinline__ void mbar_expect_tx(uint32_t a, uint32_t bytes) {
    asm volatile("mbarrier.arrive.expect_tx.shared.b64 _, [%0], %1;" :: "r"(a), "r"(bytes) : "memory");
}
__device__ __forceinline__ void mbar_wait(uint32_t a, uint32_t phase) {
    uint32_t done;
    asm volatile("{\n\t.reg .pred p;\n\t"
                 "mbarrier.try_wait.parity.acquire.cta.shared::cta.b64 p, [%1], %2;\n\t"
                 "selp.b32 %0, 1, 0, p;\n\t}"
                 : "=r"(done) : "r"(a), "r"(phase) : "memory");
    if (!done) {
        asm volatile("{\n\t.reg .pred P1;\n\t"
                     "W_%=:\n\t"
                     "mbarrier.try_wait.parity.acquire.cta.shared::cta.b64 P1, [%0], %1, 0x989680;\n\t"
                     "@P1 bra.uni D_%=;\n\t"
                     "bra.uni W_%=;\n\t"
                     "D_%=:\n\t}"
                     :: "r"(a), "r"(phase) : "memory");
    }
}
__device__ __forceinline__ void bulk_copy(uint32_t dst, const void* src,
                                          uint32_t bytes, uint32_t mbar) {
    asm volatile("cp.async.bulk.shared::cta.global.mbarrier::complete_tx::bytes "
                 "[%0], [%1], %2, [%3];"
                 :: "r"(dst), "l"(src), "r"(bytes), "r"(mbar) : "memory");
}

__device__ __forceinline__ uint32_t fkey(float f) {
    uint32_t u = __float_as_uint(f);
    uint32_t m = (u & 0x80000000u) ? 0xFFFFFFFFu : 0x80000000u;
    return u ^ m;
}
__device__ __forceinline__ void ins2u(uint32_t v, uint32_t& b0, uint32_t& b1) {
    uint32_t m0 = max(b0, v);
    b0 = min(b0, v);
    b1 = min(b1, m0);
}
__device__ __forceinline__ void ins4u(uint32_t v, uint32_t& b0, uint32_t& b1,
                                      uint32_t& b2, uint32_t& b3) {
    uint32_t m0 = max(b0, v); b0 = min(b0, v);
    uint32_t m1 = max(b1, m0); b1 = min(b1, m0);
    uint32_t m2 = max(b2, m1); b2 = min(b2, m1);
    b3 = min(b3, m2);
}

// ===========================================================================
// Kernel 1: k_prep_all — one warp per row.
//   rows [0, MM):            x row -> g_xh_sw (fp16, pre-swizzled chunks)
//   rows [MM, MM+CC):        codebook -> g_cbl0/1 limbs
//   rows [MM+CC, MM+CC+DD):  W -> g_wl0/1 limbs
// ===========================================================================
__global__ __launch_bounds__(256) void k_prep_all(const float* __restrict__ x,
                                                  const float* __restrict__ cb,
                                                  const float* __restrict__ Wm) {
    const int warp = threadIdx.x >> 5, lane = threadIdx.x & 31;
    const int row = blockIdx.x * 8 + warp;

    if (row < MM) {
        const int mtile = row >> 7, lrow = row & 127;
        const float4* sr = (const float4*)(x + (size_t)row * DD);
        char* dbase = g_xh_sw + (size_t)mtile * A_BYTES;
#pragma unroll
        for (int it = 0; it < 2; it++) {
            int g16 = lane + 32 * it;          // 0..63 (16B units along k)
            int kb = g16 >> 3, seg8 = g16 & 7;
            float4 v0 = sr[g16 * 2 + 0];
            float4 v1 = sr[g16 * 2 + 1];
            __half L[8] = {__float2half_rn(v0.x), __float2half_rn(v0.y),
                           __float2half_rn(v0.z), __float2half_rn(v0.w),
                           __float2half_rn(v1.x), __float2half_rn(v1.y),
                           __float2half_rn(v1.z), __float2half_rn(v1.w)};
            size_t off = (size_t)kb * KB_BYTES + lrow * 128 + ((seg8 ^ (lrow & 7)) << 4);
            *(uint4*)(dbase + off) = *(uint4*)L;
        }
    } else {
        const float* src;
        __half *d0, *d1;
        if (row < MM + CC) {
            int r = row - MM;
            src = cb + (size_t)r * DD;
            d0 = g_cbl0 + (size_t)r * DD;
            d1 = g_cbl1 + (size_t)r * DD;
        } else {
            int r = row - MM - CC;
            src = Wm + (size_t)r * DD;
            d0 = g_wl0 + (size_t)r * DD;
            d1 = g_wl1 + (size_t)r * DD;
        }
        const float4* sr = (const float4*)src;
#pragma unroll
        for (int t = 0; t < 4; t++) {
            float4 v = sr[lane + 32 * t];
            float vv[4] = {v.x, v.y, v.z, v.w};
            __half L0[4], L1[4];
#pragma unroll
            for (int c = 0; c < 4; c++) {
                __half h0 = __float2half_rn(vv[c]);
                float r2 = vv[c] - __half2float(h0);
                L0[c] = h0;
                L1[c] = __float2half_rn(r2);
            }
            *(uint2*)(d0 + 4 * (lane + 32 * t)) = *(uint2*)L0;
            *(uint2*)(d1 + 4 * (lane + 32 * t)) = *(uint2*)L1;
        }
    }
}

// ===========================================================================
// Kernel 2: implicit = codebook @ W^T via fp16 2-limb 3-product HMMA.
// (unchanged from R13)
// ===========================================================================
__device__ __forceinline__ void issue_impl(uint32_t st, int m0, int n0, int kc, int tid) {
#pragma unroll
    for (int t = 0; t < 16; t++) {
        const int tile = t >> 2;
        const int r = (t & 3) * 32 + (tid >> 3);
        const int seg = tid & 7;
        const __half* src;
        if (tile == 0)      src = g_cbl0 + (size_t)(m0 + r) * DD;
        else if (tile == 1) src = g_cbl1 + (size_t)(m0 + r) * DD;
        else if (tile == 2) src = g_wl0 + (size_t)(n0 + r) * DD;
        else                src = g_wl1 + (size_t)(n0 + r) * DD;
        cp16(st + tile * KB_BYTES + r * 128 + ((seg ^ (r & 7)) << 4),
             src + kc * 64 + seg * 8);
    }
}

__global__ __launch_bounds__(256, 1) void k_impl_mma() {
    extern __shared__ char dsm[];
    const uint32_t sb = smem_u32(dsm);
    const int tid = threadIdx.x;
    const int lane = tid & 31;
    const int wid = tid >> 5;
    const int warp_m = wid >> 2;
    const int warp_n = wid & 3;
    const int m0 = blockIdx.x * 128;
    const int n0 = blockIdx.y * 128;
    const int gID = lane >> 2;
    const int tg  = lane & 3;

    const uint32_t aRow = (uint32_t)(warp_m * 64 + (lane & 15)) * 128;
    const uint32_t bRow = (uint32_t)(warp_n * 32 + ((lane >> 4) & 1) * 8 + (lane & 7)) * 128;
    const int lxor = lane & 7;

    float acc[4][4][4];
#pragma unroll
    for (int mt = 0; mt < 4; mt++)
#pragma unroll
        for (int nt = 0; nt < 4; nt++)
#pragma unroll
            for (int e = 0; e < 4; e++) acc[mt][nt][e] = 0.f;

    issue_impl(sb + 0 * (4 * KB_BYTES), m0, n0, 0, tid); CP_COMMIT();
    issue_impl(sb + 1 * (4 * KB_BYTES), m0, n0, 1, tid); CP_COMMIT();

    for (int kc = 0; kc < 8; kc++) {
        CP_WAIT1();
        __syncthreads();

        const uint32_t st = sb + (kc & 1) * (4 * KB_BYTES);
#pragma unroll
        for (int ks = 0; ks < 4; ks++) {
            const uint32_t aSw = (uint32_t)(((ks * 2 + (lane >> 4)) ^ lxor) << 4);
            const uint32_t bSw = (uint32_t)(((ks * 2 + ((lane >> 3) & 1)) ^ lxor) << 4);
            uint32_t aF[4][4], b0F[4][2], b1F[4][2];
#pragma unroll
            for (int mt = 0; mt < 4; mt++)
                LDM4(aF[mt][0], aF[mt][1], aF[mt][2], aF[mt][3],
                     st + 0 * KB_BYTES + aRow + mt * (16 * 128) + aSw);
#pragma unroll
            for (int p = 0; p < 2; p++) {
                uint32_t r0, r1, r2, r3;
                LDM4(r0, r1, r2, r3, st + 2 * KB_BYTES + bRow + p * (16 * 128) + bSw);
                b0F[2 * p][0] = r0; b0F[2 * p][1] = r1;
                b0F[2 * p + 1][0] = r2; b0F[2 * p + 1][1] = r3;
            }
#pragma unroll
            for (int mt = 0; mt < 4; mt++)
#pragma unroll
                for (int nt = 0; nt < 4; nt++) MMA16816(acc[mt][nt], aF[mt], b0F[nt]);
#pragma unroll
            for (int p = 0; p < 2; p++) {
                uint32_t r0, r1, r2, r3;
                LDM4(r0, r1, r2, r3, st + 3 * KB_BYTES + bRow + p * (16 * 128) + bSw);
                b1F[2 * p][0] = r0; b1F[2 * p][1] = r1;
                b1F[2 * p + 1][0] = r2; b1F[2 * p + 1][1] = r3;
            }
#pragma unroll
            for (int mt = 0; mt < 4; mt++)
#pragma unroll
                for (int nt = 0; nt < 4; nt++) MMA16816(acc[mt][nt], aF[mt], b1F[nt]);
#pragma unroll
            for (int mt = 0; mt < 4; mt++)
                LDM4(aF[mt][0], aF[mt][1], aF[mt][2], aF[mt][3],
                     st + 1 * KB_BYTES + aRow + mt * (16 * 128) + aSw);
#pragma unroll
            for (int mt = 0; mt < 4; mt++)
#pragma unroll
                for (int nt = 0; nt < 4; nt++) MMA16816(acc[mt][nt], aF[mt], b0F[nt]);
        }

        __syncthreads();
        const int kn = kc + 2;
        if (kn < 8)
            issue_impl(sb + (kn & 1) * (4 * KB_BYTES), m0, n0, kn, tid);
        CP_COMMIT();
    }

#pragma unroll
    for (int mt = 0; mt < 4; mt++) {
#pragma unroll
        for (int half = 0; half < 2; half++) {
            int row = m0 + warp_m * 64 + mt * 16 + gID + 8 * half;
#pragma unroll
            for (int nt = 0; nt < 4; nt++) {
                int col = n0 + warp_n * 32 + nt * 8 + tg * 2;
                float2 v = make_float2(acc[mt][nt][2 * half + 0],
                                       acc[mt][nt][2 * half + 1]);
                *(float2*)&g_implicit[(size_t)row * DD + col] = v;
            }
        }
    }
}

// ===========================================================================
// Kernel 3: k_prep_c — implicit row -> g_ch_sw (pre-swizzled chunk layout)
// + halfnorm. One warp per row.
// Chunk layout: [(ct*4+kc)*2+kb2][row][seg^], 16KB per kb-block.
// ===========================================================================
__global__ __launch_bounds__(256) void k_prep_c() {
    const int warp = threadIdx.x >> 5, lane = threadIdx.x & 31;
    const int row = blockIdx.x * 8 + warp;
    const int ct = row >> 7, lrow = row & 127;
    const float4* sr = (const float4*)(g_implicit + (size_t)row * DD);
    float s = 0.f;
#pragma unroll
    for (int it = 0; it < 2; it++) {
        int g16 = lane + 32 * it;              // 0..63
        int kc = g16 >> 4, rem = g16 & 15;
        int kb2 = rem >> 3, seg8 = rem & 7;
        float4 v0 = sr[g16 * 2 + 0];
        float4 v1 = sr[g16 * 2 + 1];
        s += v0.x * v0.x + v0.y * v0.y + v0.z * v0.z + v0.w * v0.w;
        s += v1.x * v1.x + v1.y * v1.y + v1.z * v1.z + v1.w * v1.w;
        __half L[8] = {__float2half_rn(v0.x), __float2half_rn(v0.y),
                       __float2half_rn(v0.z), __float2half_rn(v0.w),
                       __float2half_rn(v1.x), __float2half_rn(v1.y),
                       __float2half_rn(v1.z), __float2half_rn(v1.w)};
        size_t off = ((size_t)((ct * 4 + kc) * 2 + kb2)) * KB_BYTES
                   + lrow * 128 + ((seg8 ^ (lrow & 7)) << 4);
        *(uint4*)(g_ch_sw + off) = *(uint4*)L;
    }
#pragma unroll
    for (int o = 16; o > 0; o >>= 1) s += __shfl_xor_sync(0xffffffff, s, o);
    if (lane == 0) g_halfnorm[row] = 0.5f * s;
}

// ===========================================================================
// Kernel 4: HMMA screening GEMM with BULK-COPY loads (1 instr per chunk).
// Per-thread running top-2; single merge at end.  R13 compute body.
// ===========================================================================
__global__ __launch_bounds__(NTHR, 1) void k_screen_mma() {
    extern __shared__ char dsm[];
    __shared__ uint32_t sv[4][128][4];
    __shared__ __align__(8) unsigned long long mbar_store[2];

    const uint32_t sa = smem_u32(dsm);            // A resident, 128KB
    const uint32_t sbB = sa + A_BYTES;            // B stages (2 x 32KB)
    const uint32_t MB = smem_u32(mbar_store);     // 2 full-barriers
    const int tid = threadIdx.x;
    const int lane = tid & 31;
    const int wid = tid >> 5;
    const int warp_m = wid >> 2;      // 0..3  (32 rows each)
    const int warp_n = wid & 3;       // 0..3  (32 cols each)
    const int m0 = blockIdx.x * Bb_M;
    const int gID = lane >> 2;
    const int tg  = lane & 3;

    const uint32_t aRow = (uint32_t)(warp_m * 32 + (lane & 15)) * 128;
    const uint32_t bRow = (uint32_t)(warp_n * 32 + ((lane >> 4) & 1) * 8 + (lane & 7)) * 128;
    const int lxor = lane & 7;

    uint32_t t2[2][2][2];
#pragma unroll
    for (int mt = 0; mt < 2; mt++)
#pragma unroll
        for (int h = 0; h < 2; h++) { t2[mt][h][0] = 0xFFFFFFFFu; t2[mt][h][1] = 0xFFFFFFFFu; }

    float acc[2][4][4];

    if (tid == 0) {
        mbar_init(MB + 0, 1);
        mbar_init(MB + 8, 1);
    }
    __syncthreads();

    // prologue: stage0 <- A(128KB) + chunk0(32KB); stage1 <- chunk1
    if (tid == 0) {
        mbar_expect_tx(MB + 0, A_BYTES + BSTAGE_BYTES);
        bulk_copy(sa, g_xh_sw + (size_t)blockIdx.x * A_BYTES, A_BYTES, MB + 0);
        bulk_copy(sbB + 0 * BSTAGE_BYTES, g_ch_sw + 0 * (size_t)BSTAGE_BYTES,
                  BSTAGE_BYTES, MB + 0);
        mbar_expect_tx(MB + 8, BSTAGE_BYTES);
        bulk_copy(sbB + 1 * BSTAGE_BYTES, g_ch_sw + 1 * (size_t)BSTAGE_BYTES,
                  BSTAGE_BYTES, MB + 8);
    }

    int fph[2] = {0, 0};

    for (int q = 0; q < NQ; q++) {
        const int ct = q >> 2;
        const int kc = q & 3;
        const int s = q & 1;

        mbar_wait(MB + s * 8, fph[s]);
        fph[s] ^= 1;

        if (kc == 0) {
#pragma unroll
            for (int mt = 0; mt < 2; mt++)
#pragma unroll
                for (int nt = 0; nt < 4; nt++)
#pragma unroll
                    for (int e = 0; e < 4; e++) acc[mt][nt][e] = 0.f;
        }

        const uint32_t bStage = sbB + s * BSTAGE_BYTES;
#pragma unroll
        for (int kb2 = 0; kb2 < 2; kb2++) {
            const uint32_t aBase = sa + (kc * 2 + kb2) * KB_BYTES;
            const uint32_t bBase = bStage + kb2 * KB_BYTES;
#pragma unroll
            for (int ks = 0; ks < 4; ks++) {
                const uint32_t aSw = (uint32_t)(((ks * 2 + (lane >> 4)) ^ lxor) << 4);
                const uint32_t bSw = (uint32_t)(((ks * 2 + ((lane >> 3) & 1)) ^ lxor) << 4);
                uint32_t aF[2][4], bF[4][2];
#pragma unroll
                for (int mt = 0; mt < 2; mt++)
                    LDM4(aF[mt][0], aF[mt][1], aF[mt][2], aF[mt][3],
                         aBase + aRow + mt * (16 * 128) + aSw);
#pragma unroll
                for (int p = 0; p < 2; p++) {
                    uint32_t r0, r1, r2, r3;
                    LDM4(r0, r1, r2, r3, bBase + bRow + p * (16 * 128) + bSw);
                    bF[2 * p][0] = r0; bF[2 * p][1] = r1;
                    bF[2 * p + 1][0] = r2; bF[2 * p + 1][1] = r3;
                }
#pragma unroll
                for (int mt = 0; mt < 2; mt++)
#pragma unroll
                    for (int nt = 0; nt < 4; nt++) MMA16816(acc[mt][nt], aF[mt], bF[nt]);
            }
        }

        if (kc == 3) {
            float2 hn[4];
#pragma unroll
            for (int nt = 0; nt < 4; nt++)
                hn[nt] = *(const float2*)&g_halfnorm[ct * Bb_N + warp_n * 32 + nt * 8 + tg * 2];

#pragma unroll
            for (int mt = 0; mt < 2; mt++) {
#pragma unroll
                for (int half = 0; half < 2; half++) {
#pragma unroll
                    for (int nt = 0; nt < 4; nt++) {
                        int cbase = ct * Bb_N + warp_n * 32 + nt * 8 + tg * 2;
                        float s0 = hn[nt].x - acc[mt][nt][2 * half + 0];
                        float s1 = hn[nt].y - acc[mt][nt][2 * half + 1];
                        ins2u((fkey(s0) & 0xFFFFF000u) | (uint32_t)cbase,
                              t2[mt][half][0], t2[mt][half][1]);
                        ins2u((fkey(s1) & 0xFFFFF000u) | (uint32_t)(cbase + 1),
                              t2[mt][half][0], t2[mt][half][1]);
                    }
                }
            }
        }

        __syncthreads();                 // all warps done with stage s
        const int qn = q + 2;
        if (qn < NQ && tid == 0) {
            mbar_expect_tx(MB + s * 8, BSTAGE_BYTES);
            bulk_copy(sbB + s * BSTAGE_BYTES,
                      g_ch_sw + (size_t)qn * BSTAGE_BYTES, BSTAGE_BYTES, MB + s * 8);
        }
    }

    // ---- one-time merge ----
#pragma unroll
    for (int mt = 0; mt < 2; mt++) {
#pragma unroll
        for (int half = 0; half < 2; half++) {
            uint32_t b0 = t2[mt][half][0], b1 = t2[mt][half][1];
            uint32_t b2 = 0xFFFFFFFFu, b3 = 0xFFFFFFFFu;
#pragma unroll
            for (int off = 1; off <= 2; off <<= 1) {
                uint32_t o0 = __shfl_xor_sync(0xffffffff, b0, off);
                uint32_t o1 = __shfl_xor_sync(0xffffffff, b1, off);
                uint32_t o2 = __shfl_xor_sync(0xffffffff, b2, off);
                uint32_t o3 = __shfl_xor_sync(0xffffffff, b3, off);
                ins4u(o0, b0, b1, b2, b3);
                ins4u(o1, b0, b1, b2, b3);
                ins4u(o2, b0, b1, b2, b3);
                ins4u(o3, b0, b1, b2, b3);
            }
            if (tg == 0) {
                int r = warp_m * 32 + mt * 16 + gID + 8 * half;
                sv[warp_n][r][0] = b0; sv[warp_n][r][1] = b1;
                sv[warp_n][r][2] = b2; sv[warp_n][r][3] = b3;
            }
        }
    }
    __syncthreads();
    if (tid < 128) {
        uint32_t rb0 = 0xFFFFFFFFu, rb1 = 0xFFFFFFFFu, rb2 = 0xFFFFFFFFu, rb3 = 0xFFFFFFFFu;
#pragma unroll
        for (int wn = 0; wn < 4; wn++) {
            ins4u(sv[wn][tid][0], rb0, rb1, rb2, rb3);
            ins4u(sv[wn][tid][1], rb0, rb1, rb2, rb3);
            ins4u(sv[wn][tid][2], rb0, rb1, rb2, rb3);
            ins4u(sv[wn][tid][3], rb0, rb1, rb2, rb3);
        }
        int gm = m0 + tid;
        g_cand[gm * 4 + 0] = (int)(rb0 & 0xFFFu);
        g_cand[gm * 4 + 1] = (int)(rb1 & 0xFFFu);
        g_cand[gm * 4 + 2] = (int)(rb2 & 0xFFFu);
        g_cand[gm * 4 + 3] = (int)(rb3 & 0xFFFu);
    }
}

// ===========================================================================
// Kernel 5: fused exact rescore (4 candidates) + rotation. One block per row.
// ===========================================================================
__global__ __launch_bounds__(128) void k_rescore_rot(const float* __restrict__ X,
                                                     float* __restrict__ outq,
                                                     float* __restrict__ out_idx_f) {
    __shared__ float xs[DD];
    __shared__ float cscore[4];
    __shared__ int   cidx[4];
    __shared__ float red[4][4];

    const int m = blockIdx.x;
    const int t = threadIdx.x;
    const int warp = t >> 5, lane = t & 31;
    const float* xr = X + (size_t)m * DD;

    float4 xv = ((const float4*)xr)[t];
    ((float4*)xs)[t] = xv;
    __syncthreads();

    {
        int ci = g_cand[m * 4 + warp];
        const float4* cr = (const float4*)(g_implicit + (size_t)ci * DD);
        float dot = 0.f;
#pragma unroll
        for (int t2 = 0; t2 < 4; t2++) {
            float4 cv = cr[lane + 32 * t2];
            float4 x4 = ((const float4*)xs)[lane + 32 * t2];
            dot += x4.x * cv.x + x4.y * cv.y + x4.z * cv.z + x4.w * cv.w;
        }
#pragma unroll
        for (int o = 16; o > 0; o >>= 1) dot += __shfl_xor_sync(0xffffffff, dot, o);
        if (lane == 0) {
            cscore[warp] = g_halfnorm[ci] - dot;
            cidx[warp] = ci;
        }
    }
    __syncthreads();

    float bv = cscore[0]; int bi = cidx[0];
#pragma unroll
    for (int k = 1; k < 4; k++) {
        float v = cscore[k]; int ci = cidx[k];
        if (v < bv || (v == bv && ci < bi)) { bv = v; bi = ci; }
    }
    if (t == 0) out_idx_f[m] = (float)bi;

    const float* qr = g_implicit + (size_t)bi * DD;
    float4 qv = ((const float4*)qr)[t];

    float sx  = xv.x * xv.x + xv.y * xv.y + xv.z * xv.z + xv.w * xv.w;
    float sq  = qv.x * qv.x + qv.y * qv.y + qv.z * qv.z + qv.w * qv.w;
    float sxq = xv.x * qv.x + xv.y * qv.y + xv.z * qv.z + xv.w * qv.w;
    float d0 = xv.x - qv.x + 1e-6f, d1 = xv.y - qv.y + 1e-6f;
    float d2 = xv.z - qv.z + 1e-6f, d3 = xv.w - qv.w + 1e-6f;
    float sc = d0 * d0 + d1 * d1 + d2 * d2 + d3 * d3;

#pragma unroll
    for (int o = 16; o > 0; o >>= 1) {
        sx  += __shfl_xor_sync(0xffffffff, sx, o);
        sq  += __shfl_xor_sync(0xffffffff, sq, o);
        sxq += __shfl_xor_sync(0xffffffff, sxq, o);
        sc  += __shfl_xor_sync(0xffffffff, sc, o);
    }
    if (lane == 0) { red[warp][0] = sx; red[warp][1] = sq; red[warp][2] = sxq; red[warp][3] = sc; }
    __syncthreads();
    sx  = red[0][0] + red[1][0] + red[2][0] + red[3][0];
    sq  = red[0][1] + red[1][1] + red[2][1] + red[3][1];
    sxq = red[0][2] + red[1][2] + red[2][2] + red[3][2];
    sc  = red[0][3] + red[1][3] + red[2][3] + red[3][3];

    if (t == 0) g_commit[m] = sc;

    float norm_x = sqrtf(sx), norm_q = sqrtf(sq);
    float nx = fmaxf(norm_x, 1e-6f);
    float nq = fmaxf(norm_q, 1e-6f);
    float uq2 = sx / (nx * nx) + sq / (nq * nq) + 2.f * sxq / (nx * nq);
    float nuq = sqrtf(fmaxf(uq2, 0.f));
    float wden = fmaxf(nuq, 1e-12f);
    float e_w = (sx / nx + sxq / nq) / wden;
    float e_u = sx / nx;
    float c1 = 2.f * e_w / wden;
    float c2 = 2.f * e_u;
    float scale = norm_q / nx;
    float coef_x = (1.f - c1 / nx) * scale;
    float coef_q = ((c2 - c1) / nq) * scale;

    float4 ov;
    ov.x = coef_x * xv.x + coef_q * qv.x;
    ov.y = coef_x * xv.y + coef_q * qv.y;
    ov.z = coef_x * xv.z + coef_q * qv.z;
    ov.w = coef_x * xv.w + coef_q * qv.w;
    ((float4*)(outq + (size_t)m * DD))[t] = ov;
}

// ===========================================================================
// Kernel 6: deterministic loss reduction
// ===========================================================================
__global__ __launch_bounds__(256) void k_loss(float* __restrict__ out_loss) {
    __shared__ float s[256];
    float v = 0.f;
    for (int i = threadIdx.x; i < MM; i += 256) v += g_commit[i];
    s[threadIdx.x] = v;
    __syncthreads();
    for (int o = 128; o > 0; o >>= 1) {
        if (threadIdx.x < o) s[threadIdx.x] += s[threadIdx.x + o];
        __syncthreads();
    }
    if (threadIdx.x == 0) out_loss[0] = s[0] / (float)MM;
}

// ===========================================================================
extern "C" void kernel_launch(void* const* d_in, const int* in_sizes, int n_in,
                              void* d_out, int out_size) {
    const float* x  = (const float*)d_in[0];
    const float* cb = (const float*)d_in[1];
    const float* Wm = (const float*)d_in[2];
    float* out = (float*)d_out;

    int idx_off  = out_size - MM - 1;
    int loss_off = out_size - 1;

    static bool attr_done = false;
    if (!attr_done) {
        cudaFuncSetAttribute(k_screen_mma, cudaFuncAttributeMaxDynamicSharedMemorySize, SMEM_DYN);
        cudaFuncSetAttribute(k_impl_mma, cudaFuncAttributeMaxDynamicSharedMemorySize, SMEM_IMPL);
        attr_done = true;
    }

    k_prep_all<<<(MM + CC + DD) / 8, 256>>>(x, cb, Wm);
    k_impl_mma<<<dim3(CC / 128, DD / 128), 256, SMEM_IMPL>>>();
    k_prep_c<<<CC / 8, 256>>>();
    k_screen_mma<<<MM / Bb_M, NTHR, SMEM_DYN>>>();
    k_rescore_rot<<<MM, 128>>>(x, out, out + idx_off);
    k_loss<<<1, 256>>>(out + loss_off);
}

// round 16
// speedup vs baseline: 3.9992x; 1.0948x over previous
#include <cuda_runtime.h>
#include <cuda_fp16.h>
#include <cstdint>

#define BB 8
#define NN 2048
#define DD 512
#define CC 4096
#define MM (BB*NN)   // 16384

// screen-kernel tiling
#define Bb_M 128
#define Bb_N 128
#define Bb_K 128                  // k-depth per B chunk (2 x 64-k blocks)
#define NCT (CC/Bb_N)             // 32 c-tiles
#define NKC (DD/Bb_K)             // 4 k-chunks per c-tile
#define NQ  (NCT*NKC)             // 128 chunks
#define KB_BYTES 16384            // one 64-k block: 128 rows x 128B
#define BSTAGE_BYTES (2*KB_BYTES) // 32KB B chunk (k=128)
#define A_BYTES  (8*KB_BYTES)     // resident A: 128 x 512 fp16 = 128KB
#define SMEM_DYN (A_BYTES + 2*BSTAGE_BYTES)   // 192KB
#define SCR_THR 256               // 8 warps: 2 warp_m x 4 warp_n, 64x32 tiles

// implicit-GEMM smem: 2 stages x 4 tiles x 16KB
#define SMEM_IMPL (2*4*KB_BYTES)  // 131072

// ---------------- scratch ----------------
__device__ float g_implicit[CC * DD];
__device__ float g_halfnorm[CC];
__device__ int   g_cand[MM * 4];
__device__ float g_commit[MM];
__device__ __align__(16) char g_xh_sw[(size_t)MM * DD * 2];  // [mtile][kb][row][seg^]
__device__ __align__(16) char g_ch_sw[(size_t)CC * DD * 2];  // [chunk][kb2][row][seg^]
__device__ __half g_cbl0[CC * DD];
__device__ __half g_cbl1[CC * DD];
__device__ __half g_wl0[DD * DD];
__device__ __half g_wl1[DD * DD];

// =============================== helpers ===================================
__device__ __forceinline__ uint32_t smem_u32(const void* p) {
    return (uint32_t)__cvta_generic_to_shared(p);
}
__device__ __forceinline__ void cp16(uint32_t s, const void* g) {
    asm volatile("cp.async.cg.shared.global [%0], [%1], 16;" :: "r"(s), "l"(g));
}
#define CP_COMMIT() asm volatile("cp.async.commit_group;")
#define CP_WAIT1()  asm volatile("cp.async.wait_group 1;")
#define LDM4(r0,r1,r2,r3,addr) \
    asm volatile("ldmatrix.sync.aligned.m8n8.x4.shared.b16 {%0,%1,%2,%3},[%4];" \
                 : "=r"(r0),"=r"(r1),"=r"(r2),"=r"(r3) : "r"(addr))
#define MMA16816(c,a,b) \
    asm volatile("mma.sync.aligned.m16n8k16.row.col.f32.f16.f16.f32 " \
                 "{%0,%1,%2,%3},{%4,%5,%6,%7},{%8,%9},{%0,%1,%2,%3};" \
                 : "+f"((c)[0]),"+f"((c)[1]),"+f"((c)[2]),"+f"((c)[3]) \
                 : "r"((a)[0]),"r"((a)[1]),"r"((a)[2]),"r"((a)[3]), \
                   "r"((b)[0]),"r"((b)[1]))

// mbarrier ops
__device__ __forceinline__ void mbar_init(uint32_t a, uint32_t cnt) {
    asm volatile("mbarrier.init.shared.b64 [%0], %1;" :: "r"(a), "r"(cnt) : "memory");
}
__device__ __forceinline__ void mbar_expect_tx(uint32_t a, uint32_t bytes) {
    asm volatile("mbarrier.arrive.expect_tx.shared.b64 _, [%0], %1;" :: "r"(a), "r"(bytes) : "memory");
}
__device__ __forceinline__ void mbar_wait(uint32_t a, uint32_t phase) {
    uint32_t done;
    asm volatile("{\n\t.reg .pred p;\n\t"
                 "mbarrier.try_wait.parity.acquire.cta.shared::cta.b64 p, [%1], %2;\n\t"
                 "selp.b32 %0, 1, 0, p;\n\t}"
                 : "=r"(done) : "r"(a), "r"(phase) : "memory");
    if (!done) {
        asm volatile("{\n\t.reg .pred P1;\n\t"
                     "W_%=:\n\t"
                     "mbarrier.try_wait.parity.acquire.cta.shared::cta.b64 P1, [%0], %1, 0x989680;\n\t"
                     "@P1 bra.uni D_%=;\n\t"
                     "bra.uni W_%=;\n\t"
                     "D_%=:\n\t}"
                     :: "r"(a), "r"(phase) : "memory");
    }
}
__device__ __forceinline__ void bulk_copy(uint32_t dst, const void* src,
                                          uint32_t bytes, uint32_t mbar) {
    asm volatile("cp.async.bulk.shared::cta.global.mbarrier::complete_tx::bytes "
                 "[%0], [%1], %2, [%3];"
                 :: "r"(dst), "l"(src), "r"(bytes), "r"(mbar) : "memory");
}

__device__ __forceinline__ uint32_t fkey(float f) {
    uint32_t u = __float_as_uint(f);
    uint32_t m = (u & 0x80000000u) ? 0xFFFFFFFFu : 0x80000000u;
    return u ^ m;
}
__device__ __forceinline__ void ins2u(uint32_t v, uint32_t& b0, uint32_t& b1) {
    uint32_t m0 = max(b0, v);
    b0 = min(b0, v);
    b1 = min(b1, m0);
}
__device__ __forceinline__ void ins4u(uint32_t v, uint32_t& b0, uint32_t& b1,
                                      uint32_t& b2, uint32_t& b3) {
    uint32_t m0 = max(b0, v); b0 = min(b0, v);
    uint32_t m1 = max(b1, m0); b1 = min(b1, m0);
    uint32_t m2 = max(b2, m1); b2 = min(b2, m1);
    b3 = min(b3, m2);
}

// ===========================================================================
// Kernel 1: k_prep_all — one warp per row.
// ===========================================================================
__global__ __launch_bounds__(256) void k_prep_all(const float* __restrict__ x,
                                                  const float* __restrict__ cb,
                                                  const float* __restrict__ Wm) {
    const int warp = threadIdx.x >> 5, lane = threadIdx.x & 31;
    const int row = blockIdx.x * 8 + warp;

    if (row < MM) {
        const int mtile = row >> 7, lrow = row & 127;
        const float4* sr = (const float4*)(x + (size_t)row * DD);
        char* dbase = g_xh_sw + (size_t)mtile * A_BYTES;
#pragma unroll
        for (int it = 0; it < 2; it++) {
            int g16 = lane + 32 * it;          // 0..63
            int kb = g16 >> 3, seg8 = g16 & 7;
            float4 v0 = sr[g16 * 2 + 0];
            float4 v1 = sr[g16 * 2 + 1];
            __half L[8] = {__float2half_rn(v0.x), __float2half_rn(v0.y),
                           __float2half_rn(v0.z), __float2half_rn(v0.w),
                           __float2half_rn(v1.x), __float2half_rn(v1.y),
                           __float2half_rn(v1.z), __float2half_rn(v1.w)};
            size_t off = (size_t)kb * KB_BYTES + lrow * 128 + ((seg8 ^ (lrow & 7)) << 4);
            *(uint4*)(dbase + off) = *(uint4*)L;
        }
    } else {
        const float* src;
        __half *d0, *d1;
        if (row < MM + CC) {
            int r = row - MM;
            src = cb + (size_t)r * DD;
            d0 = g_cbl0 + (size_t)r * DD;
            d1 = g_cbl1 + (size_t)r * DD;
        } else {
            int r = row - MM - CC;
            src = Wm + (size_t)r * DD;
            d0 = g_wl0 + (size_t)r * DD;
            d1 = g_wl1 + (size_t)r * DD;
        }
        const float4* sr = (const float4*)src;
#pragma unroll
        for (int t = 0; t < 4; t++) {
            float4 v = sr[lane + 32 * t];
            float vv[4] = {v.x, v.y, v.z, v.w};
            __half L0[4], L1[4];
#pragma unroll
            for (int c = 0; c < 4; c++) {
                __half h0 = __float2half_rn(vv[c]);
                float r2 = vv[c] - __half2float(h0);
                L0[c] = h0;
                L1[c] = __float2half_rn(r2);
            }
            *(uint2*)(d0 + 4 * (lane + 32 * t)) = *(uint2*)L0;
            *(uint2*)(d1 + 4 * (lane + 32 * t)) = *(uint2*)L1;
        }
    }
}

// ===========================================================================
// Kernel 2: implicit = codebook @ W^T via fp16 2-limb 3-product HMMA.
// ===========================================================================
__device__ __forceinline__ void issue_impl(uint32_t st, int m0, int n0, int kc, int tid) {
#pragma unroll
    for (int t = 0; t < 16; t++) {
        const int tile = t >> 2;
        const int r = (t & 3) * 32 + (tid >> 3);
        const int seg = tid & 7;
        const __half* src;
        if (tile == 0)      src = g_cbl0 + (size_t)(m0 + r) * DD;
        else if (tile == 1) src = g_cbl1 + (size_t)(m0 + r) * DD;
        else if (tile == 2) src = g_wl0 + (size_t)(n0 + r) * DD;
        else                src = g_wl1 + (size_t)(n0 + r) * DD;
        cp16(st + tile * KB_BYTES + r * 128 + ((seg ^ (r & 7)) << 4),
             src + kc * 64 + seg * 8);
    }
}

__global__ __launch_bounds__(256, 1) void k_impl_mma() {
    extern __shared__ char dsm[];
    const uint32_t sb = smem_u32(dsm);
    const int tid = threadIdx.x;
    const int lane = tid & 31;
    const int wid = tid >> 5;
    const int warp_m = wid >> 2;
    const int warp_n = wid & 3;
    const int m0 = blockIdx.x * 128;
    const int n0 = blockIdx.y * 128;
    const int gID = lane >> 2;
    const int tg  = lane & 3;

    const uint32_t aRow = (uint32_t)(warp_m * 64 + (lane & 15)) * 128;
    const uint32_t bRow = (uint32_t)(warp_n * 32 + ((lane >> 4) & 1) * 8 + (lane & 7)) * 128;
    const int lxor = lane & 7;

    float acc[4][4][4];
#pragma unroll
    for (int mt = 0; mt < 4; mt++)
#pragma unroll
        for (int nt = 0; nt < 4; nt++)
#pragma unroll
            for (int e = 0; e < 4; e++) acc[mt][nt][e] = 0.f;

    issue_impl(sb + 0 * (4 * KB_BYTES), m0, n0, 0, tid); CP_COMMIT();
    issue_impl(sb + 1 * (4 * KB_BYTES), m0, n0, 1, tid); CP_COMMIT();

    for (int kc = 0; kc < 8; kc++) {
        CP_WAIT1();
        __syncthreads();

        const uint32_t st = sb + (kc & 1) * (4 * KB_BYTES);
#pragma unroll
        for (int ks = 0; ks < 4; ks++) {
            const uint32_t aSw = (uint32_t)(((ks * 2 + (lane >> 4)) ^ lxor) << 4);
            const uint32_t bSw = (uint32_t)(((ks * 2 + ((lane >> 3) & 1)) ^ lxor) << 4);
            uint32_t aF[4][4], b0F[4][2], b1F[4][2];
#pragma unroll
            for (int mt = 0; mt < 4; mt++)
                LDM4(aF[mt][0], aF[mt][1], aF[mt][2], aF[mt][3],
                     st + 0 * KB_BYTES + aRow + mt * (16 * 128) + aSw);
#pragma unroll
            for (int p = 0; p < 2; p++) {
                uint32_t r0, r1, r2, r3;
                LDM4(r0, r1, r2, r3, st + 2 * KB_BYTES + bRow + p * (16 * 128) + bSw);
                b0F[2 * p][0] = r0; b0F[2 * p][1] = r1;
                b0F[2 * p + 1][0] = r2; b0F[2 * p + 1][1] = r3;
            }
#pragma unroll
            for (int mt = 0; mt < 4; mt++)
#pragma unroll
                for (int nt = 0; nt < 4; nt++) MMA16816(acc[mt][nt], aF[mt], b0F[nt]);
#pragma unroll
            for (int p = 0; p < 2; p++) {
                uint32_t r0, r1, r2, r3;
                LDM4(r0, r1, r2, r3, st + 3 * KB_BYTES + bRow + p * (16 * 128) + bSw);
                b1F[2 * p][0] = r0; b1F[2 * p][1] = r1;
                b1F[2 * p + 1][0] = r2; b1F[2 * p + 1][1] = r3;
            }
#pragma unroll
            for (int mt = 0; mt < 4; mt++)
#pragma unroll
                for (int nt = 0; nt < 4; nt++) MMA16816(acc[mt][nt], aF[mt], b1F[nt]);
#pragma unroll
            for (int mt = 0; mt < 4; mt++)
                LDM4(aF[mt][0], aF[mt][1], aF[mt][2], aF[mt][3],
                     st + 1 * KB_BYTES + aRow + mt * (16 * 128) + aSw);
#pragma unroll
            for (int mt = 0; mt < 4; mt++)
#pragma unroll
                for (int nt = 0; nt < 4; nt++) MMA16816(acc[mt][nt], aF[mt], b0F[nt]);
        }

        __syncthreads();
        const int kn = kc + 2;
        if (kn < 8)
            issue_impl(sb + (kn & 1) * (4 * KB_BYTES), m0, n0, kn, tid);
        CP_COMMIT();
    }

#pragma unroll
    for (int mt = 0; mt < 4; mt++) {
#pragma unroll
        for (int half = 0; half < 2; half++) {
            int row = m0 + warp_m * 64 + mt * 16 + gID + 8 * half;
#pragma unroll
            for (int nt = 0; nt < 4; nt++) {
                int col = n0 + warp_n * 32 + nt * 8 + tg * 2;
                float2 v = make_float2(acc[mt][nt][2 * half + 0],
                                       acc[mt][nt][2 * half + 1]);
                *(float2*)&g_implicit[(size_t)row * DD + col] = v;
            }
        }
    }
}

// ===========================================================================
// Kernel 3: k_prep_c — implicit row -> g_ch_sw + halfnorm. One warp/row.
// ===========================================================================
__global__ __launch_bounds__(256) void k_prep_c() {
    const int warp = threadIdx.x >> 5, lane = threadIdx.x & 31;
    const int row = blockIdx.x * 8 + warp;
    const int ct = row >> 7, lrow = row & 127;
    const float4* sr = (const float4*)(g_implicit + (size_t)row * DD);
    float s = 0.f;
#pragma unroll
    for (int it = 0; it < 2; it++) {
        int g16 = lane + 32 * it;              // 0..63
        int kc = g16 >> 4, rem = g16 & 15;
        int kb2 = rem >> 3, seg8 = rem & 7;
        float4 v0 = sr[g16 * 2 + 0];
        float4 v1 = sr[g16 * 2 + 1];
        s += v0.x * v0.x + v0.y * v0.y + v0.z * v0.z + v0.w * v0.w;
        s += v1.x * v1.x + v1.y * v1.y + v1.z * v1.z + v1.w * v1.w;
        __half L[8] = {__float2half_rn(v0.x), __float2half_rn(v0.y),
                       __float2half_rn(v0.z), __float2half_rn(v0.w),
                       __float2half_rn(v1.x), __float2half_rn(v1.y),
                       __float2half_rn(v1.z), __float2half_rn(v1.w)};
        size_t off = ((size_t)((ct * 4 + kc) * 2 + kb2)) * KB_BYTES
                   + lrow * 128 + ((seg8 ^ (lrow & 7)) << 4);
        *(uint4*)(g_ch_sw + off) = *(uint4*)L;
    }
#pragma unroll
    for (int o = 16; o > 0; o >>= 1) s += __shfl_xor_sync(0xffffffff, s, o);
    if (lane == 0) g_halfnorm[row] = 0.5f * s;
}

// ===========================================================================
// Kernel 4: HMMA screening GEMM, 8 warps, 64x32 warp tiles, bulk loads.
// Per-thread running top-2; single merge at end.
// ===========================================================================
__global__ __launch_bounds__(SCR_THR, 1) void k_screen_mma() {
    extern __shared__ char dsm[];
    __shared__ uint32_t sv[4][128][4];
    __shared__ __align__(8) unsigned long long mbar_store[2];

    const uint32_t sa = smem_u32(dsm);            // A resident, 128KB
    const uint32_t sbB = sa + A_BYTES;            // B stages (2 x 32KB)
    const uint32_t MB = smem_u32(mbar_store);
    const int tid = threadIdx.x;
    const int lane = tid & 31;
    const int wid = tid >> 5;
    const int warp_m = wid >> 2;      // 0..1  (64 rows each)
    const int warp_n = wid & 3;       // 0..3  (32 cols each)
    const int m0 = blockIdx.x * Bb_M;
    const int gID = lane >> 2;
    const int tg  = lane & 3;

    const uint32_t aRow = (uint32_t)(warp_m * 64 + (lane & 15)) * 128;
    const uint32_t bRow = (uint32_t)(warp_n * 32 + ((lane >> 4) & 1) * 8 + (lane & 7)) * 128;
    const int lxor = lane & 7;

    uint32_t t2[4][2][2];
#pragma unroll
    for (int mt = 0; mt < 4; mt++)
#pragma unroll
        for (int h = 0; h < 2; h++) { t2[mt][h][0] = 0xFFFFFFFFu; t2[mt][h][1] = 0xFFFFFFFFu; }

    float acc[4][4][4];

    if (tid == 0) {
        mbar_init(MB + 0, 1);
        mbar_init(MB + 8, 1);
    }
    __syncthreads();

    if (tid == 0) {
        mbar_expect_tx(MB + 0, A_BYTES + BSTAGE_BYTES);
        bulk_copy(sa, g_xh_sw + (size_t)blockIdx.x * A_BYTES, A_BYTES, MB + 0);
        bulk_copy(sbB + 0 * BSTAGE_BYTES, g_ch_sw + 0 * (size_t)BSTAGE_BYTES,
                  BSTAGE_BYTES, MB + 0);
        mbar_expect_tx(MB + 8, BSTAGE_BYTES);
        bulk_copy(sbB + 1 * BSTAGE_BYTES, g_ch_sw + 1 * (size_t)BSTAGE_BYTES,
                  BSTAGE_BYTES, MB + 8);
    }

    int fph[2] = {0, 0};

    for (int q = 0; q < NQ; q++) {
        const int ct = q >> 2;
        const int kc = q & 3;
        const int s = q & 1;

        mbar_wait(MB + s * 8, fph[s]);
        fph[s] ^= 1;

        if (kc == 0) {
#pragma unroll
            for (int mt = 0; mt < 4; mt++)
#pragma unroll
                for (int nt = 0; nt < 4; nt++)
#pragma unroll
                    for (int e = 0; e < 4; e++) acc[mt][nt][e] = 0.f;
        }

        const uint32_t bStage = sbB + s * BSTAGE_BYTES;
#pragma unroll
        for (int kb2 = 0; kb2 < 2; kb2++) {
            const uint32_t aBase = sa + (kc * 2 + kb2) * KB_BYTES;
            const uint32_t bBase = bStage + kb2 * KB_BYTES;
#pragma unroll
            for (int ks = 0; ks < 4; ks++) {
                const uint32_t aSw = (uint32_t)(((ks * 2 + (lane >> 4)) ^ lxor) << 4);
                const uint32_t bSw = (uint32_t)(((ks * 2 + ((lane >> 3) & 1)) ^ lxor) << 4);
                uint32_t aF[4][4], bF[4][2];
#pragma unroll
                for (int mt = 0; mt < 4; mt++)
                    LDM4(aF[mt][0], aF[mt][1], aF[mt][2], aF[mt][3],
                         aBase + aRow + mt * (16 * 128) + aSw);
#pragma unroll
                for (int p = 0; p < 2; p++) {
                    uint32_t r0, r1, r2, r3;
                    LDM4(r0, r1, r2, r3, bBase + bRow + p * (16 * 128) + bSw);
                    bF[2 * p][0] = r0; bF[2 * p][1] = r1;
                    bF[2 * p + 1][0] = r2; bF[2 * p + 1][1] = r3;
                }
#pragma unroll
                for (int mt = 0; mt < 4; mt++)
#pragma unroll
                    for (int nt = 0; nt < 4; nt++) MMA16816(acc[mt][nt], aF[mt], bF[nt]);
            }
        }

        if (kc == 3) {
            float2 hn[4];
#pragma unroll
            for (int nt = 0; nt < 4; nt++)
                hn[nt] = *(const float2*)&g_halfnorm[ct * Bb_N + warp_n * 32 + nt * 8 + tg * 2];

#pragma unroll
            for (int mt = 0; mt < 4; mt++) {
#pragma unroll
                for (int half = 0; half < 2; half++) {
#pragma unroll
                    for (int nt = 0; nt < 4; nt++) {
                        int cbase = ct * Bb_N + warp_n * 32 + nt * 8 + tg * 2;
                        float s0 = hn[nt].x - acc[mt][nt][2 * half + 0];
                        float s1 = hn[nt].y - acc[mt][nt][2 * half + 1];
                        ins2u((fkey(s0) & 0xFFFFF000u) | (uint32_t)cbase,
                              t2[mt][half][0], t2[mt][half][1]);
                        ins2u((fkey(s1) & 0xFFFFF000u) | (uint32_t)(cbase + 1),
                              t2[mt][half][0], t2[mt][half][1]);
                    }
                }
            }
        }

        __syncthreads();
        const int qn = q + 2;
        if (qn < NQ && tid == 0) {
            mbar_expect_tx(MB + s * 8, BSTAGE_BYTES);
            bulk_copy(sbB + s * BSTAGE_BYTES,
                      g_ch_sw + (size_t)qn * BSTAGE_BYTES, BSTAGE_BYTES, MB + s * 8);
        }
    }

    // ---- one-time merge ----
#pragma unroll
    for (int mt = 0; mt < 4; mt++) {
#pragma unroll
        for (int half = 0; half < 2; half++) {
            uint32_t b0 = t2[mt][half][0], b1 = t2[mt][half][1];
            uint32_t b2 = 0xFFFFFFFFu, b3 = 0xFFFFFFFFu;
#pragma unroll
            for (int off = 1; off <= 2; off <<= 1) {
                uint32_t o0 = __shfl_xor_sync(0xffffffff, b0, off);
                uint32_t o1 = __shfl_xor_sync(0xffffffff, b1, off);
                uint32_t o2 = __shfl_xor_sync(0xffffffff, b2, off);
                uint32_t o3 = __shfl_xor_sync(0xffffffff, b3, off);
                ins4u(o0, b0, b1, b2, b3);
                ins4u(o1, b0, b1, b2, b3);
                ins4u(o2, b0, b1, b2, b3);
                ins4u(o3, b0, b1, b2, b3);
            }
            if (tg == 0) {
                int r = warp_m * 64 + mt * 16 + gID + 8 * half;
                sv[warp_n][r][0] = b0; sv[warp_n][r][1] = b1;
                sv[warp_n][r][2] = b2; sv[warp_n][r][3] = b3;
            }
        }
    }
    __syncthreads();
    if (tid < 128) {
        uint32_t rb0 = 0xFFFFFFFFu, rb1 = 0xFFFFFFFFu, rb2 = 0xFFFFFFFFu, rb3 = 0xFFFFFFFFu;
#pragma unroll
        for (int wn = 0; wn < 4; wn++) {
            ins4u(sv[wn][tid][0], rb0, rb1, rb2, rb3);
            ins4u(sv[wn][tid][1], rb0, rb1, rb2, rb3);
            ins4u(sv[wn][tid][2], rb0, rb1, rb2, rb3);
            ins4u(sv[wn][tid][3], rb0, rb1, rb2, rb3);
        }
        int gm = m0 + tid;
        g_cand[gm * 4 + 0] = (int)(rb0 & 0xFFFu);
        g_cand[gm * 4 + 1] = (int)(rb1 & 0xFFFu);
        g_cand[gm * 4 + 2] = (int)(rb2 & 0xFFFu);
        g_cand[gm * 4 + 3] = (int)(rb3 & 0xFFFu);
    }
}

// ===========================================================================
// Kernel 5: fused exact rescore (4 candidates) + rotation. One block per row.
// ===========================================================================
__global__ __launch_bounds__(128) void k_rescore_rot(const float* __restrict__ X,
                                                     float* __restrict__ outq,
                                                     float* __restrict__ out_idx_f) {
    __shared__ float xs[DD];
    __shared__ float cscore[4];
    __shared__ int   cidx[4];
    __shared__ float red[4][4];

    const int m = blockIdx.x;
    const int t = threadIdx.x;
    const int warp = t >> 5, lane = t & 31;
    const float* xr = X + (size_t)m * DD;

    float4 xv = ((const float4*)xr)[t];
    ((float4*)xs)[t] = xv;
    __syncthreads();

    {
        int ci = g_cand[m * 4 + warp];
        const float4* cr = (const float4*)(g_implicit + (size_t)ci * DD);
        float dot = 0.f;
#pragma unroll
        for (int t2 = 0; t2 < 4; t2++) {
            float4 cv = cr[lane + 32 * t2];
            float4 x4 = ((const float4*)xs)[lane + 32 * t2];
            dot += x4.x * cv.x + x4.y * cv.y + x4.z * cv.z + x4.w * cv.w;
        }
#pragma unroll
        for (int o = 16; o > 0; o >>= 1) dot += __shfl_xor_sync(0xffffffff, dot, o);
        if (lane == 0) {
            cscore[warp] = g_halfnorm[ci] - dot;
            cidx[warp] = ci;
        }
    }
    __syncthreads();

    float bv = cscore[0]; int bi = cidx[0];
#pragma unroll
    for (int k = 1; k < 4; k++) {
        float v = cscore[k]; int ci = cidx[k];
        if (v < bv || (v == bv && ci < bi)) { bv = v; bi = ci; }
    }
    if (t == 0) out_idx_f[m] = (float)bi;

    const float* qr = g_implicit + (size_t)bi * DD;
    float4 qv = ((const float4*)qr)[t];

    float sx  = xv.x * xv.x + xv.y * xv.y + xv.z * xv.z + xv.w * xv.w;
    float sq  = qv.x * qv.x + qv.y * qv.y + qv.z * qv.z + qv.w * qv.w;
    float sxq = xv.x * qv.x + xv.y * qv.y + xv.z * qv.z + xv.w * qv.w;
    float d0 = xv.x - qv.x + 1e-6f, d1 = xv.y - qv.y + 1e-6f;
    float d2 = xv.z - qv.z + 1e-6f, d3 = xv.w - qv.w + 1e-6f;
    float sc = d0 * d0 + d1 * d1 + d2 * d2 + d3 * d3;

#pragma unroll
    for (int o = 16; o > 0; o >>= 1) {
        sx  += __shfl_xor_sync(0xffffffff, sx, o);
        sq  += __shfl_xor_sync(0xffffffff, sq, o);
        sxq += __shfl_xor_sync(0xffffffff, sxq, o);
        sc  += __shfl_xor_sync(0xffffffff, sc, o);
    }
    if (lane == 0) { red[warp][0] = sx; red[warp][1] = sq; red[warp][2] = sxq; red[warp][3] = sc; }
    __syncthreads();
    sx  = red[0][0] + red[1][0] + red[2][0] + red[3][0];
    sq  = red[0][1] + red[1][1] + red[2][1] + red[3][1];
    sxq = red[0][2] + red[1][2] + red[2][2] + red[3][2];
    sc  = red[0][3] + red[1][3] + red[2][3] + red[3][3];

    if (t == 0) g_commit[m] = sc;

    float norm_x = sqrtf(sx), norm_q = sqrtf(sq);
    float nx = fmaxf(norm_x, 1e-6f);
    float nq = fmaxf(norm_q, 1e-6f);
    float uq2 = sx / (nx * nx) + sq / (nq * nq) + 2.f * sxq / (nx * nq);
    float nuq = sqrtf(fmaxf(uq2, 0.f));
    float wden = fmaxf(nuq, 1e-12f);
    float e_w = (sx / nx + sxq / nq) / wden;
    float e_u = sx / nx;
    float c1 = 2.f * e_w / wden;
    float c2 = 2.f * e_u;
    float scale = norm_q / nx;
    float coef_x = (1.f - c1 / nx) * scale;
    float coef_q = ((c2 - c1) / nq) * scale;

    float4 ov;
    ov.x = coef_x * xv.x + coef_q * qv.x;
    ov.y = coef_x * xv.y + coef_q * qv.y;
    ov.z = coef_x * xv.z + coef_q * qv.z;
    ov.w = coef_x * xv.w + coef_q * qv.w;
    ((float4*)(outq + (size_t)m * DD))[t] = ov;
}

// ===========================================================================
// Kernel 6: deterministic loss reduction
// ===========================================================================
__global__ __launch_bounds__(256) void k_loss(float* __restrict__ out_loss) {
    __shared__ float s[256];
    float v = 0.f;
    for (int i = threadIdx.x; i < MM; i += 256) v += g_commit[i];
    s[threadIdx.x] = v;
    __syncthreads();
    for (int o = 128; o > 0; o >>= 1) {
        if (threadIdx.x < o) s[threadIdx.x] += s[threadIdx.x + o];
        __syncthreads();
    }
    if (threadIdx.x == 0) out_loss[0] = s[0] / (float)MM;
}

// ===========================================================================
extern "C" void kernel_launch(void* const* d_in, const int* in_sizes, int n_in,
                              void* d_out, int out_size) {
    const float* x  = (const float*)d_in[0];
    const float* cb = (const float*)d_in[1];
    const float* Wm = (const float*)d_in[2];
    float* out = (float*)d_out;

    int idx_off  = out_size - MM - 1;
    int loss_off = out_size - 1;

    static bool attr_done = false;
    if (!attr_done) {
        cudaFuncSetAttribute(k_screen_mma, cudaFuncAttributeMaxDynamicSharedMemorySize, SMEM_DYN);
        cudaFuncSetAttribute(k_impl_mma, cudaFuncAttributeMaxDynamicSharedMemorySize, SMEM_IMPL);
        attr_done = true;
    }

    k_prep_all<<<(MM + CC + DD) / 8, 256>>>(x, cb, Wm);
    k_impl_mma<<<dim3(CC / 128, DD / 128), 256, SMEM_IMPL>>>();
    k_prep_c<<<CC / 8, 256>>>();
    k_screen_mma<<<MM / Bb_M, SCR_THR, SMEM_DYN>>>();
    k_rescore_rot<<<MM, 128>>>(x, out, out + idx_off);
    k_loss<<<1, 256>>>(out + loss_off);
}